// round 1
// baseline (speedup 1.0000x reference)
#include <cuda_runtime.h>
#include <cuda_bf16.h>
#include <cstdint>

typedef unsigned long long ull;

// ---------------- constants ----------------
#define BATCH   2
#define NSEQ    2048
#define DIMM    4096
#define NHEAD   32
#define NKV     8
#define HDIM    128
#define MROWS   (BATCH*NSEQ)          // 4096
#define ATT_SCALE 0.08838834764831845f  // 1/sqrt(128)

// ---------------- scratch (device globals; no allocations allowed) ----------------
__device__ float g_q[MROWS * NHEAD * HDIM];   // (b,n,h,d)
__device__ float g_k[MROWS * NKV * HDIM];     // (b,n,kvh,d)
__device__ float g_v[MROWS * NKV * HDIM];
__device__ float g_attn[MROWS * NHEAD * HDIM];

// ---------------- f32x2 helpers (sm_100+) ----------------
__device__ __forceinline__ ull pack_dup(float a) {
    ull r;
    asm("mov.b64 %0, {%1, %1};" : "=l"(r) : "f"(a));
    return r;
}
__device__ __forceinline__ void ffma2(ull& d, ull a, ull b) {
    asm("fma.rn.f32x2 %0, %1, %2, %0;" : "+l"(d) : "l"(a), "l"(b));
}
__device__ __forceinline__ float2 unpack2(ull v) {
    float2 r;
    asm("mov.b64 {%0, %1}, %2;" : "=f"(r.x), "=f"(r.y) : "l"(v));
    return r;
}

// ---------------- NT GEMM: C[M,N] = A[M,K] * B[N,K]^T (all row-major fp32) ----------------
// 128x128 tile, BK=16, 256 threads, 8x8 per-thread, FFMA2 inner product.
__global__ __launch_bounds__(256) void gemm_nt_kernel(
    const float* __restrict__ A, const float* __restrict__ B,
    float* __restrict__ C, int M, int N, int K)
{
    __shared__ float As[16][128];
    __shared__ float Bs[16][128];

    const int tid = threadIdx.x;
    const int bm = blockIdx.y * 128;
    const int bn = blockIdx.x * 128;
    const int tx = tid & 15;
    const int ty = tid >> 4;

    ull accp[8][4];
#pragma unroll
    for (int i = 0; i < 8; i++)
#pragma unroll
        for (int j = 0; j < 4; j++) accp[i][j] = 0ull;

    const int row0 = tid >> 2;   // 0..63
    const int c4   = tid & 3;    // which float4 along K

    for (int k0 = 0; k0 < K; k0 += 16) {
#pragma unroll
        for (int t = 0; t < 2; t++) {
            int row = row0 + t * 64;
            float4 a = *(const float4*)&A[(size_t)(bm + row) * K + k0 + c4 * 4];
            As[c4 * 4 + 0][row] = a.x; As[c4 * 4 + 1][row] = a.y;
            As[c4 * 4 + 2][row] = a.z; As[c4 * 4 + 3][row] = a.w;
            float4 b = *(const float4*)&B[(size_t)(bn + row) * K + k0 + c4 * 4];
            Bs[c4 * 4 + 0][row] = b.x; Bs[c4 * 4 + 1][row] = b.y;
            Bs[c4 * 4 + 2][row] = b.z; Bs[c4 * 4 + 3][row] = b.w;
        }
        __syncthreads();

#pragma unroll
        for (int kk = 0; kk < 16; kk++) {
            float4 a0 = *(const float4*)&As[kk][ty * 8];
            float4 a1 = *(const float4*)&As[kk][ty * 8 + 4];
            ull b0 = *(const ull*)&Bs[kk][tx * 8 + 0];
            ull b1 = *(const ull*)&Bs[kk][tx * 8 + 2];
            ull b2 = *(const ull*)&Bs[kk][tx * 8 + 4];
            ull b3 = *(const ull*)&Bs[kk][tx * 8 + 6];
            ull ap[8];
            ap[0] = pack_dup(a0.x); ap[1] = pack_dup(a0.y);
            ap[2] = pack_dup(a0.z); ap[3] = pack_dup(a0.w);
            ap[4] = pack_dup(a1.x); ap[5] = pack_dup(a1.y);
            ap[6] = pack_dup(a1.z); ap[7] = pack_dup(a1.w);
#pragma unroll
            for (int i = 0; i < 8; i++) {
                ffma2(accp[i][0], ap[i], b0);
                ffma2(accp[i][1], ap[i], b1);
                ffma2(accp[i][2], ap[i], b2);
                ffma2(accp[i][3], ap[i], b3);
            }
        }
        __syncthreads();
    }

#pragma unroll
    for (int i = 0; i < 8; i++) {
        float o[8];
#pragma unroll
        for (int jp = 0; jp < 4; jp++) {
            float2 u = unpack2(accp[i][jp]);
            o[2 * jp] = u.x; o[2 * jp + 1] = u.y;
        }
        size_t base = (size_t)(bm + ty * 8 + i) * N + bn + tx * 8;
        *(float4*)&C[base]     = make_float4(o[0], o[1], o[2], o[3]);
        *(float4*)&C[base + 4] = make_float4(o[4], o[5], o[6], o[7]);
    }
}

// ---------------- RoPE: t shape (B, NSEQ, H, 128), interleaved pairs ----------------
__global__ __launch_bounds__(256) void rope_kernel(
    float* __restrict__ t, const float* __restrict__ cosb,
    const float* __restrict__ sinb, int H, int total)
{
    int idx = blockIdx.x * blockDim.x + threadIdx.x;
    if (idx >= total) return;
    int j   = idx & 63;
    int bnh = idx >> 6;             // (b*NSEQ+n)*H + h
    int n   = (bnh / H) & (NSEQ - 1);
    float c = cosb[n * 64 + j];
    float s = sinb[n * 64 + j];
    float* p = t + ((size_t)bnh << 7) + 2 * j;
    float x0 = p[0], x1 = p[1];
    p[0] = x0 * c - x1 * s;
    p[1] = x0 * s + x1 * c;
}

// ---------------- flash attention (causal, GQA 4:1), fp32 ----------------
// grid: (NSEQ/64, BATCH*NHEAD), 256 threads. Dynamic smem.
#define QPITCH 132
__global__ __launch_bounds__(256) void attn_kernel(
    const float* __restrict__ Q, const float* __restrict__ Kg,
    const float* __restrict__ Vg, float* __restrict__ O)
{
    extern __shared__ float sm_[];
    float* Qs = sm_;                     // 64 x 132
    float* Ks = Qs + 64 * QPITCH;        // 64 x 132
    float* Vs = Ks + 64 * QPITCH;        // 64 x 132
    float* Ps = Vs + 64 * QPITCH;        // 64 x 65
    float* salpha = Ps + 64 * 65;        // 64

    const int tid = threadIdx.x;
    const int qt  = blockIdx.x;
    const int bh  = blockIdx.y;
    const int b   = bh >> 5;
    const int h   = bh & 31;
    const int kvh = h >> 2;

    const float* Qb = Q  + ((size_t)(b * NSEQ) * NHEAD + h)   * HDIM; // +n*4096
    const float* Kb = Kg + ((size_t)(b * NSEQ) * NKV   + kvh) * HDIM; // +n*1024
    const float* Vb = Vg + ((size_t)(b * NSEQ) * NKV   + kvh) * HDIM;

    const int tx = tid & 15;
    const int ty = tid >> 4;

    // load Q tile (64 rows x 128)
#pragma unroll
    for (int t = 0; t < 8; t++) {
        int f = tid + t * 256;          // float4 id, 0..2047
        int r = f >> 5, cc = f & 31;
        *(float4*)&Qs[r * QPITCH + cc * 4] =
            *(const float4*)&Qb[(size_t)(qt * 64 + r) * (NHEAD * HDIM) + cc * 4];
    }

    float acc[4][8];
#pragma unroll
    for (int i = 0; i < 4; i++)
#pragma unroll
        for (int j = 0; j < 8; j++) acc[i][j] = 0.0f;

    float m_r = -1e30f, l_r = 0.0f;   // valid in threads 0..63 (row owners)

    for (int kt = 0; kt <= qt; kt++) {
        __syncthreads();
#pragma unroll
        for (int t = 0; t < 8; t++) {
            int f = tid + t * 256;
            int r = f >> 5, cc = f & 31;
            *(float4*)&Ks[r * QPITCH + cc * 4] =
                *(const float4*)&Kb[(size_t)(kt * 64 + r) * (NKV * HDIM) + cc * 4];
            *(float4*)&Vs[r * QPITCH + cc * 4] =
                *(const float4*)&Vb[(size_t)(kt * 64 + r) * (NKV * HDIM) + cc * 4];
        }
        __syncthreads();

        // S = Q K^T : 4x4 per thread
        float s[4][4];
#pragma unroll
        for (int i = 0; i < 4; i++)
#pragma unroll
            for (int j = 0; j < 4; j++) s[i][j] = 0.0f;

        for (int kk = 0; kk < 128; kk += 4) {
            float4 qv[4], kv[4];
#pragma unroll
            for (int i = 0; i < 4; i++)
                qv[i] = *(const float4*)&Qs[(ty * 4 + i) * QPITCH + kk];
#pragma unroll
            for (int j = 0; j < 4; j++)
                kv[j] = *(const float4*)&Ks[(tx * 4 + j) * QPITCH + kk];
#pragma unroll
            for (int i = 0; i < 4; i++)
#pragma unroll
                for (int j = 0; j < 4; j++) {
                    s[i][j] += qv[i].x * kv[j].x + qv[i].y * kv[j].y
                             + qv[i].z * kv[j].z + qv[i].w * kv[j].w;
                }
        }
#pragma unroll
        for (int i = 0; i < 4; i++)
#pragma unroll
            for (int j = 0; j < 4; j++) {
                int qg = qt * 64 + ty * 4 + i;
                int kg = kt * 64 + tx * 4 + j;
                float v = s[i][j] * ATT_SCALE;
                if (kg > qg) v = -1e30f;
                Ps[(ty * 4 + i) * 65 + tx * 4 + j] = v;
            }
        __syncthreads();

        // online softmax, one thread per row
        if (tid < 64) {
            int r = tid;
            float mnew = m_r;
            for (int c = 0; c < 64; c++) mnew = fmaxf(mnew, Ps[r * 65 + c]);
            float alpha = __expf(m_r - mnew);
            float ssum = 0.0f;
            for (int c = 0; c < 64; c++) {
                float p = __expf(Ps[r * 65 + c] - mnew);
                Ps[r * 65 + c] = p;
                ssum += p;
            }
            l_r = l_r * alpha + ssum;
            m_r = mnew;
            salpha[r] = alpha;
        }
        __syncthreads();

        // O = O*alpha + P V
#pragma unroll
        for (int i = 0; i < 4; i++) {
            float a_ = salpha[ty * 4 + i];
#pragma unroll
            for (int j = 0; j < 8; j++) acc[i][j] *= a_;
        }
        for (int kk = 0; kk < 64; kk++) {
            float4 v0 = *(const float4*)&Vs[kk * QPITCH + tx * 8];
            float4 v1 = *(const float4*)&Vs[kk * QPITCH + tx * 8 + 4];
#pragma unroll
            for (int i = 0; i < 4; i++) {
                float p = Ps[(ty * 4 + i) * 65 + kk];
                acc[i][0] += p * v0.x; acc[i][1] += p * v0.y;
                acc[i][2] += p * v0.z; acc[i][3] += p * v0.w;
                acc[i][4] += p * v1.x; acc[i][5] += p * v1.y;
                acc[i][6] += p * v1.z; acc[i][7] += p * v1.w;
            }
        }
    }

    __syncthreads();
    if (tid < 64) salpha[tid] = 1.0f / l_r;
    __syncthreads();

#pragma unroll
    for (int i = 0; i < 4; i++) {
        float inv = salpha[ty * 4 + i];
        int n = qt * 64 + ty * 4 + i;
        size_t base = ((size_t)(b * NSEQ + n)) * DIMM + h * HDIM + tx * 8;
        *(float4*)&O[base] = make_float4(acc[i][0] * inv, acc[i][1] * inv,
                                         acc[i][2] * inv, acc[i][3] * inv);
        *(float4*)&O[base + 4] = make_float4(acc[i][4] * inv, acc[i][5] * inv,
                                             acc[i][6] * inv, acc[i][7] * inv);
    }
}

// ---------------- launch ----------------
extern "C" void kernel_launch(void* const* d_in, const int* in_sizes, int n_in,
                              void* d_out, int out_size)
{
    const float* x    = (const float*)d_in[0];
    const float* wq   = (const float*)d_in[1];
    const float* wk   = (const float*)d_in[2];
    const float* wv   = (const float*)d_in[3];
    const float* wo   = (const float*)d_in[4];
    const float* cosb = (const float*)d_in[5];
    const float* sinb = (const float*)d_in[6];
    // d_in[7] = mask (we apply causal directly), d_in[8] = start_pos (always 0)
    float* out = (float*)d_out;

    float *pq, *pk, *pv, *pa;
    cudaGetSymbolAddress((void**)&pq, g_q);
    cudaGetSymbolAddress((void**)&pk, g_k);
    cudaGetSymbolAddress((void**)&pv, g_v);
    cudaGetSymbolAddress((void**)&pa, g_attn);

    dim3 blk(256);

    // projections
    gemm_nt_kernel<<<dim3(DIMM / 128, MROWS / 128), blk>>>(x, wq, pq, MROWS, DIMM, DIMM);
    gemm_nt_kernel<<<dim3((NKV * HDIM) / 128, MROWS / 128), blk>>>(x, wk, pk, MROWS, NKV * HDIM, DIMM);
    gemm_nt_kernel<<<dim3((NKV * HDIM) / 128, MROWS / 128), blk>>>(x, wv, pv, MROWS, NKV * HDIM, DIMM);

    // RoPE
    int qtot = BATCH * NSEQ * NHEAD * 64;
    int ktot = BATCH * NSEQ * NKV * 64;
    rope_kernel<<<(qtot + 255) / 256, blk>>>(pq, cosb, sinb, NHEAD, qtot);
    rope_kernel<<<(ktot + 255) / 256, blk>>>(pk, cosb, sinb, NKV, ktot);

    // attention
    const int ATTN_SMEM = (3 * 64 * QPITCH + 64 * 65 + 64) * (int)sizeof(float);
    cudaFuncSetAttribute(attn_kernel, cudaFuncAttributeMaxDynamicSharedMemorySize, ATTN_SMEM);
    attn_kernel<<<dim3(NSEQ / 64, BATCH * NHEAD), blk, ATTN_SMEM>>>(pq, pk, pv, pa);

    // output projection
    gemm_nt_kernel<<<dim3(DIMM / 128, MROWS / 128), blk>>>(pa, wo, out, MROWS, DIMM, DIMM);
}

// round 3
// speedup vs baseline: 2.5665x; 2.5665x over previous
#include <cuda_runtime.h>
#include <cuda_bf16.h>
#include <cstdint>

typedef unsigned long long ull;

// ---------------- constants ----------------
#define BATCH   2
#define NSEQ    2048
#define DIMM    4096
#define NHEAD   32
#define NKV     8
#define HDIM    128
#define MROWS   (BATCH*NSEQ)            // 4096
#define KVDIM   (NKV*HDIM)              // 1024
#define ATT_SCALE 0.08838834764831845f  // 1/sqrt(128)

// ---------------- scratch (device globals; no allocations allowed) ----------------
__device__ float g_q[MROWS * NHEAD * HDIM];
__device__ float g_k[MROWS * NKV * HDIM];
__device__ float g_v[MROWS * NKV * HDIM];
__device__ float g_attn[MROWS * NHEAD * HDIM];

__device__ __nv_bfloat16 g_xh[MROWS * DIMM],  g_xl[MROWS * DIMM];
__device__ __nv_bfloat16 g_wqh[DIMM * DIMM],  g_wql[DIMM * DIMM];
__device__ __nv_bfloat16 g_wkh[KVDIM * DIMM], g_wkl[KVDIM * DIMM];
__device__ __nv_bfloat16 g_wvh[KVDIM * DIMM], g_wvl[KVDIM * DIMM];
__device__ __nv_bfloat16 g_woh[DIMM * DIMM],  g_wol[DIMM * DIMM];
__device__ __nv_bfloat16 g_ah[MROWS * DIMM],  g_al[MROWS * DIMM];

// ---------------- PTX helpers (all plain sm_80+ PTX; no 'a' features) ----------------
__device__ __forceinline__ uint32_t s2u32(const void* p) {
    uint32_t a;
    asm("{ .reg .u64 t; cvta.to.shared.u64 t, %1; cvt.u32.u64 %0, t; }" : "=r"(a) : "l"(p));
    return a;
}
__device__ __forceinline__ void cp16(uint32_t d, const void* s) {
    asm volatile("cp.async.cg.shared.global [%0], [%1], 16;" :: "r"(d), "l"(s));
}
__device__ __forceinline__ void cp_commit() {
    asm volatile("cp.async.commit_group;" ::: "memory");
}
template <int N>
__device__ __forceinline__ void cp_wait() {
    asm volatile("cp.async.wait_group %0;" :: "n"(N) : "memory");
}
__device__ __forceinline__ void ldsm4(uint32_t& r0, uint32_t& r1, uint32_t& r2,
                                      uint32_t& r3, uint32_t addr) {
    asm volatile("ldmatrix.sync.aligned.m8n8.x4.shared.b16 {%0,%1,%2,%3}, [%4];"
                 : "=r"(r0), "=r"(r1), "=r"(r2), "=r"(r3) : "r"(addr));
}
__device__ __forceinline__ void mma16816(float* c, const uint32_t* a, uint32_t b0, uint32_t b1) {
    asm volatile(
        "mma.sync.aligned.m16n8k16.row.col.f32.bf16.bf16.f32 "
        "{%0,%1,%2,%3}, {%4,%5,%6,%7}, {%8,%9}, {%0,%1,%2,%3};"
        : "+f"(c[0]), "+f"(c[1]), "+f"(c[2]), "+f"(c[3])
        : "r"(a[0]), "r"(a[1]), "r"(a[2]), "r"(a[3]), "r"(b0), "r"(b1));
}

// ---------------- hi/lo split: fp32 -> bf16 pair ----------------
__global__ __launch_bounds__(256) void split_kernel(
    const float* __restrict__ src, __nv_bfloat16* __restrict__ hi,
    __nv_bfloat16* __restrict__ lo, int n4)
{
    int i = blockIdx.x * blockDim.x + threadIdx.x;
    if (i >= n4) return;
    float4 v = ((const float4*)src)[i];
    __nv_bfloat16 h0 = __float2bfloat16(v.x);
    __nv_bfloat16 h1 = __float2bfloat16(v.y);
    __nv_bfloat16 h2 = __float2bfloat16(v.z);
    __nv_bfloat16 h3 = __float2bfloat16(v.w);
    __nv_bfloat16 l0 = __float2bfloat16(v.x - __bfloat162float(h0));
    __nv_bfloat16 l1 = __float2bfloat16(v.y - __bfloat162float(h1));
    __nv_bfloat16 l2 = __float2bfloat16(v.z - __bfloat162float(h2));
    __nv_bfloat16 l3 = __float2bfloat16(v.w - __bfloat162float(h3));
    ((__nv_bfloat162*)hi)[2 * i]     = __halves2bfloat162(h0, h1);
    ((__nv_bfloat162*)hi)[2 * i + 1] = __halves2bfloat162(h2, h3);
    ((__nv_bfloat162*)lo)[2 * i]     = __halves2bfloat162(l0, l1);
    ((__nv_bfloat162*)lo)[2 * i + 1] = __halves2bfloat162(l2, l3);
}

// ---------------- mma.sync split-bf16 NT GEMM ----------------
// C[M,N] = (Ah+Al)[M,K] * (Bh+Bl)[N,K]^T, fp32 accum, drop Al*Bl.
// CTA 128x128, BK=32, 256 thr (8 warps, warp tile 32x64), 3-stage cp.async.
#define TILEBYTES (128 * 80)                 // 128 rows x 80B (32 bf16 + pad)
#define STAGEB    (4 * TILEBYTES)            // Ah,Al,Bh,Bl tiles
#define GSMEM     (3 * STAGEB)               // 122,880 B
__global__ __launch_bounds__(256) void gemm_mma(
    const __nv_bfloat16* __restrict__ Ah, const __nv_bfloat16* __restrict__ Al,
    const __nv_bfloat16* __restrict__ Bh, const __nv_bfloat16* __restrict__ Bl,
    float* __restrict__ C, int N, int K)
{
    extern __shared__ char smraw[];
    const uint32_t sbase = s2u32(smraw);

    const int tid  = threadIdx.x;
    const int wid  = tid >> 5;
    const int lane = tid & 31;
    const int bm = blockIdx.y << 7, bn = blockIdx.x << 7;
    const int wm = (wid & 3) * 32;           // warp M offset (0..96)
    const int wn = (wid >> 2) * 64;          // warp N offset (0 or 64)
    const int NCH = K >> 5;

    float acc[2][8][4];
#pragma unroll
    for (int i = 0; i < 2; i++)
#pragma unroll
        for (int j = 0; j < 8; j++)
#pragma unroll
            for (int t = 0; t < 4; t++) acc[i][j][t] = 0.0f;

    const __nv_bfloat16* tsrc[4] = {Ah, Al, Bh, Bl};

    auto load_stage = [&](int ch, int st) {
        const int k0 = ch << 5;
        const uint32_t stb = sbase + st * STAGEB;
#pragma unroll
        for (int i = 0; i < 8; i++) {
            int f = i * 256 + tid;          // 0..2047 16B chunks
            int tile = f >> 9;              // 512 chunks per tile
            int c = f & 511;
            int row = c >> 2, c4 = c & 3;
            const __nv_bfloat16* g = tsrc[tile];
            int rb = (tile < 2) ? bm : bn;
            cp16(stb + tile * TILEBYTES + row * 80 + c4 * 16,
                 g + (size_t)(rb + row) * K + k0 + c4 * 8);
        }
    };

    // ldmatrix per-thread offsets (within a tile, before kk shift)
    uint32_t offA[2], offB[4];
#pragma unroll
    for (int mt = 0; mt < 2; mt++)
        offA[mt] = (uint32_t)((wm + mt * 16 + (lane & 15)) * 80 + (lane >> 4) * 16);
#pragma unroll
    for (int nb = 0; nb < 4; nb++)
        offB[nb] = (uint32_t)((wn + nb * 16 + (lane & 15)) * 80 + (lane >> 4) * 16);

    load_stage(0, 0); cp_commit();
    load_stage(1, 1); cp_commit();

    for (int it = 0; it < NCH; ++it) {
        const int st = it % 3;
        if (it + 2 < NCH) { load_stage(it + 2, (it + 2) % 3); cp_commit(); }
        if (it + 2 < NCH)      cp_wait<2>();
        else if (it + 1 < NCH) cp_wait<1>();
        else                   cp_wait<0>();
        __syncthreads();

        const uint32_t bAh = sbase + st * STAGEB;
        const uint32_t bAl = bAh + TILEBYTES;
        const uint32_t bBh = bAh + 2 * TILEBYTES;
        const uint32_t bBl = bAh + 3 * TILEBYTES;

#pragma unroll
        for (int kk = 0; kk < 2; kk++) {
            const uint32_t ks = kk * 32;    // 16 bf16 = 32 bytes
            uint32_t ah[2][4], al[2][4], bh[4][4], bl[4][4];
#pragma unroll
            for (int mt = 0; mt < 2; mt++) {
                ldsm4(ah[mt][0], ah[mt][1], ah[mt][2], ah[mt][3], bAh + offA[mt] + ks);
                ldsm4(al[mt][0], al[mt][1], al[mt][2], al[mt][3], bAl + offA[mt] + ks);
            }
#pragma unroll
            for (int nb = 0; nb < 4; nb++) {
                ldsm4(bh[nb][0], bh[nb][1], bh[nb][2], bh[nb][3], bBh + offB[nb] + ks);
                ldsm4(bl[nb][0], bl[nb][1], bl[nb][2], bl[nb][3], bBl + offB[nb] + ks);
            }
#pragma unroll
            for (int mt = 0; mt < 2; mt++)
#pragma unroll
                for (int nb = 0; nb < 4; nb++)
#pragma unroll
                    for (int hf = 0; hf < 2; hf++) {
                        float* c = acc[mt][nb * 2 + hf];
                        mma16816(c, ah[mt], bh[nb][hf], bh[nb][hf + 2]);
                        mma16816(c, ah[mt], bl[nb][hf], bl[nb][hf + 2]);
                        mma16816(c, al[mt], bh[nb][hf], bh[nb][hf + 2]);
                    }
        }
        __syncthreads();
    }

    // epilogue: mma c-frag layout -> global
#pragma unroll
    for (int mt = 0; mt < 2; mt++) {
        int r0 = bm + wm + mt * 16 + (lane >> 2);
#pragma unroll
        for (int nt = 0; nt < 8; nt++) {
            int c0 = bn + wn + nt * 8 + (lane & 3) * 2;
            float* p = acc[mt][nt];
            *(float2*)&C[(size_t)r0 * N + c0]       = make_float2(p[0], p[1]);
            *(float2*)&C[(size_t)(r0 + 8) * N + c0] = make_float2(p[2], p[3]);
        }
    }
}

// ---------------- RoPE ----------------
__global__ __launch_bounds__(256) void rope_kernel(
    float* __restrict__ t, const float* __restrict__ cosb,
    const float* __restrict__ sinb, int H, int total)
{
    int idx = blockIdx.x * blockDim.x + threadIdx.x;
    if (idx >= total) return;
    int j   = idx & 63;
    int bnh = idx >> 6;
    int n   = (bnh / H) & (NSEQ - 1);
    float c = cosb[n * 64 + j];
    float s = sinb[n * 64 + j];
    float* p = t + ((size_t)bnh << 7) + 2 * j;
    float x0 = p[0], x1 = p[1];
    p[0] = x0 * c - x1 * s;
    p[1] = x0 * s + x1 * c;
}

// ---------------- flash attention (causal, GQA 4:1), fp32 ----------------
#define QPITCH 132
__global__ __launch_bounds__(256) void attn_kernel(
    const float* __restrict__ Q, const float* __restrict__ Kg,
    const float* __restrict__ Vg, float* __restrict__ O)
{
    extern __shared__ float sm_[];
    float* Qs = sm_;
    float* Ks = Qs + 64 * QPITCH;
    float* Vs = Ks + 64 * QPITCH;
    float* Ps = Vs + 64 * QPITCH;
    float* salpha = Ps + 64 * 65;

    const int tid = threadIdx.x;
    const int qt  = blockIdx.x;
    const int bh  = blockIdx.y;
    const int b   = bh >> 5;
    const int h   = bh & 31;
    const int kvh = h >> 2;

    const float* Qb = Q  + ((size_t)(b * NSEQ) * NHEAD + h)   * HDIM;
    const float* Kb = Kg + ((size_t)(b * NSEQ) * NKV   + kvh) * HDIM;
    const float* Vb = Vg + ((size_t)(b * NSEQ) * NKV   + kvh) * HDIM;

    const int tx = tid & 15;
    const int ty = tid >> 4;

#pragma unroll
    for (int t = 0; t < 8; t++) {
        int f = tid + t * 256;
        int r = f >> 5, cc = f & 31;
        *(float4*)&Qs[r * QPITCH + cc * 4] =
            *(const float4*)&Qb[(size_t)(qt * 64 + r) * (NHEAD * HDIM) + cc * 4];
    }

    float acc[4][8];
#pragma unroll
    for (int i = 0; i < 4; i++)
#pragma unroll
        for (int j = 0; j < 8; j++) acc[i][j] = 0.0f;

    float m_r = -1e30f, l_r = 0.0f;

    for (int kt = 0; kt <= qt; kt++) {
        __syncthreads();
#pragma unroll
        for (int t = 0; t < 8; t++) {
            int f = tid + t * 256;
            int r = f >> 5, cc = f & 31;
            *(float4*)&Ks[r * QPITCH + cc * 4] =
                *(const float4*)&Kb[(size_t)(kt * 64 + r) * (NKV * HDIM) + cc * 4];
            *(float4*)&Vs[r * QPITCH + cc * 4] =
                *(const float4*)&Vb[(size_t)(kt * 64 + r) * (NKV * HDIM) + cc * 4];
        }
        __syncthreads();

        float s[4][4];
#pragma unroll
        for (int i = 0; i < 4; i++)
#pragma unroll
            for (int j = 0; j < 4; j++) s[i][j] = 0.0f;

        for (int kk = 0; kk < 128; kk += 4) {
            float4 qv[4], kv[4];
#pragma unroll
            for (int i = 0; i < 4; i++)
                qv[i] = *(const float4*)&Qs[(ty * 4 + i) * QPITCH + kk];
#pragma unroll
            for (int j = 0; j < 4; j++)
                kv[j] = *(const float4*)&Ks[(tx * 4 + j) * QPITCH + kk];
#pragma unroll
            for (int i = 0; i < 4; i++)
#pragma unroll
                for (int j = 0; j < 4; j++) {
                    s[i][j] += qv[i].x * kv[j].x + qv[i].y * kv[j].y
                             + qv[i].z * kv[j].z + qv[i].w * kv[j].w;
                }
        }
#pragma unroll
        for (int i = 0; i < 4; i++)
#pragma unroll
            for (int j = 0; j < 4; j++) {
                int qg = qt * 64 + ty * 4 + i;
                int kg = kt * 64 + tx * 4 + j;
                float v = s[i][j] * ATT_SCALE;
                if (kg > qg) v = -1e30f;
                Ps[(ty * 4 + i) * 65 + tx * 4 + j] = v;
            }
        __syncthreads();

        if (tid < 64) {
            int r = tid;
            float mnew = m_r;
            for (int c = 0; c < 64; c++) mnew = fmaxf(mnew, Ps[r * 65 + c]);
            float alpha = __expf(m_r - mnew);
            float ssum = 0.0f;
            for (int c = 0; c < 64; c++) {
                float p = __expf(Ps[r * 65 + c] - mnew);
                Ps[r * 65 + c] = p;
                ssum += p;
            }
            l_r = l_r * alpha + ssum;
            m_r = mnew;
            salpha[r] = alpha;
        }
        __syncthreads();

#pragma unroll
        for (int i = 0; i < 4; i++) {
            float a_ = salpha[ty * 4 + i];
#pragma unroll
            for (int j = 0; j < 8; j++) acc[i][j] *= a_;
        }
        for (int kk = 0; kk < 64; kk++) {
            float4 v0 = *(const float4*)&Vs[kk * QPITCH + tx * 8];
            float4 v1 = *(const float4*)&Vs[kk * QPITCH + tx * 8 + 4];
#pragma unroll
            for (int i = 0; i < 4; i++) {
                float p = Ps[(ty * 4 + i) * 65 + kk];
                acc[i][0] += p * v0.x; acc[i][1] += p * v0.y;
                acc[i][2] += p * v0.z; acc[i][3] += p * v0.w;
                acc[i][4] += p * v1.x; acc[i][5] += p * v1.y;
                acc[i][6] += p * v1.z; acc[i][7] += p * v1.w;
            }
        }
    }

    __syncthreads();
    if (tid < 64) salpha[tid] = 1.0f / l_r;
    __syncthreads();

#pragma unroll
    for (int i = 0; i < 4; i++) {
        float inv = salpha[ty * 4 + i];
        int n = qt * 64 + ty * 4 + i;
        size_t base = ((size_t)(b * NSEQ + n)) * DIMM + h * HDIM + tx * 8;
        *(float4*)&O[base] = make_float4(acc[i][0] * inv, acc[i][1] * inv,
                                         acc[i][2] * inv, acc[i][3] * inv);
        *(float4*)&O[base + 4] = make_float4(acc[i][4] * inv, acc[i][5] * inv,
                                             acc[i][6] * inv, acc[i][7] * inv);
    }
}

// ---------------- launch ----------------
extern "C" void kernel_launch(void* const* d_in, const int* in_sizes, int n_in,
                              void* d_out, int out_size)
{
    const float* x    = (const float*)d_in[0];
    const float* wq   = (const float*)d_in[1];
    const float* wk   = (const float*)d_in[2];
    const float* wv   = (const float*)d_in[3];
    const float* wo   = (const float*)d_in[4];
    const float* cosb = (const float*)d_in[5];
    const float* sinb = (const float*)d_in[6];
    float* out = (float*)d_out;

    float *pq, *pk, *pv, *pa;
    cudaGetSymbolAddress((void**)&pq, g_q);
    cudaGetSymbolAddress((void**)&pk, g_k);
    cudaGetSymbolAddress((void**)&pv, g_v);
    cudaGetSymbolAddress((void**)&pa, g_attn);
    __nv_bfloat16 *xh, *xl, *wqh, *wql, *wkh, *wkl, *wvh, *wvl, *woh, *wol, *ah, *al;
    cudaGetSymbolAddress((void**)&xh,  g_xh);  cudaGetSymbolAddress((void**)&xl,  g_xl);
    cudaGetSymbolAddress((void**)&wqh, g_wqh); cudaGetSymbolAddress((void**)&wql, g_wql);
    cudaGetSymbolAddress((void**)&wkh, g_wkh); cudaGetSymbolAddress((void**)&wkl, g_wkl);
    cudaGetSymbolAddress((void**)&wvh, g_wvh); cudaGetSymbolAddress((void**)&wvl, g_wvl);
    cudaGetSymbolAddress((void**)&woh, g_woh); cudaGetSymbolAddress((void**)&wol, g_wol);
    cudaGetSymbolAddress((void**)&ah,  g_ah);  cudaGetSymbolAddress((void**)&al,  g_al);

    cudaFuncSetAttribute(gemm_mma, cudaFuncAttributeMaxDynamicSharedMemorySize, GSMEM);
    const int ATTN_SMEM = (3 * 64 * QPITCH + 64 * 65 + 64) * (int)sizeof(float);
    cudaFuncSetAttribute(attn_kernel, cudaFuncAttributeMaxDynamicSharedMemorySize, ATTN_SMEM);

    dim3 blk(256);

    // hi/lo splits
    split_kernel<<<(MROWS * DIMM / 4 + 255) / 256, blk>>>(x,  xh,  xl,  MROWS * DIMM / 4);
    split_kernel<<<(DIMM * DIMM / 4 + 255) / 256, blk>>>(wq, wqh, wql, DIMM * DIMM / 4);
    split_kernel<<<(KVDIM * DIMM / 4 + 255) / 256, blk>>>(wk, wkh, wkl, KVDIM * DIMM / 4);
    split_kernel<<<(KVDIM * DIMM / 4 + 255) / 256, blk>>>(wv, wvh, wvl, KVDIM * DIMM / 4);
    split_kernel<<<(DIMM * DIMM / 4 + 255) / 256, blk>>>(wo, woh, wol, DIMM * DIMM / 4);

    // projections on tensor cores (mma.sync)
    gemm_mma<<<dim3(DIMM / 128, MROWS / 128), blk, GSMEM>>>(xh, xl, wqh, wql, pq, DIMM, DIMM);
    gemm_mma<<<dim3(KVDIM / 128, MROWS / 128), blk, GSMEM>>>(xh, xl, wkh, wkl, pk, KVDIM, DIMM);
    gemm_mma<<<dim3(KVDIM / 128, MROWS / 128), blk, GSMEM>>>(xh, xl, wvh, wvl, pv, KVDIM, DIMM);

    // RoPE
    int qtot = BATCH * NSEQ * NHEAD * 64;
    int ktot = BATCH * NSEQ * NKV * 64;
    rope_kernel<<<(qtot + 255) / 256, blk>>>(pq, cosb, sinb, NHEAD, qtot);
    rope_kernel<<<(ktot + 255) / 256, blk>>>(pk, cosb, sinb, NKV, ktot);

    // attention
    attn_kernel<<<dim3(NSEQ / 64, BATCH * NHEAD), blk, ATTN_SMEM>>>(pq, pk, pv, pa);

    // output projection
    split_kernel<<<(MROWS * DIMM / 4 + 255) / 256, blk>>>(pa, ah, al, MROWS * DIMM / 4);
    gemm_mma<<<dim3(DIMM / 128, MROWS / 128), blk, GSMEM>>>(ah, al, woh, wol, out, DIMM, DIMM);
}

// round 4
// speedup vs baseline: 4.5321x; 1.7659x over previous
#include <cuda_runtime.h>
#include <cuda_bf16.h>
#include <cuda_fp16.h>
#include <cstdint>

typedef unsigned long long ull;

// ---------------- constants ----------------
#define BATCH   2
#define NSEQ    2048
#define DIMM    4096
#define NHEAD   32
#define NKV     8
#define HDIM    128
#define MROWS   (BATCH*NSEQ)            // 4096
#define KVDIM   (NKV*HDIM)              // 1024
#define ATT_SCALE 0.08838834764831845f  // 1/sqrt(128)

// ---------------- scratch (device globals; no allocations allowed) ----------------
__device__ float g_q[MROWS * NHEAD * HDIM];
__device__ float g_k[MROWS * NKV * HDIM];
__device__ float g_v[MROWS * NKV * HDIM];
__device__ float g_attn[MROWS * NHEAD * HDIM];

__device__ __nv_bfloat16 g_xh[MROWS * DIMM],  g_xl[MROWS * DIMM];
__device__ __nv_bfloat16 g_wqh[DIMM * DIMM],  g_wql[DIMM * DIMM];
__device__ __nv_bfloat16 g_wkh[KVDIM * DIMM], g_wkl[KVDIM * DIMM];
__device__ __nv_bfloat16 g_wvh[KVDIM * DIMM], g_wvl[KVDIM * DIMM];
__device__ __nv_bfloat16 g_woh[DIMM * DIMM],  g_wol[DIMM * DIMM];
__device__ __nv_bfloat16 g_ah[MROWS * DIMM],  g_al[MROWS * DIMM];

__device__ __half g_k16h[MROWS * KVDIM], g_k16l[MROWS * KVDIM];
__device__ __half g_v16[MROWS * KVDIM];

// ---------------- PTX helpers (plain sm_80+ PTX) ----------------
__device__ __forceinline__ uint32_t s2u32(const void* p) {
    uint32_t a;
    asm("{ .reg .u64 t; cvta.to.shared.u64 t, %1; cvt.u32.u64 %0, t; }" : "=r"(a) : "l"(p));
    return a;
}
__device__ __forceinline__ void cp16(uint32_t d, const void* s) {
    asm volatile("cp.async.cg.shared.global [%0], [%1], 16;" :: "r"(d), "l"(s));
}
__device__ __forceinline__ void cp_commit() {
    asm volatile("cp.async.commit_group;" ::: "memory");
}
template <int N>
__device__ __forceinline__ void cp_wait() {
    asm volatile("cp.async.wait_group %0;" :: "n"(N) : "memory");
}
__device__ __forceinline__ void ldsm4(uint32_t& r0, uint32_t& r1, uint32_t& r2,
                                      uint32_t& r3, uint32_t addr) {
    asm volatile("ldmatrix.sync.aligned.m8n8.x4.shared.b16 {%0,%1,%2,%3}, [%4];"
                 : "=r"(r0), "=r"(r1), "=r"(r2), "=r"(r3) : "r"(addr));
}
__device__ __forceinline__ void ldsm4t(uint32_t& r0, uint32_t& r1, uint32_t& r2,
                                       uint32_t& r3, uint32_t addr) {
    asm volatile("ldmatrix.sync.aligned.m8n8.x4.trans.shared.b16 {%0,%1,%2,%3}, [%4];"
                 : "=r"(r0), "=r"(r1), "=r"(r2), "=r"(r3) : "r"(addr));
}
__device__ __forceinline__ void mma16816(float* c, const uint32_t* a, uint32_t b0, uint32_t b1) {
    asm volatile(
        "mma.sync.aligned.m16n8k16.row.col.f32.bf16.bf16.f32 "
        "{%0,%1,%2,%3}, {%4,%5,%6,%7}, {%8,%9}, {%0,%1,%2,%3};"
        : "+f"(c[0]), "+f"(c[1]), "+f"(c[2]), "+f"(c[3])
        : "r"(a[0]), "r"(a[1]), "r"(a[2]), "r"(a[3]), "r"(b0), "r"(b1));
}
__device__ __forceinline__ void mma16816f(float* c, const uint32_t* a, uint32_t b0, uint32_t b1) {
    asm volatile(
        "mma.sync.aligned.m16n8k16.row.col.f32.f16.f16.f32 "
        "{%0,%1,%2,%3}, {%4,%5,%6,%7}, {%8,%9}, {%0,%1,%2,%3};"
        : "+f"(c[0]), "+f"(c[1]), "+f"(c[2]), "+f"(c[3])
        : "r"(a[0]), "r"(a[1]), "r"(a[2]), "r"(a[3]), "r"(b0), "r"(b1));
}
__device__ __forceinline__ uint32_t packh2(float x, float y) {
    __half2 h = __floats2half2_rn(x, y);
    return *(uint32_t*)&h;
}

// ---------------- hi/lo split: fp32 -> bf16 pair ----------------
__global__ __launch_bounds__(256) void split_kernel(
    const float* __restrict__ src, __nv_bfloat16* __restrict__ hi,
    __nv_bfloat16* __restrict__ lo, int n4)
{
    int i = blockIdx.x * blockDim.x + threadIdx.x;
    if (i >= n4) return;
    float4 v = ((const float4*)src)[i];
    __nv_bfloat16 h0 = __float2bfloat16(v.x);
    __nv_bfloat16 h1 = __float2bfloat16(v.y);
    __nv_bfloat16 h2 = __float2bfloat16(v.z);
    __nv_bfloat16 h3 = __float2bfloat16(v.w);
    __nv_bfloat16 l0 = __float2bfloat16(v.x - __bfloat162float(h0));
    __nv_bfloat16 l1 = __float2bfloat16(v.y - __bfloat162float(h1));
    __nv_bfloat16 l2 = __float2bfloat16(v.z - __bfloat162float(h2));
    __nv_bfloat16 l3 = __float2bfloat16(v.w - __bfloat162float(h3));
    ((__nv_bfloat162*)hi)[2 * i]     = __halves2bfloat162(h0, h1);
    ((__nv_bfloat162*)hi)[2 * i + 1] = __halves2bfloat162(h2, h3);
    ((__nv_bfloat162*)lo)[2 * i]     = __halves2bfloat162(l0, l1);
    ((__nv_bfloat162*)lo)[2 * i + 1] = __halves2bfloat162(l2, l3);
}

// ---------------- hi/lo split: fp32 -> fp16 pair ----------------
__global__ __launch_bounds__(256) void splitf16_kernel(
    const float* __restrict__ src, __half* __restrict__ hi,
    __half* __restrict__ lo, int n4)
{
    int i = blockIdx.x * blockDim.x + threadIdx.x;
    if (i >= n4) return;
    float4 v = ((const float4*)src)[i];
    __half h0 = __float2half_rn(v.x), h1 = __float2half_rn(v.y);
    __half h2 = __float2half_rn(v.z), h3 = __float2half_rn(v.w);
    __half l0 = __float2half_rn(v.x - __half2float(h0));
    __half l1 = __float2half_rn(v.y - __half2float(h1));
    __half l2 = __float2half_rn(v.z - __half2float(h2));
    __half l3 = __float2half_rn(v.w - __half2float(h3));
    ((__half2*)hi)[2 * i]     = __halves2half2(h0, h1);
    ((__half2*)hi)[2 * i + 1] = __halves2half2(h2, h3);
    ((__half2*)lo)[2 * i]     = __halves2half2(l0, l1);
    ((__half2*)lo)[2 * i + 1] = __halves2half2(l2, l3);
}

// ---------------- fp32 -> fp16 convert ----------------
__global__ __launch_bounds__(256) void cvt16_kernel(
    const float* __restrict__ src, __half* __restrict__ dst, int n4)
{
    int i = blockIdx.x * blockDim.x + threadIdx.x;
    if (i >= n4) return;
    float4 v = ((const float4*)src)[i];
    ((__half2*)dst)[2 * i]     = __floats2half2_rn(v.x, v.y);
    ((__half2*)dst)[2 * i + 1] = __floats2half2_rn(v.z, v.w);
}

// ---------------- mma.sync split-bf16 NT GEMM (unchanged from R3) ----------------
#define TILEBYTES (128 * 80)
#define STAGEB    (4 * TILEBYTES)
#define GSMEM     (3 * STAGEB)
__global__ __launch_bounds__(256) void gemm_mma(
    const __nv_bfloat16* __restrict__ Ah, const __nv_bfloat16* __restrict__ Al,
    const __nv_bfloat16* __restrict__ Bh, const __nv_bfloat16* __restrict__ Bl,
    float* __restrict__ C, int N, int K)
{
    extern __shared__ char smraw[];
    const uint32_t sbase = s2u32(smraw);

    const int tid  = threadIdx.x;
    const int wid  = tid >> 5;
    const int lane = tid & 31;
    const int bm = blockIdx.y << 7, bn = blockIdx.x << 7;
    const int wm = (wid & 3) * 32;
    const int wn = (wid >> 2) * 64;
    const int NCH = K >> 5;

    float acc[2][8][4];
#pragma unroll
    for (int i = 0; i < 2; i++)
#pragma unroll
        for (int j = 0; j < 8; j++)
#pragma unroll
            for (int t = 0; t < 4; t++) acc[i][j][t] = 0.0f;

    const __nv_bfloat16* tsrc[4] = {Ah, Al, Bh, Bl};

    auto load_stage = [&](int ch, int st) {
        const int k0 = ch << 5;
        const uint32_t stb = sbase + st * STAGEB;
#pragma unroll
        for (int i = 0; i < 8; i++) {
            int f = i * 256 + tid;
            int tile = f >> 9;
            int c = f & 511;
            int row = c >> 2, c4 = c & 3;
            const __nv_bfloat16* g = tsrc[tile];
            int rb = (tile < 2) ? bm : bn;
            cp16(stb + tile * TILEBYTES + row * 80 + c4 * 16,
                 g + (size_t)(rb + row) * K + k0 + c4 * 8);
        }
    };

    uint32_t offA[2], offB[4];
#pragma unroll
    for (int mt = 0; mt < 2; mt++)
        offA[mt] = (uint32_t)((wm + mt * 16 + (lane & 15)) * 80 + (lane >> 4) * 16);
#pragma unroll
    for (int nb = 0; nb < 4; nb++)
        offB[nb] = (uint32_t)((wn + nb * 16 + (lane & 15)) * 80 + (lane >> 4) * 16);

    load_stage(0, 0); cp_commit();
    load_stage(1, 1); cp_commit();

    for (int it = 0; it < NCH; ++it) {
        const int st = it % 3;
        if (it + 2 < NCH) { load_stage(it + 2, (it + 2) % 3); cp_commit(); }
        if (it + 2 < NCH)      cp_wait<2>();
        else if (it + 1 < NCH) cp_wait<1>();
        else                   cp_wait<0>();
        __syncthreads();

        const uint32_t bAh = sbase + st * STAGEB;
        const uint32_t bAl = bAh + TILEBYTES;
        const uint32_t bBh = bAh + 2 * TILEBYTES;
        const uint32_t bBl = bAh + 3 * TILEBYTES;

#pragma unroll
        for (int kk = 0; kk < 2; kk++) {
            const uint32_t ks = kk * 32;
            uint32_t ah[2][4], al[2][4], bh[4][4], bl[4][4];
#pragma unroll
            for (int mt = 0; mt < 2; mt++) {
                ldsm4(ah[mt][0], ah[mt][1], ah[mt][2], ah[mt][3], bAh + offA[mt] + ks);
                ldsm4(al[mt][0], al[mt][1], al[mt][2], al[mt][3], bAl + offA[mt] + ks);
            }
#pragma unroll
            for (int nb = 0; nb < 4; nb++) {
                ldsm4(bh[nb][0], bh[nb][1], bh[nb][2], bh[nb][3], bBh + offB[nb] + ks);
                ldsm4(bl[nb][0], bl[nb][1], bl[nb][2], bl[nb][3], bBl + offB[nb] + ks);
            }
#pragma unroll
            for (int mt = 0; mt < 2; mt++)
#pragma unroll
                for (int nb = 0; nb < 4; nb++)
#pragma unroll
                    for (int hf = 0; hf < 2; hf++) {
                        float* c = acc[mt][nb * 2 + hf];
                        mma16816(c, ah[mt], bh[nb][hf], bh[nb][hf + 2]);
                        mma16816(c, ah[mt], bl[nb][hf], bl[nb][hf + 2]);
                        mma16816(c, al[mt], bh[nb][hf], bh[nb][hf + 2]);
                    }
        }
        __syncthreads();
    }

#pragma unroll
    for (int mt = 0; mt < 2; mt++) {
        int r0 = bm + wm + mt * 16 + (lane >> 2);
#pragma unroll
        for (int nt = 0; nt < 8; nt++) {
            int c0 = bn + wn + nt * 8 + (lane & 3) * 2;
            float* p = acc[mt][nt];
            *(float2*)&C[(size_t)r0 * N + c0]       = make_float2(p[0], p[1]);
            *(float2*)&C[(size_t)(r0 + 8) * N + c0] = make_float2(p[2], p[3]);
        }
    }
}

// ---------------- RoPE ----------------
__global__ __launch_bounds__(256) void rope_kernel(
    float* __restrict__ t, const float* __restrict__ cosb,
    const float* __restrict__ sinb, int H, int total)
{
    int idx = blockIdx.x * blockDim.x + threadIdx.x;
    if (idx >= total) return;
    int j   = idx & 63;
    int bnh = idx >> 6;
    int n   = (bnh / H) & (NSEQ - 1);
    float c = cosb[n * 64 + j];
    float s = sinb[n * 64 + j];
    float* p = t + ((size_t)bnh << 7) + 2 * j;
    float x0 = p[0], x1 = p[1];
    p[0] = x0 * c - x1 * s;
    p[1] = x0 * s + x1 * c;
}

// ---------------- flash attention via mma.sync ----------------
// 128 q-rows/CTA, 8 warps x 16 rows, 64-key tiles double buffered.
// S: fp16 hi/lo 3-pass; PV: fp16 single pass. fp32 softmax/accum.
#define APITCH  272
#define QS_BYTES (128 * APITCH)         // 34816
#define KVTILE   (64 * APITCH)          // 17408
#define STG      (3 * KVTILE)           // 52224 (Kh, Kl, V)
#define ASMEM    (2 * QS_BYTES + 2 * STG)   // 174080
__global__ __launch_bounds__(256) void attn_mma(
    const float* __restrict__ Q, const __half* __restrict__ Kh,
    const __half* __restrict__ Kl, const __half* __restrict__ V,
    float* __restrict__ O)
{
    extern __shared__ char smraw[];
    const uint32_t sb = s2u32(smraw);
    const uint32_t qh_s = sb;
    const uint32_t ql_s = sb + QS_BYTES;
    const uint32_t kvb  = sb + 2 * QS_BYTES;

    const int tid = threadIdx.x;
    const int wid = tid >> 5, lane = tid & 31;
    const int qt = blockIdx.x;
    const int bh = blockIdx.y;
    const int b = bh >> 5, h = bh & 31;
    const int kvh = h >> 2;

    // ---- stage Q (scaled, fp16 hi/lo) into smem ----
    {
        const float* qbase = Q + ((size_t)(b * NSEQ + qt * 128) * NHEAD + h) * HDIM;
#pragma unroll
        for (int i = 0; i < 32; i++) {
            int idx = tid + i * 256;            // float2 id, 8192 total
            int r = idx >> 6, c2 = idx & 63;
            float2 v = *(const float2*)(qbase + (size_t)r * (NHEAD * HDIM) + c2 * 2);
            v.x *= ATT_SCALE; v.y *= ATT_SCALE;
            __half hx = __float2half_rn(v.x), hy = __float2half_rn(v.y);
            __half lx = __float2half_rn(v.x - __half2float(hx));
            __half ly = __float2half_rn(v.y - __half2float(hy));
            uint32_t off = (uint32_t)(r * APITCH + c2 * 4);
            *(__half2*)(smraw + off)            = __halves2half2(hx, hy);
            *(__half2*)(smraw + QS_BYTES + off) = __halves2half2(lx, ly);
        }
    }

    const size_t kvstride = (size_t)NKV * HDIM;
    auto load_kv = [&](int kt, int st) {
        const uint32_t stb = kvb + st * STG;
        const size_t row0 = ((size_t)(b * NSEQ + kt * 64) * NKV + kvh) * HDIM;
#pragma unroll
        for (int i = 0; i < 12; i++) {
            int f = i * 256 + tid;              // 0..3071 16B chunks
            int tile = f >> 10;
            int c = f & 1023;
            int row = c >> 4, ch = c & 15;
            const __half* src = (tile == 0 ? Kh : (tile == 1 ? Kl : V))
                                + row0 + (size_t)row * kvstride + ch * 8;
            cp16(stb + tile * KVTILE + row * APITCH + ch * 16, src);
        }
    };

    float o[16][4];
#pragma unroll
    for (int t = 0; t < 16; t++)
#pragma unroll
        for (int r = 0; r < 4; r++) o[t][r] = 0.0f;
    float m0 = -1e30f, m1 = -1e30f, l0 = 0.0f, l1 = 0.0f;

    const int NIT = 2 * qt + 2;
    load_kv(0, 0); cp_commit();

    const int rowA = qt * 128 + wid * 16 + (lane >> 2);   // global q row (A half)
    const uint32_t aoff = (uint32_t)((wid * 16 + (lane & 15)) * APITCH + (lane >> 4) * 16);

    for (int it = 0; it < NIT; it++) {
        const int st = it & 1;
        if (it + 1 < NIT) { load_kv(it + 1, (it + 1) & 1); cp_commit(); cp_wait<1>(); }
        else              { cp_wait<0>(); }
        __syncthreads();

        const uint32_t kh_t = kvb + st * STG;
        const uint32_t kl_t = kh_t + KVTILE;
        const uint32_t v_t  = kh_t + 2 * KVTILE;

        // ---- S = Q K^T (3-pass fp16) ----
        float s[8][4];
#pragma unroll
        for (int t = 0; t < 8; t++)
#pragma unroll
            for (int r = 0; r < 4; r++) s[t][r] = 0.0f;

#pragma unroll
        for (int kki = 0; kki < 8; kki++) {
            uint32_t ah[4], al[4];
            ldsm4(ah[0], ah[1], ah[2], ah[3], qh_s + aoff + kki * 32);
            ldsm4(al[0], al[1], al[2], al[3], ql_s + aoff + kki * 32);
#pragma unroll
            for (int g = 0; g < 4; g++) {
                uint32_t boff = (uint32_t)((16 * g + (lane & 15)) * APITCH
                                           + (kki * 2 + (lane >> 4)) * 16);
                uint32_t b0, b1, b2, b3, c0, c1, c2, c3;
                ldsm4(b0, b1, b2, b3, kh_t + boff);
                ldsm4(c0, c1, c2, c3, kl_t + boff);
                mma16816f(s[2 * g],     ah, b0, b2);
                mma16816f(s[2 * g],     ah, c0, c2);
                mma16816f(s[2 * g],     al, b0, b2);
                mma16816f(s[2 * g + 1], ah, b1, b3);
                mma16816f(s[2 * g + 1], ah, c1, c3);
                mma16816f(s[2 * g + 1], al, b1, b3);
            }
        }

        // ---- causal mask on diagonal tiles ----
        if (it >= 2 * qt) {
            const int kbase = it * 64 + (lane & 3) * 2;
#pragma unroll
            for (int t = 0; t < 8; t++) {
                int k0 = kbase + t * 8;
                if (k0     > rowA)     s[t][0] = -1e30f;
                if (k0 + 1 > rowA)     s[t][1] = -1e30f;
                if (k0     > rowA + 8) s[t][2] = -1e30f;
                if (k0 + 1 > rowA + 8) s[t][3] = -1e30f;
            }
        }

        // ---- online softmax (warp-internal) ----
        float mxA = m0, mxB = m1;
#pragma unroll
        for (int t = 0; t < 8; t++) {
            mxA = fmaxf(mxA, fmaxf(s[t][0], s[t][1]));
            mxB = fmaxf(mxB, fmaxf(s[t][2], s[t][3]));
        }
        mxA = fmaxf(mxA, __shfl_xor_sync(0xFFFFFFFFu, mxA, 1));
        mxA = fmaxf(mxA, __shfl_xor_sync(0xFFFFFFFFu, mxA, 2));
        mxB = fmaxf(mxB, __shfl_xor_sync(0xFFFFFFFFu, mxB, 1));
        mxB = fmaxf(mxB, __shfl_xor_sync(0xFFFFFFFFu, mxB, 2));

        float aA = __expf(m0 - mxA), aB = __expf(m1 - mxB);
        float sA = 0.0f, sB = 0.0f;
#pragma unroll
        for (int t = 0; t < 8; t++) {
            s[t][0] = __expf(s[t][0] - mxA);
            s[t][1] = __expf(s[t][1] - mxA);
            s[t][2] = __expf(s[t][2] - mxB);
            s[t][3] = __expf(s[t][3] - mxB);
            sA += s[t][0] + s[t][1];
            sB += s[t][2] + s[t][3];
        }
        sA += __shfl_xor_sync(0xFFFFFFFFu, sA, 1);
        sA += __shfl_xor_sync(0xFFFFFFFFu, sA, 2);
        sB += __shfl_xor_sync(0xFFFFFFFFu, sB, 1);
        sB += __shfl_xor_sync(0xFFFFFFFFu, sB, 2);
        l0 = l0 * aA + sA;  l1 = l1 * aB + sB;
        m0 = mxA;           m1 = mxB;

#pragma unroll
        for (int t = 0; t < 16; t++) {
            o[t][0] *= aA; o[t][1] *= aA;
            o[t][2] *= aB; o[t][3] *= aB;
        }

        // ---- P -> fp16 A-frags, PV single pass ----
        uint32_t ap[4][4];
#pragma unroll
        for (int kk = 0; kk < 4; kk++) {
            ap[kk][0] = packh2(s[2 * kk][0],     s[2 * kk][1]);
            ap[kk][1] = packh2(s[2 * kk][2],     s[2 * kk][3]);
            ap[kk][2] = packh2(s[2 * kk + 1][0], s[2 * kk + 1][1]);
            ap[kk][3] = packh2(s[2 * kk + 1][2], s[2 * kk + 1][3]);
        }
        const uint32_t vrow = (uint32_t)((((lane >> 3) & 1) * 8 + (lane & 7)) * APITCH
                                         + (lane >> 4) * 16);
#pragma unroll
        for (int kk = 0; kk < 4; kk++) {
#pragma unroll
            for (int g = 0; g < 8; g++) {
                uint32_t v0, v1, v2, v3;
                ldsm4t(v0, v1, v2, v3, v_t + vrow + (uint32_t)(16 * kk * APITCH + g * 32));
                mma16816f(o[2 * g],     ap[kk], v0, v1);
                mma16816f(o[2 * g + 1], ap[kk], v2, v3);
            }
        }
        __syncthreads();
    }

    // ---- final normalize + store ----
    const float iA = 1.0f / l0, iB = 1.0f / l1;
    float* obase = O + ((size_t)(b * NSEQ) * NHEAD + h) * HDIM;
#pragma unroll
    for (int t = 0; t < 16; t++) {
        int d = t * 8 + (lane & 3) * 2;
        *(float2*)(obase + (size_t)rowA * (NHEAD * HDIM) + d) =
            make_float2(o[t][0] * iA, o[t][1] * iA);
        *(float2*)(obase + (size_t)(rowA + 8) * (NHEAD * HDIM) + d) =
            make_float2(o[t][2] * iB, o[t][3] * iB);
    }
}

// ---------------- launch ----------------
extern "C" void kernel_launch(void* const* d_in, const int* in_sizes, int n_in,
                              void* d_out, int out_size)
{
    const float* x    = (const float*)d_in[0];
    const float* wq   = (const float*)d_in[1];
    const float* wk   = (const float*)d_in[2];
    const float* wv   = (const float*)d_in[3];
    const float* wo   = (const float*)d_in[4];
    const float* cosb = (const float*)d_in[5];
    const float* sinb = (const float*)d_in[6];
    float* out = (float*)d_out;

    float *pq, *pk, *pv, *pa;
    cudaGetSymbolAddress((void**)&pq, g_q);
    cudaGetSymbolAddress((void**)&pk, g_k);
    cudaGetSymbolAddress((void**)&pv, g_v);
    cudaGetSymbolAddress((void**)&pa, g_attn);
    __nv_bfloat16 *xh, *xl, *wqh, *wql, *wkh, *wkl, *wvh, *wvl, *woh, *wol, *ah, *al;
    cudaGetSymbolAddress((void**)&xh,  g_xh);  cudaGetSymbolAddress((void**)&xl,  g_xl);
    cudaGetSymbolAddress((void**)&wqh, g_wqh); cudaGetSymbolAddress((void**)&wql, g_wql);
    cudaGetSymbolAddress((void**)&wkh, g_wkh); cudaGetSymbolAddress((void**)&wkl, g_wkl);
    cudaGetSymbolAddress((void**)&wvh, g_wvh); cudaGetSymbolAddress((void**)&wvl, g_wvl);
    cudaGetSymbolAddress((void**)&woh, g_woh); cudaGetSymbolAddress((void**)&wol, g_wol);
    cudaGetSymbolAddress((void**)&ah,  g_ah);  cudaGetSymbolAddress((void**)&al,  g_al);
    __half *k16h, *k16l, *v16;
    cudaGetSymbolAddress((void**)&k16h, g_k16h);
    cudaGetSymbolAddress((void**)&k16l, g_k16l);
    cudaGetSymbolAddress((void**)&v16,  g_v16);

    cudaFuncSetAttribute(gemm_mma, cudaFuncAttributeMaxDynamicSharedMemorySize, GSMEM);
    cudaFuncSetAttribute(attn_mma, cudaFuncAttributeMaxDynamicSharedMemorySize, ASMEM);

    dim3 blk(256);

    // hi/lo splits (bf16, for GEMMs)
    split_kernel<<<(MROWS * DIMM / 4 + 255) / 256, blk>>>(x,  xh,  xl,  MROWS * DIMM / 4);
    split_kernel<<<(DIMM * DIMM / 4 + 255) / 256, blk>>>(wq, wqh, wql, DIMM * DIMM / 4);
    split_kernel<<<(KVDIM * DIMM / 4 + 255) / 256, blk>>>(wk, wkh, wkl, KVDIM * DIMM / 4);
    split_kernel<<<(KVDIM * DIMM / 4 + 255) / 256, blk>>>(wv, wvh, wvl, KVDIM * DIMM / 4);
    split_kernel<<<(DIMM * DIMM / 4 + 255) / 256, blk>>>(wo, woh, wol, DIMM * DIMM / 4);

    // projections on tensor cores
    gemm_mma<<<dim3(DIMM / 128, MROWS / 128), blk, GSMEM>>>(xh, xl, wqh, wql, pq, DIMM, DIMM);
    gemm_mma<<<dim3(KVDIM / 128, MROWS / 128), blk, GSMEM>>>(xh, xl, wkh, wkl, pk, KVDIM, DIMM);
    gemm_mma<<<dim3(KVDIM / 128, MROWS / 128), blk, GSMEM>>>(xh, xl, wvh, wvl, pv, KVDIM, DIMM);

    // RoPE
    int qtot = BATCH * NSEQ * NHEAD * 64;
    int ktot = BATCH * NSEQ * NKV * 64;
    rope_kernel<<<(qtot + 255) / 256, blk>>>(pq, cosb, sinb, NHEAD, qtot);
    rope_kernel<<<(ktot + 255) / 256, blk>>>(pk, cosb, sinb, NKV, ktot);

    // K hi/lo fp16 + V fp16
    splitf16_kernel<<<(MROWS * KVDIM / 4 + 255) / 256, blk>>>(pk, k16h, k16l, MROWS * KVDIM / 4);
    cvt16_kernel<<<(MROWS * KVDIM / 4 + 255) / 256, blk>>>(pv, v16, MROWS * KVDIM / 4);

    // attention on tensor cores
    attn_mma<<<dim3(NSEQ / 128, BATCH * NHEAD), blk, ASMEM>>>(pq, k16h, k16l, v16, pa);

    // output projection
    split_kernel<<<(MROWS * DIMM / 4 + 255) / 256, blk>>>(pa, ah, al, MROWS * DIMM / 4);
    gemm_mma<<<dim3(DIMM / 128, MROWS / 128), blk, GSMEM>>>(ah, al, woh, wol, out, DIMM, DIMM);
}

// round 6
// speedup vs baseline: 5.8387x; 1.2883x over previous
#include <cuda_runtime.h>
#include <cuda_bf16.h>
#include <cuda_fp16.h>
#include <cstdint>

typedef unsigned long long ull;

// ---------------- constants ----------------
#define BATCH   2
#define NSEQ    2048
#define DIMM    4096
#define NHEAD   32
#define NKV     8
#define HDIM    128
#define MROWS   (BATCH*NSEQ)            // 4096
#define KVDIM   (NKV*HDIM)              // 1024
#define ATT_SCALE 0.08838834764831845f  // 1/sqrt(128)

// ---------------- scratch (device globals; no allocations allowed) ----------------
__device__ float g_q[MROWS * NHEAD * HDIM];
__device__ float g_k[MROWS * NKV * HDIM];
__device__ float g_v[MROWS * NKV * HDIM];

__device__ __nv_bfloat16 g_xh[MROWS * DIMM],  g_xl[MROWS * DIMM];
__device__ __nv_bfloat16 g_wqh[DIMM * DIMM],  g_wql[DIMM * DIMM];
__device__ __nv_bfloat16 g_wkh[KVDIM * DIMM], g_wkl[KVDIM * DIMM];
__device__ __nv_bfloat16 g_wvh[KVDIM * DIMM], g_wvl[KVDIM * DIMM];

__device__ __half g_k16h[MROWS * KVDIM], g_k16l[MROWS * KVDIM];
__device__ __half g_v16[MROWS * KVDIM];
__device__ __half g_o16[MROWS * DIMM];        // attention output, fp16
__device__ __half g_wo16[DIMM * DIMM];        // wo, fp16

// ---------------- PTX helpers (plain sm_80+ PTX) ----------------
__device__ __forceinline__ uint32_t s2u32(const void* p) {
    uint32_t a;
    asm("{ .reg .u64 t; cvta.to.shared.u64 t, %1; cvt.u32.u64 %0, t; }" : "=r"(a) : "l"(p));
    return a;
}
__device__ __forceinline__ void cp16(uint32_t d, const void* s) {
    asm volatile("cp.async.cg.shared.global [%0], [%1], 16;" :: "r"(d), "l"(s));
}
__device__ __forceinline__ void cp_commit() {
    asm volatile("cp.async.commit_group;" ::: "memory");
}
template <int N>
__device__ __forceinline__ void cp_wait() {
    asm volatile("cp.async.wait_group %0;" :: "n"(N) : "memory");
}
__device__ __forceinline__ void ldsm4(uint32_t& r0, uint32_t& r1, uint32_t& r2,
                                      uint32_t& r3, uint32_t addr) {
    asm volatile("ldmatrix.sync.aligned.m8n8.x4.shared.b16 {%0,%1,%2,%3}, [%4];"
                 : "=r"(r0), "=r"(r1), "=r"(r2), "=r"(r3) : "r"(addr));
}
__device__ __forceinline__ void ldsm4t(uint32_t& r0, uint32_t& r1, uint32_t& r2,
                                       uint32_t& r3, uint32_t addr) {
    asm volatile("ldmatrix.sync.aligned.m8n8.x4.trans.shared.b16 {%0,%1,%2,%3}, [%4];"
                 : "=r"(r0), "=r"(r1), "=r"(r2), "=r"(r3) : "r"(addr));
}
__device__ __forceinline__ void mma16816(float* c, const uint32_t* a, uint32_t b0, uint32_t b1) {
    asm volatile(
        "mma.sync.aligned.m16n8k16.row.col.f32.bf16.bf16.f32 "
        "{%0,%1,%2,%3}, {%4,%5,%6,%7}, {%8,%9}, {%0,%1,%2,%3};"
        : "+f"(c[0]), "+f"(c[1]), "+f"(c[2]), "+f"(c[3])
        : "r"(a[0]), "r"(a[1]), "r"(a[2]), "r"(a[3]), "r"(b0), "r"(b1));
}
__device__ __forceinline__ void mma16816f(float* c, const uint32_t* a, uint32_t b0, uint32_t b1) {
    asm volatile(
        "mma.sync.aligned.m16n8k16.row.col.f32.f16.f16.f32 "
        "{%0,%1,%2,%3}, {%4,%5,%6,%7}, {%8,%9}, {%0,%1,%2,%3};"
        : "+f"(c[0]), "+f"(c[1]), "+f"(c[2]), "+f"(c[3])
        : "r"(a[0]), "r"(a[1]), "r"(a[2]), "r"(a[3]), "r"(b0), "r"(b1));
}
__device__ __forceinline__ uint32_t packh2(float x, float y) {
    __half2 h = __floats2half2_rn(x, y);
    return *(uint32_t*)&h;
}

// ---------------- hi/lo split: fp32 -> bf16 pair ----------------
__global__ __launch_bounds__(256) void split_kernel(
    const float* __restrict__ src, __nv_bfloat16* __restrict__ hi,
    __nv_bfloat16* __restrict__ lo, int n4)
{
    int i = blockIdx.x * blockDim.x + threadIdx.x;
    if (i >= n4) return;
    float4 v = ((const float4*)src)[i];
    __nv_bfloat16 h0 = __float2bfloat16(v.x);
    __nv_bfloat16 h1 = __float2bfloat16(v.y);
    __nv_bfloat16 h2 = __float2bfloat16(v.z);
    __nv_bfloat16 h3 = __float2bfloat16(v.w);
    __nv_bfloat16 l0 = __float2bfloat16(v.x - __bfloat162float(h0));
    __nv_bfloat16 l1 = __float2bfloat16(v.y - __bfloat162float(h1));
    __nv_bfloat16 l2 = __float2bfloat16(v.z - __bfloat162float(h2));
    __nv_bfloat16 l3 = __float2bfloat16(v.w - __bfloat162float(h3));
    ((__nv_bfloat162*)hi)[2 * i]     = __halves2bfloat162(h0, h1);
    ((__nv_bfloat162*)hi)[2 * i + 1] = __halves2bfloat162(h2, h3);
    ((__nv_bfloat162*)lo)[2 * i]     = __halves2bfloat162(l0, l1);
    ((__nv_bfloat162*)lo)[2 * i + 1] = __halves2bfloat162(l2, l3);
}

// ---------------- hi/lo split: fp32 -> fp16 pair ----------------
__global__ __launch_bounds__(256) void splitf16_kernel(
    const float* __restrict__ src, __half* __restrict__ hi,
    __half* __restrict__ lo, int n4)
{
    int i = blockIdx.x * blockDim.x + threadIdx.x;
    if (i >= n4) return;
    float4 v = ((const float4*)src)[i];
    __half h0 = __float2half_rn(v.x), h1 = __float2half_rn(v.y);
    __half h2 = __float2half_rn(v.z), h3 = __float2half_rn(v.w);
    __half l0 = __float2half_rn(v.x - __half2float(h0));
    __half l1 = __float2half_rn(v.y - __half2float(h1));
    __half l2 = __float2half_rn(v.z - __half2float(h2));
    __half l3 = __float2half_rn(v.w - __half2float(h3));
    ((__half2*)hi)[2 * i]     = __halves2half2(h0, h1);
    ((__half2*)hi)[2 * i + 1] = __halves2half2(h2, h3);
    ((__half2*)lo)[2 * i]     = __halves2half2(l0, l1);
    ((__half2*)lo)[2 * i + 1] = __halves2half2(l2, l3);
}

// ---------------- fp32 -> fp16 convert ----------------
__global__ __launch_bounds__(256) void cvt16_kernel(
    const float* __restrict__ src, __half* __restrict__ dst, int n4)
{
    int i = blockIdx.x * blockDim.x + threadIdx.x;
    if (i >= n4) return;
    float4 v = ((const float4*)src)[i];
    ((__half2*)dst)[2 * i]     = __floats2half2_rn(v.x, v.y);
    ((__half2*)dst)[2 * i + 1] = __floats2half2_rn(v.z, v.w);
}

// ---------------- mma.sync split-bf16 3-pass NT GEMM ----------------
#define TILEBYTES (128 * 80)
#define STAGEB    (4 * TILEBYTES)
#define GSMEM     (3 * STAGEB)
__global__ __launch_bounds__(256) void gemm_mma(
    const __nv_bfloat16* __restrict__ Ah, const __nv_bfloat16* __restrict__ Al,
    const __nv_bfloat16* __restrict__ Bh, const __nv_bfloat16* __restrict__ Bl,
    float* __restrict__ C, int N, int K)
{
    extern __shared__ char smraw[];
    const uint32_t sbase = s2u32(smraw);

    const int tid  = threadIdx.x;
    const int wid  = tid >> 5;
    const int lane = tid & 31;
    const int bm = blockIdx.y << 7, bn = blockIdx.x << 7;
    const int wm = (wid & 3) * 32;
    const int wn = (wid >> 2) * 64;
    const int NCH = K >> 5;

    float acc[2][8][4];
#pragma unroll
    for (int i = 0; i < 2; i++)
#pragma unroll
        for (int j = 0; j < 8; j++)
#pragma unroll
            for (int t = 0; t < 4; t++) acc[i][j][t] = 0.0f;

    const __nv_bfloat16* tsrc[4] = {Ah, Al, Bh, Bl};

    auto load_stage = [&](int ch, int st) {
        const int k0 = ch << 5;
        const uint32_t stb = sbase + st * STAGEB;
#pragma unroll
        for (int i = 0; i < 8; i++) {
            int f = i * 256 + tid;
            int tile = f >> 9;
            int c = f & 511;
            int row = c >> 2, c4 = c & 3;
            const __nv_bfloat16* g = tsrc[tile];
            int rb = (tile < 2) ? bm : bn;
            cp16(stb + tile * TILEBYTES + row * 80 + c4 * 16,
                 g + (size_t)(rb + row) * K + k0 + c4 * 8);
        }
    };

    uint32_t offA[2], offB[4];
#pragma unroll
    for (int mt = 0; mt < 2; mt++)
        offA[mt] = (uint32_t)((wm + mt * 16 + (lane & 15)) * 80 + (lane >> 4) * 16);
#pragma unroll
    for (int nb = 0; nb < 4; nb++)
        offB[nb] = (uint32_t)((wn + nb * 16 + (lane & 15)) * 80 + (lane >> 4) * 16);

    load_stage(0, 0); cp_commit();
    load_stage(1, 1); cp_commit();

    for (int it = 0; it < NCH; ++it) {
        const int st = it % 3;
        if (it + 2 < NCH) { load_stage(it + 2, (it + 2) % 3); cp_commit(); }
        if (it + 2 < NCH)      cp_wait<2>();
        else if (it + 1 < NCH) cp_wait<1>();
        else                   cp_wait<0>();
        __syncthreads();

        const uint32_t bAh = sbase + st * STAGEB;
        const uint32_t bAl = bAh + TILEBYTES;
        const uint32_t bBh = bAh + 2 * TILEBYTES;
        const uint32_t bBl = bAh + 3 * TILEBYTES;

#pragma unroll
        for (int kk = 0; kk < 2; kk++) {
            const uint32_t ks = kk * 32;
            uint32_t ah[2][4], al[2][4], bh[4][4], bl[4][4];
#pragma unroll
            for (int mt = 0; mt < 2; mt++) {
                ldsm4(ah[mt][0], ah[mt][1], ah[mt][2], ah[mt][3], bAh + offA[mt] + ks);
                ldsm4(al[mt][0], al[mt][1], al[mt][2], al[mt][3], bAl + offA[mt] + ks);
            }
#pragma unroll
            for (int nb = 0; nb < 4; nb++) {
                ldsm4(bh[nb][0], bh[nb][1], bh[nb][2], bh[nb][3], bBh + offB[nb] + ks);
                ldsm4(bl[nb][0], bl[nb][1], bl[nb][2], bl[nb][3], bBl + offB[nb] + ks);
            }
#pragma unroll
            for (int mt = 0; mt < 2; mt++)
#pragma unroll
                for (int nb = 0; nb < 4; nb++)
#pragma unroll
                    for (int hf = 0; hf < 2; hf++) {
                        float* c = acc[mt][nb * 2 + hf];
                        mma16816(c, ah[mt], bh[nb][hf], bh[nb][hf + 2]);
                        mma16816(c, ah[mt], bl[nb][hf], bl[nb][hf + 2]);
                        mma16816(c, al[mt], bh[nb][hf], bh[nb][hf + 2]);
                    }
        }
        __syncthreads();
    }

#pragma unroll
    for (int mt = 0; mt < 2; mt++) {
        int r0 = bm + wm + mt * 16 + (lane >> 2);
#pragma unroll
        for (int nt = 0; nt < 8; nt++) {
            int c0 = bn + wn + nt * 8 + (lane & 3) * 2;
            float* p = acc[mt][nt];
            *(float2*)&C[(size_t)r0 * N + c0]       = make_float2(p[0], p[1]);
            *(float2*)&C[(size_t)(r0 + 8) * N + c0] = make_float2(p[2], p[3]);
        }
    }
}

// ---------------- single-pass fp16 NT GEMM ----------------
// C[M,N] = A[M,K] * B[N,K]^T, fp16 in, fp32 accum, OUT = __half or float.
#define T1P    (128 * 80)          // one 128x32-fp16 tile (80B pitch)
#define S1P    (2 * T1P)           // A,B tiles
#define G1SMEM (3 * S1P)           // 61440
template <typename OUT>
__global__ __launch_bounds__(256) void gemm1p(
    const __half* __restrict__ A, const __half* __restrict__ B,
    OUT* __restrict__ C, int N, int K)
{
    extern __shared__ char smraw[];
    const uint32_t sbase = s2u32(smraw);

    const int tid  = threadIdx.x;
    const int wid  = tid >> 5;
    const int lane = tid & 31;
    const int bm = blockIdx.y << 7, bn = blockIdx.x << 7;
    const int wm = (wid & 3) * 32;
    const int wn = (wid >> 2) * 64;
    const int NCH = K >> 5;

    float acc[2][8][4];
#pragma unroll
    for (int i = 0; i < 2; i++)
#pragma unroll
        for (int j = 0; j < 8; j++)
#pragma unroll
            for (int t = 0; t < 4; t++) acc[i][j][t] = 0.0f;

    auto load_stage = [&](int ch, int st) {
        const int k0 = ch << 5;
        const uint32_t stb = sbase + st * S1P;
#pragma unroll
        for (int i = 0; i < 4; i++) {
            int f = i * 256 + tid;          // 0..1023 16B chunks
            int tile = f >> 9;
            int c = f & 511;
            int row = c >> 2, c4 = c & 3;
            const __half* g = tile ? B : A;
            int rb = tile ? bn : bm;
            cp16(stb + tile * T1P + row * 80 + c4 * 16,
                 g + (size_t)(rb + row) * K + k0 + c4 * 8);
        }
    };

    uint32_t offA[2], offB[4];
#pragma unroll
    for (int mt = 0; mt < 2; mt++)
        offA[mt] = (uint32_t)((wm + mt * 16 + (lane & 15)) * 80 + (lane >> 4) * 16);
#pragma unroll
    for (int nb = 0; nb < 4; nb++)
        offB[nb] = (uint32_t)((wn + nb * 16 + (lane & 15)) * 80 + (lane >> 4) * 16);

    load_stage(0, 0); cp_commit();
    load_stage(1, 1); cp_commit();

    for (int it = 0; it < NCH; ++it) {
        const int st = it % 3;
        if (it + 2 < NCH) { load_stage(it + 2, (it + 2) % 3); cp_commit(); }
        if (it + 2 < NCH)      cp_wait<2>();
        else if (it + 1 < NCH) cp_wait<1>();
        else                   cp_wait<0>();
        __syncthreads();

        const uint32_t bA = sbase + st * S1P;
        const uint32_t bB = bA + T1P;

#pragma unroll
        for (int kk = 0; kk < 2; kk++) {
            const uint32_t ks = kk * 32;
            uint32_t a[2][4], bfr[4][4];
#pragma unroll
            for (int mt = 0; mt < 2; mt++)
                ldsm4(a[mt][0], a[mt][1], a[mt][2], a[mt][3], bA + offA[mt] + ks);
#pragma unroll
            for (int nb = 0; nb < 4; nb++)
                ldsm4(bfr[nb][0], bfr[nb][1], bfr[nb][2], bfr[nb][3], bB + offB[nb] + ks);
#pragma unroll
            for (int mt = 0; mt < 2; mt++)
#pragma unroll
                for (int nb = 0; nb < 4; nb++)
#pragma unroll
                    for (int hf = 0; hf < 2; hf++)
                        mma16816f(acc[mt][nb * 2 + hf], a[mt],
                                  bfr[nb][hf], bfr[nb][hf + 2]);
        }
        __syncthreads();
    }

#pragma unroll
    for (int mt = 0; mt < 2; mt++) {
        int r0 = bm + wm + mt * 16 + (lane >> 2);
#pragma unroll
        for (int nt = 0; nt < 8; nt++) {
            int c0 = bn + wn + nt * 8 + (lane & 3) * 2;
            float* p = acc[mt][nt];
            if constexpr (sizeof(OUT) == 2) {
                *(__half2*)&C[(size_t)r0 * N + c0] = __floats2half2_rn(p[0], p[1]);
                *(__half2*)&C[(size_t)(r0 + 8) * N + c0] = __floats2half2_rn(p[2], p[3]);
            } else {
                *(float2*)&C[(size_t)r0 * N + c0]       = make_float2(p[0], p[1]);
                *(float2*)&C[(size_t)(r0 + 8) * N + c0] = make_float2(p[2], p[3]);
            }
        }
    }
}

// ---------------- RoPE ----------------
__global__ __launch_bounds__(256) void rope_kernel(
    float* __restrict__ t, const float* __restrict__ cosb,
    const float* __restrict__ sinb, int H, int total)
{
    int idx = blockIdx.x * blockDim.x + threadIdx.x;
    if (idx >= total) return;
    int j   = idx & 63;
    int bnh = idx >> 6;
    int n   = (bnh / H) & (NSEQ - 1);
    float c = cosb[n * 64 + j];
    float s = sinb[n * 64 + j];
    float* p = t + ((size_t)bnh << 7) + 2 * j;
    float x0 = p[0], x1 = p[1];
    p[0] = x0 * c - x1 * s;
    p[1] = x0 * s + x1 * c;
}

// ---------------- flash attention via mma.sync ----------------
// 128 q-rows/CTA, 8 warps x 16 rows, 64-key tiles double buffered.
// S: fp16 hi/lo 3-pass; PV: fp16 single pass. fp32 softmax/accum.
// Output written directly as fp16 (feeds 1-pass O projection).
#define APITCH  272
#define QS_BYTES (128 * APITCH)
#define KVTILE   (64 * APITCH)
#define STG      (3 * KVTILE)
#define ASMEM    (2 * QS_BYTES + 2 * STG)
__global__ __launch_bounds__(256) void attn_mma(
    const float* __restrict__ Q, const __half* __restrict__ Kh,
    const __half* __restrict__ Kl, const __half* __restrict__ V,
    __half* __restrict__ O16)
{
    extern __shared__ char smraw[];
    const uint32_t sb = s2u32(smraw);
    const uint32_t qh_s = sb;
    const uint32_t ql_s = sb + QS_BYTES;
    const uint32_t kvb  = sb + 2 * QS_BYTES;

    const int tid = threadIdx.x;
    const int wid = tid >> 5, lane = tid & 31;
    const int qt = blockIdx.x;
    const int bh = blockIdx.y;
    const int b = bh >> 5, h = bh & 31;
    const int kvh = h >> 2;

    {
        const float* qbase = Q + ((size_t)(b * NSEQ + qt * 128) * NHEAD + h) * HDIM;
#pragma unroll
        for (int i = 0; i < 32; i++) {
            int idx = tid + i * 256;
            int r = idx >> 6, c2 = idx & 63;
            float2 v = *(const float2*)(qbase + (size_t)r * (NHEAD * HDIM) + c2 * 2);
            v.x *= ATT_SCALE; v.y *= ATT_SCALE;
            __half hx = __float2half_rn(v.x), hy = __float2half_rn(v.y);
            __half lx = __float2half_rn(v.x - __half2float(hx));
            __half ly = __float2half_rn(v.y - __half2float(hy));
            uint32_t off = (uint32_t)(r * APITCH + c2 * 4);
            *(__half2*)(smraw + off)            = __halves2half2(hx, hy);
            *(__half2*)(smraw + QS_BYTES + off) = __halves2half2(lx, ly);
        }
    }

    const size_t kvstride = (size_t)NKV * HDIM;
    auto load_kv = [&](int kt, int st) {
        const uint32_t stb = kvb + st * STG;
        const size_t row0 = ((size_t)(b * NSEQ + kt * 64) * NKV + kvh) * HDIM;
#pragma unroll
        for (int i = 0; i < 12; i++) {
            int f = i * 256 + tid;
            int tile = f >> 10;
            int c = f & 1023;
            int row = c >> 4, ch = c & 15;
            const __half* src = (tile == 0 ? Kh : (tile == 1 ? Kl : V))
                                + row0 + (size_t)row * kvstride + ch * 8;
            cp16(stb + tile * KVTILE + row * APITCH + ch * 16, src);
        }
    };

    float o[16][4];
#pragma unroll
    for (int t = 0; t < 16; t++)
#pragma unroll
        for (int r = 0; r < 4; r++) o[t][r] = 0.0f;
    float m0 = -1e30f, m1 = -1e30f, l0 = 0.0f, l1 = 0.0f;

    const int NIT = 2 * qt + 2;
    load_kv(0, 0); cp_commit();

    const int rowA = qt * 128 + wid * 16 + (lane >> 2);
    const uint32_t aoff = (uint32_t)((wid * 16 + (lane & 15)) * APITCH + (lane >> 4) * 16);

    for (int it = 0; it < NIT; it++) {
        const int st = it & 1;
        if (it + 1 < NIT) { load_kv(it + 1, (it + 1) & 1); cp_commit(); cp_wait<1>(); }
        else              { cp_wait<0>(); }
        __syncthreads();

        const uint32_t kh_t = kvb + st * STG;
        const uint32_t kl_t = kh_t + KVTILE;
        const uint32_t v_t  = kh_t + 2 * KVTILE;

        float s[8][4];
#pragma unroll
        for (int t = 0; t < 8; t++)
#pragma unroll
            for (int r = 0; r < 4; r++) s[t][r] = 0.0f;

#pragma unroll
        for (int kki = 0; kki < 8; kki++) {
            uint32_t ah[4], al[4];
            ldsm4(ah[0], ah[1], ah[2], ah[3], qh_s + aoff + kki * 32);
            ldsm4(al[0], al[1], al[2], al[3], ql_s + aoff + kki * 32);
#pragma unroll
            for (int g = 0; g < 4; g++) {
                uint32_t boff = (uint32_t)((16 * g + (lane & 15)) * APITCH
                                           + (kki * 2 + (lane >> 4)) * 16);
                uint32_t b0, b1, b2, b3, c0, c1, c2, c3;
                ldsm4(b0, b1, b2, b3, kh_t + boff);
                ldsm4(c0, c1, c2, c3, kl_t + boff);
                mma16816f(s[2 * g],     ah, b0, b2);
                mma16816f(s[2 * g],     ah, c0, c2);
                mma16816f(s[2 * g],     al, b0, b2);
                mma16816f(s[2 * g + 1], ah, b1, b3);
                mma16816f(s[2 * g + 1], ah, c1, c3);
                mma16816f(s[2 * g + 1], al, b1, b3);
            }
        }

        if (it >= 2 * qt) {
            const int kbase = it * 64 + (lane & 3) * 2;
#pragma unroll
            for (int t = 0; t < 8; t++) {
                int k0 = kbase + t * 8;
                if (k0     > rowA)     s[t][0] = -1e30f;
                if (k0 + 1 > rowA)     s[t][1] = -1e30f;
                if (k0     > rowA + 8) s[t][2] = -1e30f;
                if (k0 + 1 > rowA + 8) s[t][3] = -1e30f;
            }
        }

        float mxA = m0, mxB = m1;
#pragma unroll
        for (int t = 0; t < 8; t++) {
            mxA = fmaxf(mxA, fmaxf(s[t][0], s[t][1]));
            mxB = fmaxf(mxB, fmaxf(s[t][2], s[t][3]));
        }
        mxA = fmaxf(mxA, __shfl_xor_sync(0xFFFFFFFFu, mxA, 1));
        mxA = fmaxf(mxA, __shfl_xor_sync(0xFFFFFFFFu, mxA, 2));
        mxB = fmaxf(mxB, __shfl_xor_sync(0xFFFFFFFFu, mxB, 1));
        mxB = fmaxf(mxB, __shfl_xor_sync(0xFFFFFFFFu, mxB, 2));

        float aA = __expf(m0 - mxA), aB = __expf(m1 - mxB);
        float sA = 0.0f, sB = 0.0f;
#pragma unroll
        for (int t = 0; t < 8; t++) {
            s[t][0] = __expf(s[t][0] - mxA);
            s[t][1] = __expf(s[t][1] - mxA);
            s[t][2] = __expf(s[t][2] - mxB);
            s[t][3] = __expf(s[t][3] - mxB);
            sA += s[t][0] + s[t][1];
            sB += s[t][2] + s[t][3];
        }
        sA += __shfl_xor_sync(0xFFFFFFFFu, sA, 1);
        sA += __shfl_xor_sync(0xFFFFFFFFu, sA, 2);
        sB += __shfl_xor_sync(0xFFFFFFFFu, sB, 1);
        sB += __shfl_xor_sync(0xFFFFFFFFu, sB, 2);
        l0 = l0 * aA + sA;  l1 = l1 * aB + sB;
        m0 = mxA;           m1 = mxB;

#pragma unroll
        for (int t = 0; t < 16; t++) {
            o[t][0] *= aA; o[t][1] *= aA;
            o[t][2] *= aB; o[t][3] *= aB;
        }

        uint32_t ap[4][4];
#pragma unroll
        for (int kk = 0; kk < 4; kk++) {
            ap[kk][0] = packh2(s[2 * kk][0],     s[2 * kk][1]);
            ap[kk][1] = packh2(s[2 * kk][2],     s[2 * kk][3]);
            ap[kk][2] = packh2(s[2 * kk + 1][0], s[2 * kk + 1][1]);
            ap[kk][3] = packh2(s[2 * kk + 1][2], s[2 * kk + 1][3]);
        }
        const uint32_t vrow = (uint32_t)((((lane >> 3) & 1) * 8 + (lane & 7)) * APITCH
                                         + (lane >> 4) * 16);
#pragma unroll
        for (int kk = 0; kk < 4; kk++) {
#pragma unroll
            for (int g = 0; g < 8; g++) {
                uint32_t v0, v1, v2, v3;
                ldsm4t(v0, v1, v2, v3, v_t + vrow + (uint32_t)(16 * kk * APITCH + g * 32));
                mma16816f(o[2 * g],     ap[kk], v0, v1);
                mma16816f(o[2 * g + 1], ap[kk], v2, v3);
            }
        }
        __syncthreads();
    }

    // ---- final normalize + store fp16 ----
    const float iA = 1.0f / l0, iB = 1.0f / l1;
    __half* obase = O16 + ((size_t)(b * NSEQ) * NHEAD + h) * HDIM;
#pragma unroll
    for (int t = 0; t < 16; t++) {
        int d = t * 8 + (lane & 3) * 2;
        *(__half2*)(obase + (size_t)rowA * (NHEAD * HDIM) + d) =
            __floats2half2_rn(o[t][0] * iA, o[t][1] * iA);
        *(__half2*)(obase + (size_t)(rowA + 8) * (NHEAD * HDIM) + d) =
            __floats2half2_rn(o[t][2] * iB, o[t][3] * iB);
    }
}

// ---------------- launch ----------------
extern "C" void kernel_launch(void* const* d_in, const int* in_sizes, int n_in,
                              void* d_out, int out_size)
{
    const float* x    = (const float*)d_in[0];
    const float* wq   = (const float*)d_in[1];
    const float* wk   = (const float*)d_in[2];
    const float* wv   = (const float*)d_in[3];
    const float* wo   = (const float*)d_in[4];
    const float* cosb = (const float*)d_in[5];
    const float* sinb = (const float*)d_in[6];
    float* out = (float*)d_out;

    float *pq, *pk, *pv;
    cudaGetSymbolAddress((void**)&pq, g_q);
    cudaGetSymbolAddress((void**)&pk, g_k);
    cudaGetSymbolAddress((void**)&pv, g_v);
    __nv_bfloat16 *xh, *xl, *wqh, *wql, *wkh, *wkl, *wvh, *wvl;
    cudaGetSymbolAddress((void**)&xh,  g_xh);  cudaGetSymbolAddress((void**)&xl,  g_xl);
    cudaGetSymbolAddress((void**)&wqh, g_wqh); cudaGetSymbolAddress((void**)&wql, g_wql);
    cudaGetSymbolAddress((void**)&wkh, g_wkh); cudaGetSymbolAddress((void**)&wkl, g_wkl);
    cudaGetSymbolAddress((void**)&wvh, g_wvh); cudaGetSymbolAddress((void**)&wvl, g_wvl);
    __half *k16h, *k16l, *v16, *o16, *wo16;
    cudaGetSymbolAddress((void**)&k16h, g_k16h);
    cudaGetSymbolAddress((void**)&k16l, g_k16l);
    cudaGetSymbolAddress((void**)&v16,  g_v16);
    cudaGetSymbolAddress((void**)&o16,  g_o16);
    cudaGetSymbolAddress((void**)&wo16, g_wo16);

    cudaFuncSetAttribute(gemm_mma, cudaFuncAttributeMaxDynamicSharedMemorySize, GSMEM);
    cudaFuncSetAttribute(gemm1p<float>, cudaFuncAttributeMaxDynamicSharedMemorySize, G1SMEM);
    cudaFuncSetAttribute(attn_mma, cudaFuncAttributeMaxDynamicSharedMemorySize, ASMEM);

    dim3 blk(256);

    // hi/lo splits (bf16) for Q/K/V projections; wo -> fp16 single
    split_kernel<<<(MROWS * DIMM / 4 + 255) / 256, blk>>>(x,  xh,  xl,  MROWS * DIMM / 4);
    split_kernel<<<(DIMM * DIMM / 4 + 255) / 256, blk>>>(wq, wqh, wql, DIMM * DIMM / 4);
    split_kernel<<<(KVDIM * DIMM / 4 + 255) / 256, blk>>>(wk, wkh, wkl, KVDIM * DIMM / 4);
    split_kernel<<<(KVDIM * DIMM / 4 + 255) / 256, blk>>>(wv, wvh, wvl, KVDIM * DIMM / 4);
    cvt16_kernel<<<(DIMM * DIMM / 4 + 255) / 256, blk>>>(wo, wo16, DIMM * DIMM / 4);

    // projections (3-pass bf16)
    gemm_mma<<<dim3(DIMM / 128, MROWS / 128), blk, GSMEM>>>(xh, xl, wqh, wql, pq, DIMM, DIMM);
    gemm_mma<<<dim3(KVDIM / 128, MROWS / 128), blk, GSMEM>>>(xh, xl, wkh, wkl, pk, KVDIM, DIMM);
    gemm_mma<<<dim3(KVDIM / 128, MROWS / 128), blk, GSMEM>>>(xh, xl, wvh, wvl, pv, KVDIM, DIMM);

    // RoPE
    int qtot = BATCH * NSEQ * NHEAD * 64;
    int ktot = BATCH * NSEQ * NKV * 64;
    rope_kernel<<<(qtot + 255) / 256, blk>>>(pq, cosb, sinb, NHEAD, qtot);
    rope_kernel<<<(ktot + 255) / 256, blk>>>(pk, cosb, sinb, NKV, ktot);

    // K hi/lo fp16 + V fp16
    splitf16_kernel<<<(MROWS * KVDIM / 4 + 255) / 256, blk>>>(pk, k16h, k16l, MROWS * KVDIM / 4);
    cvt16_kernel<<<(MROWS * KVDIM / 4 + 255) / 256, blk>>>(pv, v16, MROWS * KVDIM / 4);

    // attention (writes fp16 o16)
    attn_mma<<<dim3(NSEQ / 128, BATCH * NHEAD), blk, ASMEM>>>(pq, k16h, k16l, v16, o16);

    // output projection: single-pass fp16
    gemm1p<float><<<dim3(DIMM / 128, MROWS / 128), blk, G1SMEM>>>(o16, wo16, out, DIMM, DIMM);
}

// round 7
// speedup vs baseline: 7.0797x; 1.2125x over previous
#include <cuda_runtime.h>
#include <cuda_fp16.h>
#include <cstdint>

// ---------------- constants ----------------
#define BATCH   2
#define NSEQ    2048
#define DIMM    4096
#define NHEAD   32
#define NKV     8
#define HDIM    128
#define MROWS   (BATCH*NSEQ)            // 4096
#define KVDIM   (NKV*HDIM)              // 1024
#define ATT_SCALE 0.08838834764831845f  // 1/sqrt(128)

// ---------------- scratch (device globals; no allocations allowed) ----------------
__device__ float g_q[MROWS * NHEAD * HDIM];
__device__ float g_k[MROWS * NKV * HDIM];
__device__ float g_v[MROWS * NKV * HDIM];

__device__ __half g_x16h[MROWS * DIMM],  g_x16l[MROWS * DIMM];
__device__ __half g_wq16[DIMM * DIMM];
__device__ __half g_wk16h[KVDIM * DIMM], g_wk16l[KVDIM * DIMM];
__device__ __half g_wv16h[KVDIM * DIMM], g_wv16l[KVDIM * DIMM];
__device__ __half g_wo16[DIMM * DIMM];

__device__ __half g_k16h[MROWS * KVDIM], g_k16l[MROWS * KVDIM];
__device__ __half g_v16[MROWS * KVDIM];
__device__ __half g_o16[MROWS * DIMM];

// ---------------- PTX helpers (plain sm_80+ PTX) ----------------
__device__ __forceinline__ uint32_t s2u32(const void* p) {
    uint32_t a;
    asm("{ .reg .u64 t; cvta.to.shared.u64 t, %1; cvt.u32.u64 %0, t; }" : "=r"(a) : "l"(p));
    return a;
}
__device__ __forceinline__ void cp16(uint32_t d, const void* s) {
    asm volatile("cp.async.cg.shared.global [%0], [%1], 16;" :: "r"(d), "l"(s));
}
__device__ __forceinline__ void cp_commit() {
    asm volatile("cp.async.commit_group;" ::: "memory");
}
template <int N>
__device__ __forceinline__ void cp_wait() {
    asm volatile("cp.async.wait_group %0;" :: "n"(N) : "memory");
}
__device__ __forceinline__ void ldsm4(uint32_t& r0, uint32_t& r1, uint32_t& r2,
                                      uint32_t& r3, uint32_t addr) {
    asm volatile("ldmatrix.sync.aligned.m8n8.x4.shared.b16 {%0,%1,%2,%3}, [%4];"
                 : "=r"(r0), "=r"(r1), "=r"(r2), "=r"(r3) : "r"(addr));
}
__device__ __forceinline__ void ldsm4t(uint32_t& r0, uint32_t& r1, uint32_t& r2,
                                       uint32_t& r3, uint32_t addr) {
    asm volatile("ldmatrix.sync.aligned.m8n8.x4.trans.shared.b16 {%0,%1,%2,%3}, [%4];"
                 : "=r"(r0), "=r"(r1), "=r"(r2), "=r"(r3) : "r"(addr));
}
__device__ __forceinline__ void mma16816f(float* c, const uint32_t* a, uint32_t b0, uint32_t b1) {
    asm volatile(
        "mma.sync.aligned.m16n8k16.row.col.f32.f16.f16.f32 "
        "{%0,%1,%2,%3}, {%4,%5,%6,%7}, {%8,%9}, {%0,%1,%2,%3};"
        : "+f"(c[0]), "+f"(c[1]), "+f"(c[2]), "+f"(c[3])
        : "r"(a[0]), "r"(a[1]), "r"(a[2]), "r"(a[3]), "r"(b0), "r"(b1));
}
__device__ __forceinline__ uint32_t packh2(float x, float y) {
    __half2 h = __floats2half2_rn(x, y);
    return *(uint32_t*)&h;
}

// ---------------- hi/lo split: fp32 -> fp16 pair ----------------
__global__ __launch_bounds__(256) void splitf16_kernel(
    const float* __restrict__ src, __half* __restrict__ hi,
    __half* __restrict__ lo, int n4)
{
    int i = blockIdx.x * blockDim.x + threadIdx.x;
    if (i >= n4) return;
    float4 v = ((const float4*)src)[i];
    __half h0 = __float2half_rn(v.x), h1 = __float2half_rn(v.y);
    __half h2 = __float2half_rn(v.z), h3 = __float2half_rn(v.w);
    __half l0 = __float2half_rn(v.x - __half2float(h0));
    __half l1 = __float2half_rn(v.y - __half2float(h1));
    __half l2 = __float2half_rn(v.z - __half2float(h2));
    __half l3 = __float2half_rn(v.w - __half2float(h3));
    ((__half2*)hi)[2 * i]     = __halves2half2(h0, h1);
    ((__half2*)hi)[2 * i + 1] = __halves2half2(h2, h3);
    ((__half2*)lo)[2 * i]     = __halves2half2(l0, l1);
    ((__half2*)lo)[2 * i + 1] = __halves2half2(l2, l3);
}

// ---------------- fp32 -> fp16 convert ----------------
__global__ __launch_bounds__(256) void cvt16_kernel(
    const float* __restrict__ src, __half* __restrict__ dst, int n4)
{
    int i = blockIdx.x * blockDim.x + threadIdx.x;
    if (i >= n4) return;
    float4 v = ((const float4*)src)[i];
    ((__half2*)dst)[2 * i]     = __floats2half2_rn(v.x, v.y);
    ((__half2*)dst)[2 * i + 1] = __floats2half2_rn(v.z, v.w);
}

// =====================================================================
// GEMM family: C[M,N] = A[M,K] * B[N,K]^T, fp16 inputs, fp32 accum.
// CTA 128x128, BK=32, 256 thr (8 warps, warp tile 32x64).
// 3-stage cp.async, single __syncthreads per iteration:
//   wait(load it) -> sync -> issue load(it+2) -> compute(it)
// =====================================================================
#define TILE80 (128 * 80)

// ---------------- 3-pass (A,B both hi/lo split): K/V projections ----------------
#define G3STAGE (4 * TILE80)
#define G3SMEM  (3 * G3STAGE)
__global__ __launch_bounds__(256) void gemm3p(
    const __half* __restrict__ Ah, const __half* __restrict__ Al,
    const __half* __restrict__ Bh, const __half* __restrict__ Bl,
    float* __restrict__ C, int N, int K)
{
    extern __shared__ char smraw[];
    const uint32_t sbase = s2u32(smraw);
    const int tid  = threadIdx.x;
    const int wid  = tid >> 5;
    const int lane = tid & 31;
    const int bm = blockIdx.y << 7, bn = blockIdx.x << 7;
    const int wm = (wid & 3) * 32;
    const int wn = (wid >> 2) * 64;
    const int NCH = K >> 5;

    float acc[2][8][4];
#pragma unroll
    for (int i = 0; i < 2; i++)
#pragma unroll
        for (int j = 0; j < 8; j++)
#pragma unroll
            for (int t = 0; t < 4; t++) acc[i][j][t] = 0.0f;

    const __half* tsrc[4] = {Ah, Al, Bh, Bl};

    auto load_stage = [&](int ch, int st) {
        const int k0 = ch << 5;
        const uint32_t stb = sbase + st * G3STAGE;
#pragma unroll
        for (int i = 0; i < 8; i++) {
            int f = i * 256 + tid;
            int tile = f >> 9;
            int c = f & 511;
            int row = c >> 2, c4 = c & 3;
            const __half* g = tsrc[tile];
            int rb = (tile < 2) ? bm : bn;
            cp16(stb + tile * TILE80 + row * 80 + c4 * 16,
                 g + (size_t)(rb + row) * K + k0 + c4 * 8);
        }
    };

    uint32_t offA[2], offB[4];
#pragma unroll
    for (int mt = 0; mt < 2; mt++)
        offA[mt] = (uint32_t)((wm + mt * 16 + (lane & 15)) * 80 + (lane >> 4) * 16);
#pragma unroll
    for (int nb = 0; nb < 4; nb++)
        offB[nb] = (uint32_t)((wn + nb * 16 + (lane & 15)) * 80 + (lane >> 4) * 16);

    load_stage(0, 0); cp_commit();
    load_stage(1, 1); cp_commit();

    for (int it = 0; it < NCH; ++it) {
        if (it + 1 < NCH) cp_wait<1>(); else cp_wait<0>();
        __syncthreads();
        if (it + 2 < NCH) { load_stage(it + 2, (it + 2) % 3); cp_commit(); }

        const uint32_t bAh = sbase + (it % 3) * G3STAGE;
        const uint32_t bAl = bAh + TILE80;
        const uint32_t bBh = bAh + 2 * TILE80;
        const uint32_t bBl = bAh + 3 * TILE80;

#pragma unroll
        for (int kk = 0; kk < 2; kk++) {
            const uint32_t ks = kk * 32;
            uint32_t ah[2][4], al[2][4], bh[4][4], bl[4][4];
#pragma unroll
            for (int mt = 0; mt < 2; mt++) {
                ldsm4(ah[mt][0], ah[mt][1], ah[mt][2], ah[mt][3], bAh + offA[mt] + ks);
                ldsm4(al[mt][0], al[mt][1], al[mt][2], al[mt][3], bAl + offA[mt] + ks);
            }
#pragma unroll
            for (int nb = 0; nb < 4; nb++) {
                ldsm4(bh[nb][0], bh[nb][1], bh[nb][2], bh[nb][3], bBh + offB[nb] + ks);
                ldsm4(bl[nb][0], bl[nb][1], bl[nb][2], bl[nb][3], bBl + offB[nb] + ks);
            }
#pragma unroll
            for (int mt = 0; mt < 2; mt++)
#pragma unroll
                for (int nb = 0; nb < 4; nb++)
#pragma unroll
                    for (int hf = 0; hf < 2; hf++) {
                        float* c = acc[mt][nb * 2 + hf];
                        mma16816f(c, ah[mt], bh[nb][hf], bh[nb][hf + 2]);
                        mma16816f(c, ah[mt], bl[nb][hf], bl[nb][hf + 2]);
                        mma16816f(c, al[mt], bh[nb][hf], bh[nb][hf + 2]);
                    }
        }
    }

#pragma unroll
    for (int mt = 0; mt < 2; mt++) {
        int r0 = bm + wm + mt * 16 + (lane >> 2);
#pragma unroll
        for (int nt = 0; nt < 8; nt++) {
            int c0 = bn + wn + nt * 8 + (lane & 3) * 2;
            float* p = acc[mt][nt];
            *(float2*)&C[(size_t)r0 * N + c0]       = make_float2(p[0], p[1]);
            *(float2*)&C[(size_t)(r0 + 8) * N + c0] = make_float2(p[2], p[3]);
        }
    }
}

// ---------------- 2-pass (A hi/lo split, B single): Q projection ----------------
#define G2STAGE (3 * TILE80)
#define G2SMEM  (3 * G2STAGE)
__global__ __launch_bounds__(256) void gemm2p(
    const __half* __restrict__ Ah, const __half* __restrict__ Al,
    const __half* __restrict__ B, float* __restrict__ C, int N, int K)
{
    extern __shared__ char smraw[];
    const uint32_t sbase = s2u32(smraw);
    const int tid  = threadIdx.x;
    const int wid  = tid >> 5;
    const int lane = tid & 31;
    const int bm = blockIdx.y << 7, bn = blockIdx.x << 7;
    const int wm = (wid & 3) * 32;
    const int wn = (wid >> 2) * 64;
    const int NCH = K >> 5;

    float acc[2][8][4];
#pragma unroll
    for (int i = 0; i < 2; i++)
#pragma unroll
        for (int j = 0; j < 8; j++)
#pragma unroll
            for (int t = 0; t < 4; t++) acc[i][j][t] = 0.0f;

    const __half* tsrc[3] = {Ah, Al, B};

    auto load_stage = [&](int ch, int st) {
        const int k0 = ch << 5;
        const uint32_t stb = sbase + st * G2STAGE;
#pragma unroll
        for (int i = 0; i < 6; i++) {
            int f = i * 256 + tid;           // 0..1535
            int tile = f >> 9;
            int c = f & 511;
            int row = c >> 2, c4 = c & 3;
            const __half* g = tsrc[tile];
            int rb = (tile < 2) ? bm : bn;
            cp16(stb + tile * TILE80 + row * 80 + c4 * 16,
                 g + (size_t)(rb + row) * K + k0 + c4 * 8);
        }
    };

    uint32_t offA[2], offB[4];
#pragma unroll
    for (int mt = 0; mt < 2; mt++)
        offA[mt] = (uint32_t)((wm + mt * 16 + (lane & 15)) * 80 + (lane >> 4) * 16);
#pragma unroll
    for (int nb = 0; nb < 4; nb++)
        offB[nb] = (uint32_t)((wn + nb * 16 + (lane & 15)) * 80 + (lane >> 4) * 16);

    load_stage(0, 0); cp_commit();
    load_stage(1, 1); cp_commit();

    for (int it = 0; it < NCH; ++it) {
        if (it + 1 < NCH) cp_wait<1>(); else cp_wait<0>();
        __syncthreads();
        if (it + 2 < NCH) { load_stage(it + 2, (it + 2) % 3); cp_commit(); }

        const uint32_t bAh = sbase + (it % 3) * G2STAGE;
        const uint32_t bAl = bAh + TILE80;
        const uint32_t bB  = bAh + 2 * TILE80;

#pragma unroll
        for (int kk = 0; kk < 2; kk++) {
            const uint32_t ks = kk * 32;
            uint32_t ah[2][4], al[2][4], bfr[4][4];
#pragma unroll
            for (int mt = 0; mt < 2; mt++) {
                ldsm4(ah[mt][0], ah[mt][1], ah[mt][2], ah[mt][3], bAh + offA[mt] + ks);
                ldsm4(al[mt][0], al[mt][1], al[mt][2], al[mt][3], bAl + offA[mt] + ks);
            }
#pragma unroll
            for (int nb = 0; nb < 4; nb++)
                ldsm4(bfr[nb][0], bfr[nb][1], bfr[nb][2], bfr[nb][3], bB + offB[nb] + ks);
#pragma unroll
            for (int mt = 0; mt < 2; mt++)
#pragma unroll
                for (int nb = 0; nb < 4; nb++)
#pragma unroll
                    for (int hf = 0; hf < 2; hf++) {
                        float* c = acc[mt][nb * 2 + hf];
                        mma16816f(c, ah[mt], bfr[nb][hf], bfr[nb][hf + 2]);
                        mma16816f(c, al[mt], bfr[nb][hf], bfr[nb][hf + 2]);
                    }
        }
    }

#pragma unroll
    for (int mt = 0; mt < 2; mt++) {
        int r0 = bm + wm + mt * 16 + (lane >> 2);
#pragma unroll
        for (int nt = 0; nt < 8; nt++) {
            int c0 = bn + wn + nt * 8 + (lane & 3) * 2;
            float* p = acc[mt][nt];
            *(float2*)&C[(size_t)r0 * N + c0]       = make_float2(p[0], p[1]);
            *(float2*)&C[(size_t)(r0 + 8) * N + c0] = make_float2(p[2], p[3]);
        }
    }
}

// ---------------- 1-pass: O projection ----------------
#define G1STAGE (2 * TILE80)
#define G1SMEM  (3 * G1STAGE)
__global__ __launch_bounds__(256) void gemm1p(
    const __half* __restrict__ A, const __half* __restrict__ B,
    float* __restrict__ C, int N, int K)
{
    extern __shared__ char smraw[];
    const uint32_t sbase = s2u32(smraw);
    const int tid  = threadIdx.x;
    const int wid  = tid >> 5;
    const int lane = tid & 31;
    const int bm = blockIdx.y << 7, bn = blockIdx.x << 7;
    const int wm = (wid & 3) * 32;
    const int wn = (wid >> 2) * 64;
    const int NCH = K >> 5;

    float acc[2][8][4];
#pragma unroll
    for (int i = 0; i < 2; i++)
#pragma unroll
        for (int j = 0; j < 8; j++)
#pragma unroll
            for (int t = 0; t < 4; t++) acc[i][j][t] = 0.0f;

    auto load_stage = [&](int ch, int st) {
        const int k0 = ch << 5;
        const uint32_t stb = sbase + st * G1STAGE;
#pragma unroll
        for (int i = 0; i < 4; i++) {
            int f = i * 256 + tid;
            int tile = f >> 9;
            int c = f & 511;
            int row = c >> 2, c4 = c & 3;
            const __half* g = tile ? B : A;
            int rb = tile ? bn : bm;
            cp16(stb + tile * TILE80 + row * 80 + c4 * 16,
                 g + (size_t)(rb + row) * K + k0 + c4 * 8);
        }
    };

    uint32_t offA[2], offB[4];
#pragma unroll
    for (int mt = 0; mt < 2; mt++)
        offA[mt] = (uint32_t)((wm + mt * 16 + (lane & 15)) * 80 + (lane >> 4) * 16);
#pragma unroll
    for (int nb = 0; nb < 4; nb++)
        offB[nb] = (uint32_t)((wn + nb * 16 + (lane & 15)) * 80 + (lane >> 4) * 16);

    load_stage(0, 0); cp_commit();
    load_stage(1, 1); cp_commit();

    for (int it = 0; it < NCH; ++it) {
        if (it + 1 < NCH) cp_wait<1>(); else cp_wait<0>();
        __syncthreads();
        if (it + 2 < NCH) { load_stage(it + 2, (it + 2) % 3); cp_commit(); }

        const uint32_t bA = sbase + (it % 3) * G1STAGE;
        const uint32_t bB = bA + TILE80;

#pragma unroll
        for (int kk = 0; kk < 2; kk++) {
            const uint32_t ks = kk * 32;
            uint32_t a[2][4], bfr[4][4];
#pragma unroll
            for (int mt = 0; mt < 2; mt++)
                ldsm4(a[mt][0], a[mt][1], a[mt][2], a[mt][3], bA + offA[mt] + ks);
#pragma unroll
            for (int nb = 0; nb < 4; nb++)
                ldsm4(bfr[nb][0], bfr[nb][1], bfr[nb][2], bfr[nb][3], bB + offB[nb] + ks);
#pragma unroll
            for (int mt = 0; mt < 2; mt++)
#pragma unroll
                for (int nb = 0; nb < 4; nb++)
#pragma unroll
                    for (int hf = 0; hf < 2; hf++)
                        mma16816f(acc[mt][nb * 2 + hf], a[mt],
                                  bfr[nb][hf], bfr[nb][hf + 2]);
        }
    }

#pragma unroll
    for (int mt = 0; mt < 2; mt++) {
        int r0 = bm + wm + mt * 16 + (lane >> 2);
#pragma unroll
        for (int nt = 0; nt < 8; nt++) {
            int c0 = bn + wn + nt * 8 + (lane & 3) * 2;
            float* p = acc[mt][nt];
            *(float2*)&C[(size_t)r0 * N + c0]       = make_float2(p[0], p[1]);
            *(float2*)&C[(size_t)(r0 + 8) * N + c0] = make_float2(p[2], p[3]);
        }
    }
}

// ---------------- RoPE ----------------
__global__ __launch_bounds__(256) void rope_kernel(
    float* __restrict__ t, const float* __restrict__ cosb,
    const float* __restrict__ sinb, int H, int total)
{
    int idx = blockIdx.x * blockDim.x + threadIdx.x;
    if (idx >= total) return;
    int j   = idx & 63;
    int bnh = idx >> 6;
    int n   = (bnh / H) & (NSEQ - 1);
    float c = cosb[n * 64 + j];
    float s = sinb[n * 64 + j];
    float* p = t + ((size_t)bnh << 7) + 2 * j;
    float x0 = p[0], x1 = p[1];
    p[0] = x0 * c - x1 * s;
    p[1] = x0 * s + x1 * c;
}

// ---------------- flash attention via mma.sync ----------------
// 128 q-rows/CTA, 8 warps x 16 rows, 64-key tiles double buffered.
// S: fp16 hi/lo 3-pass; PV: fp16 single pass. fp32 softmax/accum.
#define APITCH  272
#define QS_BYTES (128 * APITCH)
#define KVTILE   (64 * APITCH)
#define STG      (3 * KVTILE)
#define ASMEM    (2 * QS_BYTES + 2 * STG)
__global__ __launch_bounds__(256) void attn_mma(
    const float* __restrict__ Q, const __half* __restrict__ Kh,
    const __half* __restrict__ Kl, const __half* __restrict__ V,
    __half* __restrict__ O16)
{
    extern __shared__ char smraw[];
    const uint32_t sb = s2u32(smraw);
    const uint32_t qh_s = sb;
    const uint32_t ql_s = sb + QS_BYTES;
    const uint32_t kvb  = sb + 2 * QS_BYTES;

    const int tid = threadIdx.x;
    const int wid = tid >> 5, lane = tid & 31;
    const int qt = blockIdx.x;
    const int bh = blockIdx.y;
    const int b = bh >> 5, h = bh & 31;
    const int kvh = h >> 2;

    {
        const float* qbase = Q + ((size_t)(b * NSEQ + qt * 128) * NHEAD + h) * HDIM;
#pragma unroll
        for (int i = 0; i < 32; i++) {
            int idx = tid + i * 256;
            int r = idx >> 6, c2 = idx & 63;
            float2 v = *(const float2*)(qbase + (size_t)r * (NHEAD * HDIM) + c2 * 2);
            v.x *= ATT_SCALE; v.y *= ATT_SCALE;
            __half hx = __float2half_rn(v.x), hy = __float2half_rn(v.y);
            __half lx = __float2half_rn(v.x - __half2float(hx));
            __half ly = __float2half_rn(v.y - __half2float(hy));
            uint32_t off = (uint32_t)(r * APITCH + c2 * 4);
            *(__half2*)(smraw + off)            = __halves2half2(hx, hy);
            *(__half2*)(smraw + QS_BYTES + off) = __halves2half2(lx, ly);
        }
    }

    const size_t kvstride = (size_t)NKV * HDIM;
    auto load_kv = [&](int kt, int st) {
        const uint32_t stb = kvb + st * STG;
        const size_t row0 = ((size_t)(b * NSEQ + kt * 64) * NKV + kvh) * HDIM;
#pragma unroll
        for (int i = 0; i < 12; i++) {
            int f = i * 256 + tid;
            int tile = f >> 10;
            int c = f & 1023;
            int row = c >> 4, ch = c & 15;
            const __half* src = (tile == 0 ? Kh : (tile == 1 ? Kl : V))
                                + row0 + (size_t)row * kvstride + ch * 8;
            cp16(stb + tile * KVTILE + row * APITCH + ch * 16, src);
        }
    };

    float o[16][4];
#pragma unroll
    for (int t = 0; t < 16; t++)
#pragma unroll
        for (int r = 0; r < 4; r++) o[t][r] = 0.0f;
    float m0 = -1e30f, m1 = -1e30f, l0 = 0.0f, l1 = 0.0f;

    const int NIT = 2 * qt + 2;
    load_kv(0, 0); cp_commit();

    const int rowA = qt * 128 + wid * 16 + (lane >> 2);
    const uint32_t aoff = (uint32_t)((wid * 16 + (lane & 15)) * APITCH + (lane >> 4) * 16);

    for (int it = 0; it < NIT; it++) {
        const int st = it & 1;
        cp_wait<0>();
        __syncthreads();
        if (it + 1 < NIT) { load_kv(it + 1, (it + 1) & 1); cp_commit(); }

        const uint32_t kh_t = kvb + st * STG;
        const uint32_t kl_t = kh_t + KVTILE;
        const uint32_t v_t  = kh_t + 2 * KVTILE;

        float s[8][4];
#pragma unroll
        for (int t = 0; t < 8; t++)
#pragma unroll
            for (int r = 0; r < 4; r++) s[t][r] = 0.0f;

#pragma unroll
        for (int kki = 0; kki < 8; kki++) {
            uint32_t ah[4], al[4];
            ldsm4(ah[0], ah[1], ah[2], ah[3], qh_s + aoff + kki * 32);
            ldsm4(al[0], al[1], al[2], al[3], ql_s + aoff + kki * 32);
#pragma unroll
            for (int g = 0; g < 4; g++) {
                uint32_t boff = (uint32_t)((16 * g + (lane & 15)) * APITCH
                                           + (kki * 2 + (lane >> 4)) * 16);
                uint32_t b0, b1, b2, b3, c0, c1, c2, c3;
                ldsm4(b0, b1, b2, b3, kh_t + boff);
                ldsm4(c0, c1, c2, c3, kl_t + boff);
                mma16816f(s[2 * g],     ah, b0, b2);
                mma16816f(s[2 * g],     ah, c0, c2);
                mma16816f(s[2 * g],     al, b0, b2);
                mma16816f(s[2 * g + 1], ah, b1, b3);
                mma16816f(s[2 * g + 1], ah, c1, c3);
                mma16816f(s[2 * g + 1], al, b1, b3);
            }
        }

        if (it >= 2 * qt) {
            const int kbase = it * 64 + (lane & 3) * 2;
#pragma unroll
            for (int t = 0; t < 8; t++) {
                int k0 = kbase + t * 8;
                if (k0     > rowA)     s[t][0] = -1e30f;
                if (k0 + 1 > rowA)     s[t][1] = -1e30f;
                if (k0     > rowA + 8) s[t][2] = -1e30f;
                if (k0 + 1 > rowA + 8) s[t][3] = -1e30f;
            }
        }

        float mxA = m0, mxB = m1;
#pragma unroll
        for (int t = 0; t < 8; t++) {
            mxA = fmaxf(mxA, fmaxf(s[t][0], s[t][1]));
            mxB = fmaxf(mxB, fmaxf(s[t][2], s[t][3]));
        }
        mxA = fmaxf(mxA, __shfl_xor_sync(0xFFFFFFFFu, mxA, 1));
        mxA = fmaxf(mxA, __shfl_xor_sync(0xFFFFFFFFu, mxA, 2));
        mxB = fmaxf(mxB, __shfl_xor_sync(0xFFFFFFFFu, mxB, 1));
        mxB = fmaxf(mxB, __shfl_xor_sync(0xFFFFFFFFu, mxB, 2));

        float aA = __expf(m0 - mxA), aB = __expf(m1 - mxB);
        float sA = 0.0f, sB = 0.0f;
#pragma unroll
        for (int t = 0; t < 8; t++) {
            s[t][0] = __expf(s[t][0] - mxA);
            s[t][1] = __expf(s[t][1] - mxA);
            s[t][2] = __expf(s[t][2] - mxB);
            s[t][3] = __expf(s[t][3] - mxB);
            sA += s[t][0] + s[t][1];
            sB += s[t][2] + s[t][3];
        }
        sA += __shfl_xor_sync(0xFFFFFFFFu, sA, 1);
        sA += __shfl_xor_sync(0xFFFFFFFFu, sA, 2);
        sB += __shfl_xor_sync(0xFFFFFFFFu, sB, 1);
        sB += __shfl_xor_sync(0xFFFFFFFFu, sB, 2);
        l0 = l0 * aA + sA;  l1 = l1 * aB + sB;
        m0 = mxA;           m1 = mxB;

#pragma unroll
        for (int t = 0; t < 16; t++) {
            o[t][0] *= aA; o[t][1] *= aA;
            o[t][2] *= aB; o[t][3] *= aB;
        }

        uint32_t ap[4][4];
#pragma unroll
        for (int kk = 0; kk < 4; kk++) {
            ap[kk][0] = packh2(s[2 * kk][0],     s[2 * kk][1]);
            ap[kk][1] = packh2(s[2 * kk][2],     s[2 * kk][3]);
            ap[kk][2] = packh2(s[2 * kk + 1][0], s[2 * kk + 1][1]);
            ap[kk][3] = packh2(s[2 * kk + 1][2], s[2 * kk + 1][3]);
        }
        const uint32_t vrow = (uint32_t)((((lane >> 3) & 1) * 8 + (lane & 7)) * APITCH
                                         + (lane >> 4) * 16);
#pragma unroll
        for (int kk = 0; kk < 4; kk++) {
#pragma unroll
            for (int g = 0; g < 8; g++) {
                uint32_t v0, v1, v2, v3;
                ldsm4t(v0, v1, v2, v3, v_t + vrow + (uint32_t)(16 * kk * APITCH + g * 32));
                mma16816f(o[2 * g],     ap[kk], v0, v1);
                mma16816f(o[2 * g + 1], ap[kk], v2, v3);
            }
        }
    }

    const float iA = 1.0f / l0, iB = 1.0f / l1;
    __half* obase = O16 + ((size_t)(b * NSEQ) * NHEAD + h) * HDIM;
#pragma unroll
    for (int t = 0; t < 16; t++) {
        int d = t * 8 + (lane & 3) * 2;
        *(__half2*)(obase + (size_t)rowA * (NHEAD * HDIM) + d) =
            __floats2half2_rn(o[t][0] * iA, o[t][1] * iA);
        *(__half2*)(obase + (size_t)(rowA + 8) * (NHEAD * HDIM) + d) =
            __floats2half2_rn(o[t][2] * iB, o[t][3] * iB);
    }
}

// ---------------- launch ----------------
extern "C" void kernel_launch(void* const* d_in, const int* in_sizes, int n_in,
                              void* d_out, int out_size)
{
    const float* x    = (const float*)d_in[0];
    const float* wq   = (const float*)d_in[1];
    const float* wk   = (const float*)d_in[2];
    const float* wv   = (const float*)d_in[3];
    const float* wo   = (const float*)d_in[4];
    const float* cosb = (const float*)d_in[5];
    const float* sinb = (const float*)d_in[6];
    float* out = (float*)d_out;

    float *pq, *pk, *pv;
    cudaGetSymbolAddress((void**)&pq, g_q);
    cudaGetSymbolAddress((void**)&pk, g_k);
    cudaGetSymbolAddress((void**)&pv, g_v);
    __half *x16h, *x16l, *wq16, *wk16h, *wk16l, *wv16h, *wv16l, *wo16;
    cudaGetSymbolAddress((void**)&x16h,  g_x16h);
    cudaGetSymbolAddress((void**)&x16l,  g_x16l);
    cudaGetSymbolAddress((void**)&wq16,  g_wq16);
    cudaGetSymbolAddress((void**)&wk16h, g_wk16h);
    cudaGetSymbolAddress((void**)&wk16l, g_wk16l);
    cudaGetSymbolAddress((void**)&wv16h, g_wv16h);
    cudaGetSymbolAddress((void**)&wv16l, g_wv16l);
    cudaGetSymbolAddress((void**)&wo16,  g_wo16);
    __half *k16h, *k16l, *v16, *o16;
    cudaGetSymbolAddress((void**)&k16h, g_k16h);
    cudaGetSymbolAddress((void**)&k16l, g_k16l);
    cudaGetSymbolAddress((void**)&v16,  g_v16);
    cudaGetSymbolAddress((void**)&o16,  g_o16);

    cudaFuncSetAttribute(gemm3p, cudaFuncAttributeMaxDynamicSharedMemorySize, G3SMEM);
    cudaFuncSetAttribute(gemm2p, cudaFuncAttributeMaxDynamicSharedMemorySize, G2SMEM);
    cudaFuncSetAttribute(gemm1p, cudaFuncAttributeMaxDynamicSharedMemorySize, G1SMEM);
    cudaFuncSetAttribute(attn_mma, cudaFuncAttributeMaxDynamicSharedMemorySize, ASMEM);

    dim3 blk(256);

    // fp16 hi/lo splits + converts
    splitf16_kernel<<<(MROWS * DIMM / 4 + 255) / 256, blk>>>(x, x16h, x16l, MROWS * DIMM / 4);
    cvt16_kernel<<<(DIMM * DIMM / 4 + 255) / 256, blk>>>(wq, wq16, DIMM * DIMM / 4);
    splitf16_kernel<<<(KVDIM * DIMM / 4 + 255) / 256, blk>>>(wk, wk16h, wk16l, KVDIM * DIMM / 4);
    splitf16_kernel<<<(KVDIM * DIMM / 4 + 255) / 256, blk>>>(wv, wv16h, wv16l, KVDIM * DIMM / 4);
    cvt16_kernel<<<(DIMM * DIMM / 4 + 255) / 256, blk>>>(wo, wo16, DIMM * DIMM / 4);

    // projections: Q 2-pass, K/V 3-pass
    gemm2p<<<dim3(DIMM / 128, MROWS / 128), blk, G2SMEM>>>(x16h, x16l, wq16, pq, DIMM, DIMM);
    gemm3p<<<dim3(KVDIM / 128, MROWS / 128), blk, G3SMEM>>>(x16h, x16l, wk16h, wk16l, pk, KVDIM, DIMM);
    gemm3p<<<dim3(KVDIM / 128, MROWS / 128), blk, G3SMEM>>>(x16h, x16l, wv16h, wv16l, pv, KVDIM, DIMM);

    // RoPE
    int qtot = BATCH * NSEQ * NHEAD * 64;
    int ktot = BATCH * NSEQ * NKV * 64;
    rope_kernel<<<(qtot + 255) / 256, blk>>>(pq, cosb, sinb, NHEAD, qtot);
    rope_kernel<<<(ktot + 255) / 256, blk>>>(pk, cosb, sinb, NKV, ktot);

    // K hi/lo fp16 + V fp16
    splitf16_kernel<<<(MROWS * KVDIM / 4 + 255) / 256, blk>>>(pk, k16h, k16l, MROWS * KVDIM / 4);
    cvt16_kernel<<<(MROWS * KVDIM / 4 + 255) / 256, blk>>>(pv, v16, MROWS * KVDIM / 4);

    // attention (writes fp16 o16)
    attn_mma<<<dim3(NSEQ / 128, BATCH * NHEAD), blk, ASMEM>>>(pq, k16h, k16l, v16, o16);

    // output projection: single-pass fp16
    gemm1p<<<dim3(DIMM / 128, MROWS / 128), blk, G1SMEM>>>(o16, wo16, out, DIMM, DIMM);
}

// round 8
// speedup vs baseline: 8.5907x; 1.2134x over previous
#include <cuda_runtime.h>
#include <cuda_fp16.h>
#include <cstdint>

// ---------------- constants ----------------
#define BATCH   2
#define NSEQ    2048
#define DIMM    4096
#define NHEAD   32
#define NKV     8
#define HDIM    128
#define MROWS   (BATCH*NSEQ)            // 4096
#define KVDIM   (NKV*HDIM)              // 1024
#define ATT_SCALE 0.08838834764831845f  // 1/sqrt(128)

// ---------------- scratch (device globals; no allocations allowed) ----------------
__device__ __half g_x16h[MROWS * DIMM], g_x16l[MROWS * DIMM];
__device__ __half g_wq16[DIMM * DIMM];
__device__ __half g_wk16[KVDIM * DIMM];
__device__ __half g_wv16[KVDIM * DIMM];
__device__ __half g_wo16[DIMM * DIMM];

__device__ __half g_q16h[MROWS * DIMM], g_q16l[MROWS * DIMM];  // roped+scaled Q hi/lo
__device__ __half g_k16[MROWS * KVDIM];                        // roped K
__device__ __half g_v16[MROWS * KVDIM];
__device__ __half g_o16[MROWS * DIMM];

// ---------------- PTX helpers (plain sm_80+ PTX) ----------------
__device__ __forceinline__ uint32_t s2u32(const void* p) {
    uint32_t a;
    asm("{ .reg .u64 t; cvta.to.shared.u64 t, %1; cvt.u32.u64 %0, t; }" : "=r"(a) : "l"(p));
    return a;
}
__device__ __forceinline__ void cp16(uint32_t d, const void* s) {
    asm volatile("cp.async.cg.shared.global [%0], [%1], 16;" :: "r"(d), "l"(s));
}
__device__ __forceinline__ void cp_commit() {
    asm volatile("cp.async.commit_group;" ::: "memory");
}
template <int N>
__device__ __forceinline__ void cp_wait() {
    asm volatile("cp.async.wait_group %0;" :: "n"(N) : "memory");
}
__device__ __forceinline__ void ldsm4(uint32_t& r0, uint32_t& r1, uint32_t& r2,
                                      uint32_t& r3, uint32_t addr) {
    asm volatile("ldmatrix.sync.aligned.m8n8.x4.shared.b16 {%0,%1,%2,%3}, [%4];"
                 : "=r"(r0), "=r"(r1), "=r"(r2), "=r"(r3) : "r"(addr));
}
__device__ __forceinline__ void ldsm4t(uint32_t& r0, uint32_t& r1, uint32_t& r2,
                                       uint32_t& r3, uint32_t addr) {
    asm volatile("ldmatrix.sync.aligned.m8n8.x4.trans.shared.b16 {%0,%1,%2,%3}, [%4];"
                 : "=r"(r0), "=r"(r1), "=r"(r2), "=r"(r3) : "r"(addr));
}
__device__ __forceinline__ void mma16816f(float* c, const uint32_t* a, uint32_t b0, uint32_t b1) {
    asm volatile(
        "mma.sync.aligned.m16n8k16.row.col.f32.f16.f16.f32 "
        "{%0,%1,%2,%3}, {%4,%5,%6,%7}, {%8,%9}, {%0,%1,%2,%3};"
        : "+f"(c[0]), "+f"(c[1]), "+f"(c[2]), "+f"(c[3])
        : "r"(a[0]), "r"(a[1]), "r"(a[2]), "r"(a[3]), "r"(b0), "r"(b1));
}
__device__ __forceinline__ uint32_t packh2(float x, float y) {
    __half2 h = __floats2half2_rn(x, y);
    return *(uint32_t*)&h;
}

// ---------------- hi/lo split: fp32 -> fp16 pair ----------------
__global__ __launch_bounds__(256) void splitf16_kernel(
    const float* __restrict__ src, __half* __restrict__ hi,
    __half* __restrict__ lo, int n4)
{
    int i = blockIdx.x * blockDim.x + threadIdx.x;
    if (i >= n4) return;
    float4 v = ((const float4*)src)[i];
    __half h0 = __float2half_rn(v.x), h1 = __float2half_rn(v.y);
    __half h2 = __float2half_rn(v.z), h3 = __float2half_rn(v.w);
    __half l0 = __float2half_rn(v.x - __half2float(h0));
    __half l1 = __float2half_rn(v.y - __half2float(h1));
    __half l2 = __float2half_rn(v.z - __half2float(h2));
    __half l3 = __float2half_rn(v.w - __half2float(h3));
    ((__half2*)hi)[2 * i]     = __halves2half2(h0, h1);
    ((__half2*)hi)[2 * i + 1] = __halves2half2(h2, h3);
    ((__half2*)lo)[2 * i]     = __halves2half2(l0, l1);
    ((__half2*)lo)[2 * i + 1] = __halves2half2(l2, l3);
}

// ---------------- fp32 -> fp16 convert ----------------
__global__ __launch_bounds__(256) void cvt16_kernel(
    const float* __restrict__ src, __half* __restrict__ dst, int n4)
{
    int i = blockIdx.x * blockDim.x + threadIdx.x;
    if (i >= n4) return;
    float4 v = ((const float4*)src)[i];
    ((__half2*)dst)[2 * i]     = __floats2half2_rn(v.x, v.y);
    ((__half2*)dst)[2 * i + 1] = __floats2half2_rn(v.z, v.w);
}

// =====================================================================
// GEMM: C[M,N] = A[M,K] * B[N,K]^T, fp16 in, fp32 accum.
// CTA 128x128, BK=32, 256 thr (8 warps, warp tile 32x64), 3-stage cp.async,
// single __syncthreads per iteration.
// =====================================================================
#define TILE80 (128 * 80)

// ---------------- 2-pass (A hi/lo, B single) with fused epilogues ----------------
// EPI 0: rope + ATT_SCALE + hi/lo fp16 split (Q)   -> Ch, Cl
// EPI 1: rope + fp16 (K)                            -> Ch
// EPI 2: fp16 (V)                                   -> Ch
#define G2STAGE (3 * TILE80)
#define G2SMEM  (3 * G2STAGE)
template <int EPI>
__global__ __launch_bounds__(256) void gemm2p(
    const __half* __restrict__ Ah, const __half* __restrict__ Al,
    const __half* __restrict__ B, __half* __restrict__ Ch, __half* __restrict__ Cl,
    const float* __restrict__ cosb, const float* __restrict__ sinb, int N, int K)
{
    extern __shared__ char smraw[];
    const uint32_t sbase = s2u32(smraw);
    const int tid  = threadIdx.x;
    const int wid  = tid >> 5;
    const int lane = tid & 31;
    const int bm = blockIdx.y << 7, bn = blockIdx.x << 7;
    const int wm = (wid & 3) * 32;
    const int wn = (wid >> 2) * 64;
    const int NCH = K >> 5;

    float acc[2][8][4];
#pragma unroll
    for (int i = 0; i < 2; i++)
#pragma unroll
        for (int j = 0; j < 8; j++)
#pragma unroll
            for (int t = 0; t < 4; t++) acc[i][j][t] = 0.0f;

    const __half* tsrc[3] = {Ah, Al, B};

    auto load_stage = [&](int ch, int st) {
        const int k0 = ch << 5;
        const uint32_t stb = sbase + st * G2STAGE;
#pragma unroll
        for (int i = 0; i < 6; i++) {
            int f = i * 256 + tid;
            int tile = f >> 9;
            int c = f & 511;
            int row = c >> 2, c4 = c & 3;
            const __half* g = tsrc[tile];
            int rb = (tile < 2) ? bm : bn;
            cp16(stb + tile * TILE80 + row * 80 + c4 * 16,
                 g + (size_t)(rb + row) * K + k0 + c4 * 8);
        }
    };

    uint32_t offA[2], offB[4];
#pragma unroll
    for (int mt = 0; mt < 2; mt++)
        offA[mt] = (uint32_t)((wm + mt * 16 + (lane & 15)) * 80 + (lane >> 4) * 16);
#pragma unroll
    for (int nb = 0; nb < 4; nb++)
        offB[nb] = (uint32_t)((wn + nb * 16 + (lane & 15)) * 80 + (lane >> 4) * 16);

    load_stage(0, 0); cp_commit();
    load_stage(1, 1); cp_commit();

    for (int it = 0; it < NCH; ++it) {
        if (it + 1 < NCH) cp_wait<1>(); else cp_wait<0>();
        __syncthreads();
        if (it + 2 < NCH) { load_stage(it + 2, (it + 2) % 3); cp_commit(); }

        const uint32_t bAh = sbase + (it % 3) * G2STAGE;
        const uint32_t bAl = bAh + TILE80;
        const uint32_t bB  = bAh + 2 * TILE80;

#pragma unroll
        for (int kk = 0; kk < 2; kk++) {
            const uint32_t ks = kk * 32;
            uint32_t ah[2][4], al[2][4], bfr[4][4];
#pragma unroll
            for (int mt = 0; mt < 2; mt++) {
                ldsm4(ah[mt][0], ah[mt][1], ah[mt][2], ah[mt][3], bAh + offA[mt] + ks);
                ldsm4(al[mt][0], al[mt][1], al[mt][2], al[mt][3], bAl + offA[mt] + ks);
            }
#pragma unroll
            for (int nb = 0; nb < 4; nb++)
                ldsm4(bfr[nb][0], bfr[nb][1], bfr[nb][2], bfr[nb][3], bB + offB[nb] + ks);
#pragma unroll
            for (int mt = 0; mt < 2; mt++)
#pragma unroll
                for (int nb = 0; nb < 4; nb++)
#pragma unroll
                    for (int hf = 0; hf < 2; hf++) {
                        float* c = acc[mt][nb * 2 + hf];
                        mma16816f(c, ah[mt], bfr[nb][hf], bfr[nb][hf + 2]);
                        mma16816f(c, al[mt], bfr[nb][hf], bfr[nb][hf + 2]);
                    }
        }
    }

    // fused epilogue
#pragma unroll
    for (int mt = 0; mt < 2; mt++) {
        int r0 = bm + wm + mt * 16 + (lane >> 2);
        int n0 = r0 & (NSEQ - 1);           // seq position (rows never straddle batches)
#pragma unroll
        for (int nt = 0; nt < 8; nt++) {
            int c0 = bn + wn + nt * 8 + (lane & 3) * 2;   // even column
            float* p = acc[mt][nt];
            float p0 = p[0], p1 = p[1], p2 = p[2], p3 = p[3];
            if (EPI <= 1) {   // rope: (p0,p1) at row r0, (p2,p3) at row r0+8, same pair j
                int j = (c0 & (HDIM - 1)) >> 1;
                float ca = cosb[n0 * 64 + j],       sa = sinb[n0 * 64 + j];
                float cb = cosb[(n0 + 8) * 64 + j], sb = sinb[(n0 + 8) * 64 + j];
                float t0 = p0 * ca - p1 * sa, t1 = p0 * sa + p1 * ca;
                float t2 = p2 * cb - p3 * sb, t3 = p2 * sb + p3 * cb;
                p0 = t0; p1 = t1; p2 = t2; p3 = t3;
            }
            if (EPI == 0) {
                p0 *= ATT_SCALE; p1 *= ATT_SCALE; p2 *= ATT_SCALE; p3 *= ATT_SCALE;
                __half h0 = __float2half_rn(p0), h1 = __float2half_rn(p1);
                __half h2 = __float2half_rn(p2), h3 = __float2half_rn(p3);
                *(__half2*)&Ch[(size_t)r0 * N + c0]       = __halves2half2(h0, h1);
                *(__half2*)&Ch[(size_t)(r0 + 8) * N + c0] = __halves2half2(h2, h3);
                *(__half2*)&Cl[(size_t)r0 * N + c0] = __halves2half2(
                    __float2half_rn(p0 - __half2float(h0)),
                    __float2half_rn(p1 - __half2float(h1)));
                *(__half2*)&Cl[(size_t)(r0 + 8) * N + c0] = __halves2half2(
                    __float2half_rn(p2 - __half2float(h2)),
                    __float2half_rn(p3 - __half2float(h3)));
            } else {
                *(__half2*)&Ch[(size_t)r0 * N + c0]       = __floats2half2_rn(p0, p1);
                *(__half2*)&Ch[(size_t)(r0 + 8) * N + c0] = __floats2half2_rn(p2, p3);
            }
        }
    }
}

// ---------------- 1-pass fp16 -> fp32 out: O projection ----------------
#define G1STAGE (2 * TILE80)
#define G1SMEM  (3 * G1STAGE)
__global__ __launch_bounds__(256) void gemm1p(
    const __half* __restrict__ A, const __half* __restrict__ B,
    float* __restrict__ C, int N, int K)
{
    extern __shared__ char smraw[];
    const uint32_t sbase = s2u32(smraw);
    const int tid  = threadIdx.x;
    const int wid  = tid >> 5;
    const int lane = tid & 31;
    const int bm = blockIdx.y << 7, bn = blockIdx.x << 7;
    const int wm = (wid & 3) * 32;
    const int wn = (wid >> 2) * 64;
    const int NCH = K >> 5;

    float acc[2][8][4];
#pragma unroll
    for (int i = 0; i < 2; i++)
#pragma unroll
        for (int j = 0; j < 8; j++)
#pragma unroll
            for (int t = 0; t < 4; t++) acc[i][j][t] = 0.0f;

    auto load_stage = [&](int ch, int st) {
        const int k0 = ch << 5;
        const uint32_t stb = sbase + st * G1STAGE;
#pragma unroll
        for (int i = 0; i < 4; i++) {
            int f = i * 256 + tid;
            int tile = f >> 9;
            int c = f & 511;
            int row = c >> 2, c4 = c & 3;
            const __half* g = tile ? B : A;
            int rb = tile ? bn : bm;
            cp16(stb + tile * TILE80 + row * 80 + c4 * 16,
                 g + (size_t)(rb + row) * K + k0 + c4 * 8);
        }
    };

    uint32_t offA[2], offB[4];
#pragma unroll
    for (int mt = 0; mt < 2; mt++)
        offA[mt] = (uint32_t)((wm + mt * 16 + (lane & 15)) * 80 + (lane >> 4) * 16);
#pragma unroll
    for (int nb = 0; nb < 4; nb++)
        offB[nb] = (uint32_t)((wn + nb * 16 + (lane & 15)) * 80 + (lane >> 4) * 16);

    load_stage(0, 0); cp_commit();
    load_stage(1, 1); cp_commit();

    for (int it = 0; it < NCH; ++it) {
        if (it + 1 < NCH) cp_wait<1>(); else cp_wait<0>();
        __syncthreads();
        if (it + 2 < NCH) { load_stage(it + 2, (it + 2) % 3); cp_commit(); }

        const uint32_t bA = sbase + (it % 3) * G1STAGE;
        const uint32_t bB = bA + TILE80;

#pragma unroll
        for (int kk = 0; kk < 2; kk++) {
            const uint32_t ks = kk * 32;
            uint32_t a[2][4], bfr[4][4];
#pragma unroll
            for (int mt = 0; mt < 2; mt++)
                ldsm4(a[mt][0], a[mt][1], a[mt][2], a[mt][3], bA + offA[mt] + ks);
#pragma unroll
            for (int nb = 0; nb < 4; nb++)
                ldsm4(bfr[nb][0], bfr[nb][1], bfr[nb][2], bfr[nb][3], bB + offB[nb] + ks);
#pragma unroll
            for (int mt = 0; mt < 2; mt++)
#pragma unroll
                for (int nb = 0; nb < 4; nb++)
#pragma unroll
                    for (int hf = 0; hf < 2; hf++)
                        mma16816f(acc[mt][nb * 2 + hf], a[mt],
                                  bfr[nb][hf], bfr[nb][hf + 2]);
        }
    }

#pragma unroll
    for (int mt = 0; mt < 2; mt++) {
        int r0 = bm + wm + mt * 16 + (lane >> 2);
#pragma unroll
        for (int nt = 0; nt < 8; nt++) {
            int c0 = bn + wn + nt * 8 + (lane & 3) * 2;
            float* p = acc[mt][nt];
            *(float2*)&C[(size_t)r0 * N + c0]       = make_float2(p[0], p[1]);
            *(float2*)&C[(size_t)(r0 + 8) * N + c0] = make_float2(p[2], p[3]);
        }
    }
}

// ---------------- flash attention via mma.sync ----------------
// 128 q-rows/CTA, 8 warps x 16 rows, 64-key tiles double buffered.
// S: Q hi/lo 2-pass vs K fp16; PV: fp16 single pass. fp32 softmax/accum.
#define APITCH  272
#define QS_BYTES (128 * APITCH)            // 34816
#define KVTILE   (64 * APITCH)             // 17408
#define STG      (2 * KVTILE)              // K, V
#define ASMEM    (2 * QS_BYTES + 2 * STG)  // 139264
__global__ __launch_bounds__(256) void attn_mma(
    const __half* __restrict__ Qh, const __half* __restrict__ Ql,
    const __half* __restrict__ Kk, const __half* __restrict__ V,
    __half* __restrict__ O16)
{
    extern __shared__ char smraw[];
    const uint32_t sb = s2u32(smraw);
    const uint32_t qh_s = sb;
    const uint32_t ql_s = sb + QS_BYTES;
    const uint32_t kvb  = sb + 2 * QS_BYTES;

    const int tid = threadIdx.x;
    const int wid = tid >> 5, lane = tid & 31;
    const int qt = blockIdx.x;
    const int bh = blockIdx.y;
    const int b = bh >> 5, h = bh & 31;
    const int kvh = h >> 2;

    // ---- stage Q hi/lo via cp.async (already roped+scaled fp16) ----
    {
        const size_t qrow0 = (size_t)(b * NSEQ + qt * 128) * DIMM + h * HDIM;
#pragma unroll
        for (int i = 0; i < 16; i++) {
            int f = i * 256 + tid;           // 0..4095 16B chunks
            int tile = f >> 11;              // 0=Qh, 1=Ql
            int c = f & 2047;
            int row = c >> 4, ch = c & 15;
            const __half* src = (tile ? Ql : Qh) + qrow0 + (size_t)row * DIMM + ch * 8;
            cp16((tile ? ql_s : qh_s) + row * APITCH + ch * 16, src);
        }
    }

    auto load_kv = [&](int kt, int st) {
        const uint32_t stb = kvb + st * STG;
        const size_t row0 = (size_t)(b * NSEQ + kt * 64) * KVDIM + kvh * HDIM;
#pragma unroll
        for (int i = 0; i < 8; i++) {
            int f = i * 256 + tid;           // 0..2047 16B chunks
            int tile = f >> 10;              // 0=K, 1=V
            int c = f & 1023;
            int row = c >> 4, ch = c & 15;
            const __half* src = (tile ? V : Kk) + row0 + (size_t)row * KVDIM + ch * 8;
            cp16(stb + tile * KVTILE + row * APITCH + ch * 16, src);
        }
    };

    float o[16][4];
#pragma unroll
    for (int t = 0; t < 16; t++)
#pragma unroll
        for (int r = 0; r < 4; r++) o[t][r] = 0.0f;
    float m0 = -1e30f, m1 = -1e30f, l0 = 0.0f, l1 = 0.0f;

    const int NIT = 2 * qt + 2;
    load_kv(0, 0); cp_commit();

    const int rowA = qt * 128 + wid * 16 + (lane >> 2);
    const uint32_t aoff = (uint32_t)((wid * 16 + (lane & 15)) * APITCH + (lane >> 4) * 16);

    for (int it = 0; it < NIT; it++) {
        const int st = it & 1;
        cp_wait<0>();
        __syncthreads();
        if (it + 1 < NIT) { load_kv(it + 1, st ^ 1); cp_commit(); }

        const uint32_t k_t = kvb + st * STG;
        const uint32_t v_t = k_t + KVTILE;

        // ---- S = Q K^T (Q hi/lo 2-pass) ----
        float s[8][4];
#pragma unroll
        for (int t = 0; t < 8; t++)
#pragma unroll
            for (int r = 0; r < 4; r++) s[t][r] = 0.0f;

#pragma unroll
        for (int kki = 0; kki < 8; kki++) {
            uint32_t ah[4], al[4];
            ldsm4(ah[0], ah[1], ah[2], ah[3], qh_s + aoff + kki * 32);
            ldsm4(al[0], al[1], al[2], al[3], ql_s + aoff + kki * 32);
#pragma unroll
            for (int g = 0; g < 4; g++) {
                uint32_t boff = (uint32_t)((16 * g + (lane & 15)) * APITCH
                                           + (kki * 2 + (lane >> 4)) * 16);
                uint32_t b0, b1, b2, b3;
                ldsm4(b0, b1, b2, b3, k_t + boff);
                mma16816f(s[2 * g],     ah, b0, b2);
                mma16816f(s[2 * g],     al, b0, b2);
                mma16816f(s[2 * g + 1], ah, b1, b3);
                mma16816f(s[2 * g + 1], al, b1, b3);
            }
        }

        if (it >= 2 * qt) {
            const int kbase = it * 64 + (lane & 3) * 2;
#pragma unroll
            for (int t = 0; t < 8; t++) {
                int k0 = kbase + t * 8;
                if (k0     > rowA)     s[t][0] = -1e30f;
                if (k0 + 1 > rowA)     s[t][1] = -1e30f;
                if (k0     > rowA + 8) s[t][2] = -1e30f;
                if (k0 + 1 > rowA + 8) s[t][3] = -1e30f;
            }
        }

        float mxA = m0, mxB = m1;
#pragma unroll
        for (int t = 0; t < 8; t++) {
            mxA = fmaxf(mxA, fmaxf(s[t][0], s[t][1]));
            mxB = fmaxf(mxB, fmaxf(s[t][2], s[t][3]));
        }
        mxA = fmaxf(mxA, __shfl_xor_sync(0xFFFFFFFFu, mxA, 1));
        mxA = fmaxf(mxA, __shfl_xor_sync(0xFFFFFFFFu, mxA, 2));
        mxB = fmaxf(mxB, __shfl_xor_sync(0xFFFFFFFFu, mxB, 1));
        mxB = fmaxf(mxB, __shfl_xor_sync(0xFFFFFFFFu, mxB, 2));

        float aA = __expf(m0 - mxA), aB = __expf(m1 - mxB);
        float sA = 0.0f, sB = 0.0f;
#pragma unroll
        for (int t = 0; t < 8; t++) {
            s[t][0] = __expf(s[t][0] - mxA);
            s[t][1] = __expf(s[t][1] - mxA);
            s[t][2] = __expf(s[t][2] - mxB);
            s[t][3] = __expf(s[t][3] - mxB);
            sA += s[t][0] + s[t][1];
            sB += s[t][2] + s[t][3];
        }
        sA += __shfl_xor_sync(0xFFFFFFFFu, sA, 1);
        sA += __shfl_xor_sync(0xFFFFFFFFu, sA, 2);
        sB += __shfl_xor_sync(0xFFFFFFFFu, sB, 1);
        sB += __shfl_xor_sync(0xFFFFFFFFu, sB, 2);
        l0 = l0 * aA + sA;  l1 = l1 * aB + sB;
        m0 = mxA;           m1 = mxB;

#pragma unroll
        for (int t = 0; t < 16; t++) {
            o[t][0] *= aA; o[t][1] *= aA;
            o[t][2] *= aB; o[t][3] *= aB;
        }

        uint32_t ap[4][4];
#pragma unroll
        for (int kk = 0; kk < 4; kk++) {
            ap[kk][0] = packh2(s[2 * kk][0],     s[2 * kk][1]);
            ap[kk][1] = packh2(s[2 * kk][2],     s[2 * kk][3]);
            ap[kk][2] = packh2(s[2 * kk + 1][0], s[2 * kk + 1][1]);
            ap[kk][3] = packh2(s[2 * kk + 1][2], s[2 * kk + 1][3]);
        }
        const uint32_t vrow = (uint32_t)((((lane >> 3) & 1) * 8 + (lane & 7)) * APITCH
                                         + (lane >> 4) * 16);
#pragma unroll
        for (int kk = 0; kk < 4; kk++) {
#pragma unroll
            for (int g = 0; g < 8; g++) {
                uint32_t v0, v1, v2, v3;
                ldsm4t(v0, v1, v2, v3, v_t + vrow + (uint32_t)(16 * kk * APITCH + g * 32));
                mma16816f(o[2 * g],     ap[kk], v0, v1);
                mma16816f(o[2 * g + 1], ap[kk], v2, v3);
            }
        }
    }

    const float iA = 1.0f / l0, iB = 1.0f / l1;
    __half* obase = O16 + ((size_t)(b * NSEQ) * NHEAD + h) * HDIM;
#pragma unroll
    for (int t = 0; t < 16; t++) {
        int d = t * 8 + (lane & 3) * 2;
        *(__half2*)(obase + (size_t)rowA * (NHEAD * HDIM) + d) =
            __floats2half2_rn(o[t][0] * iA, o[t][1] * iA);
        *(__half2*)(obase + (size_t)(rowA + 8) * (NHEAD * HDIM) + d) =
            __floats2half2_rn(o[t][2] * iB, o[t][3] * iB);
    }
}

// ---------------- launch ----------------
extern "C" void kernel_launch(void* const* d_in, const int* in_sizes, int n_in,
                              void* d_out, int out_size)
{
    const float* x    = (const float*)d_in[0];
    const float* wq   = (const float*)d_in[1];
    const float* wk   = (const float*)d_in[2];
    const float* wv   = (const float*)d_in[3];
    const float* wo   = (const float*)d_in[4];
    const float* cosb = (const float*)d_in[5];
    const float* sinb = (const float*)d_in[6];
    float* out = (float*)d_out;

    __half *x16h, *x16l, *wq16, *wk16, *wv16, *wo16;
    cudaGetSymbolAddress((void**)&x16h, g_x16h);
    cudaGetSymbolAddress((void**)&x16l, g_x16l);
    cudaGetSymbolAddress((void**)&wq16, g_wq16);
    cudaGetSymbolAddress((void**)&wk16, g_wk16);
    cudaGetSymbolAddress((void**)&wv16, g_wv16);
    cudaGetSymbolAddress((void**)&wo16, g_wo16);
    __half *q16h, *q16l, *k16, *v16, *o16;
    cudaGetSymbolAddress((void**)&q16h, g_q16h);
    cudaGetSymbolAddress((void**)&q16l, g_q16l);
    cudaGetSymbolAddress((void**)&k16,  g_k16);
    cudaGetSymbolAddress((void**)&v16,  g_v16);
    cudaGetSymbolAddress((void**)&o16,  g_o16);

    cudaFuncSetAttribute(gemm2p<0>, cudaFuncAttributeMaxDynamicSharedMemorySize, G2SMEM);
    cudaFuncSetAttribute(gemm2p<1>, cudaFuncAttributeMaxDynamicSharedMemorySize, G2SMEM);
    cudaFuncSetAttribute(gemm2p<2>, cudaFuncAttributeMaxDynamicSharedMemorySize, G2SMEM);
    cudaFuncSetAttribute(gemm1p, cudaFuncAttributeMaxDynamicSharedMemorySize, G1SMEM);
    cudaFuncSetAttribute(attn_mma, cudaFuncAttributeMaxDynamicSharedMemorySize, ASMEM);

    dim3 blk(256);

    // input conversions
    splitf16_kernel<<<(MROWS * DIMM / 4 + 255) / 256, blk>>>(x, x16h, x16l, MROWS * DIMM / 4);
    cvt16_kernel<<<(DIMM * DIMM / 4 + 255) / 256, blk>>>(wq, wq16, DIMM * DIMM / 4);
    cvt16_kernel<<<(KVDIM * DIMM / 4 + 255) / 256, blk>>>(wk, wk16, KVDIM * DIMM / 4);
    cvt16_kernel<<<(KVDIM * DIMM / 4 + 255) / 256, blk>>>(wv, wv16, KVDIM * DIMM / 4);
    cvt16_kernel<<<(DIMM * DIMM / 4 + 255) / 256, blk>>>(wo, wo16, DIMM * DIMM / 4);

    // projections with fused rope/scale/convert epilogues
    gemm2p<0><<<dim3(DIMM / 128, MROWS / 128), blk, G2SMEM>>>(
        x16h, x16l, wq16, q16h, q16l, cosb, sinb, DIMM, DIMM);
    gemm2p<1><<<dim3(KVDIM / 128, MROWS / 128), blk, G2SMEM>>>(
        x16h, x16l, wk16, k16, nullptr, cosb, sinb, KVDIM, DIMM);
    gemm2p<2><<<dim3(KVDIM / 128, MROWS / 128), blk, G2SMEM>>>(
        x16h, x16l, wv16, v16, nullptr, cosb, sinb, KVDIM, DIMM);

    // attention (Q hi/lo, K/V fp16) -> fp16 o16
    attn_mma<<<dim3(NSEQ / 128, BATCH * NHEAD), blk, ASMEM>>>(q16h, q16l, k16, v16, o16);

    // output projection: single-pass fp16
    gemm1p<<<dim3(DIMM / 128, MROWS / 128), blk, G1SMEM>>>(o16, wo16, out, DIMM, DIMM);
}

// round 9
// speedup vs baseline: 10.8892x; 1.2676x over previous
#include <cuda_runtime.h>
#include <cuda_fp16.h>
#include <cstdint>

// ---------------- constants ----------------
#define BATCH   2
#define NSEQ    2048
#define DIMM    4096
#define NHEAD   32
#define NKV     8
#define HDIM    128
#define MROWS   (BATCH*NSEQ)            // 4096
#define KVDIM   (NKV*HDIM)              // 1024
#define ATT_SCALE 0.08838834764831845f  // 1/sqrt(128)

// ---------------- scratch (device globals; no allocations allowed) ----------------
__device__ __half g_x16h[MROWS * DIMM], g_x16l[MROWS * DIMM];
__device__ __half g_wq16[DIMM * DIMM];
__device__ __half g_wk16[KVDIM * DIMM];
__device__ __half g_wv16[KVDIM * DIMM];
__device__ __half g_wo16[DIMM * DIMM];

__device__ __half g_q16h[MROWS * DIMM], g_q16l[MROWS * DIMM];  // roped+scaled Q hi/lo
__device__ __half g_k16[MROWS * KVDIM];                        // roped K
__device__ __half g_v16[MROWS * KVDIM];
__device__ __half g_o16[MROWS * DIMM];

// ---------------- PTX helpers (plain sm_80+ PTX) ----------------
__device__ __forceinline__ uint32_t s2u32(const void* p) {
    uint32_t a;
    asm("{ .reg .u64 t; cvta.to.shared.u64 t, %1; cvt.u32.u64 %0, t; }" : "=r"(a) : "l"(p));
    return a;
}
__device__ __forceinline__ void cp16(uint32_t d, const void* s) {
    asm volatile("cp.async.cg.shared.global [%0], [%1], 16;" :: "r"(d), "l"(s));
}
__device__ __forceinline__ void cp_commit() {
    asm volatile("cp.async.commit_group;" ::: "memory");
}
template <int N>
__device__ __forceinline__ void cp_wait() {
    asm volatile("cp.async.wait_group %0;" :: "n"(N) : "memory");
}
__device__ __forceinline__ void ldsm4(uint32_t& r0, uint32_t& r1, uint32_t& r2,
                                      uint32_t& r3, uint32_t addr) {
    asm volatile("ldmatrix.sync.aligned.m8n8.x4.shared.b16 {%0,%1,%2,%3}, [%4];"
                 : "=r"(r0), "=r"(r1), "=r"(r2), "=r"(r3) : "r"(addr));
}
__device__ __forceinline__ void ldsm4t(uint32_t& r0, uint32_t& r1, uint32_t& r2,
                                       uint32_t& r3, uint32_t addr) {
    asm volatile("ldmatrix.sync.aligned.m8n8.x4.trans.shared.b16 {%0,%1,%2,%3}, [%4];"
                 : "=r"(r0), "=r"(r1), "=r"(r2), "=r"(r3) : "r"(addr));
}
__device__ __forceinline__ void mma16816f(float* c, const uint32_t* a, uint32_t b0, uint32_t b1) {
    asm volatile(
        "mma.sync.aligned.m16n8k16.row.col.f32.f16.f16.f32 "
        "{%0,%1,%2,%3}, {%4,%5,%6,%7}, {%8,%9}, {%0,%1,%2,%3};"
        : "+f"(c[0]), "+f"(c[1]), "+f"(c[2]), "+f"(c[3])
        : "r"(a[0]), "r"(a[1]), "r"(a[2]), "r"(a[3]), "r"(b0), "r"(b1));
}
__device__ __forceinline__ uint32_t packh2(float x, float y) {
    __half2 h = __floats2half2_rn(x, y);
    return *(uint32_t*)&h;
}

// ---------------- hi/lo split: fp32 -> fp16 pair ----------------
__global__ __launch_bounds__(256) void splitf16_kernel(
    const float* __restrict__ src, __half* __restrict__ hi,
    __half* __restrict__ lo, int n4)
{
    int i = blockIdx.x * blockDim.x + threadIdx.x;
    if (i >= n4) return;
    float4 v = ((const float4*)src)[i];
    __half h0 = __float2half_rn(v.x), h1 = __float2half_rn(v.y);
    __half h2 = __float2half_rn(v.z), h3 = __float2half_rn(v.w);
    __half l0 = __float2half_rn(v.x - __half2float(h0));
    __half l1 = __float2half_rn(v.y - __half2float(h1));
    __half l2 = __float2half_rn(v.z - __half2float(h2));
    __half l3 = __float2half_rn(v.w - __half2float(h3));
    ((__half2*)hi)[2 * i]     = __halves2half2(h0, h1);
    ((__half2*)hi)[2 * i + 1] = __halves2half2(h2, h3);
    ((__half2*)lo)[2 * i]     = __halves2half2(l0, l1);
    ((__half2*)lo)[2 * i + 1] = __halves2half2(l2, l3);
}

// ---------------- fp32 -> fp16 convert ----------------
__global__ __launch_bounds__(256) void cvt16_kernel(
    const float* __restrict__ src, __half* __restrict__ dst, int n4)
{
    int i = blockIdx.x * blockDim.x + threadIdx.x;
    if (i >= n4) return;
    float4 v = ((const float4*)src)[i];
    ((__half2*)dst)[2 * i]     = __floats2half2_rn(v.x, v.y);
    ((__half2*)dst)[2 * i + 1] = __floats2half2_rn(v.z, v.w);
}

// =====================================================================
// GEMM: C[M,N] = A[M,K] * B[N,K]^T, fp16 in, fp32 accum.
// CTA 128x128, BK=32, 256 thr (8 warps, warp tile 32x64), 3-stage cp.async,
// single __syncthreads per iteration.
// =====================================================================
#define TILE80 (128 * 80)

// shared fused epilogue:
//  EPI 0: rope + ATT_SCALE + hi/lo fp16 split -> Ch, Cl   (Q)
//  EPI 1: rope + fp16 -> Ch                                (K)
//  EPI 2: fp16 -> Ch                                       (V)
template <int EPI>
__device__ __forceinline__ void epilogue16(
    float acc[2][8][4], __half* Ch, __half* Cl,
    const float* cosb, const float* sinb,
    int bm, int bn, int wm, int wn, int lane, int N)
{
#pragma unroll
    for (int mt = 0; mt < 2; mt++) {
        int r0 = bm + wm + mt * 16 + (lane >> 2);
        int n0 = r0 & (NSEQ - 1);
#pragma unroll
        for (int nt = 0; nt < 8; nt++) {
            int c0 = bn + wn + nt * 8 + (lane & 3) * 2;
            float* p = acc[mt][nt];
            float p0 = p[0], p1 = p[1], p2 = p[2], p3 = p[3];
            if (EPI <= 1) {
                int j = (c0 & (HDIM - 1)) >> 1;
                float ca = cosb[n0 * 64 + j],       sa = sinb[n0 * 64 + j];
                float cb = cosb[(n0 + 8) * 64 + j], sb = sinb[(n0 + 8) * 64 + j];
                float t0 = p0 * ca - p1 * sa, t1 = p0 * sa + p1 * ca;
                float t2 = p2 * cb - p3 * sb, t3 = p2 * sb + p3 * cb;
                p0 = t0; p1 = t1; p2 = t2; p3 = t3;
            }
            if (EPI == 0) {
                p0 *= ATT_SCALE; p1 *= ATT_SCALE; p2 *= ATT_SCALE; p3 *= ATT_SCALE;
                __half h0 = __float2half_rn(p0), h1 = __float2half_rn(p1);
                __half h2 = __float2half_rn(p2), h3 = __float2half_rn(p3);
                *(__half2*)&Ch[(size_t)r0 * N + c0]       = __halves2half2(h0, h1);
                *(__half2*)&Ch[(size_t)(r0 + 8) * N + c0] = __halves2half2(h2, h3);
                *(__half2*)&Cl[(size_t)r0 * N + c0] = __halves2half2(
                    __float2half_rn(p0 - __half2float(h0)),
                    __float2half_rn(p1 - __half2float(h1)));
                *(__half2*)&Cl[(size_t)(r0 + 8) * N + c0] = __halves2half2(
                    __float2half_rn(p2 - __half2float(h2)),
                    __float2half_rn(p3 - __half2float(h3)));
            } else {
                *(__half2*)&Ch[(size_t)r0 * N + c0]       = __floats2half2_rn(p0, p1);
                *(__half2*)&Ch[(size_t)(r0 + 8) * N + c0] = __floats2half2_rn(p2, p3);
            }
        }
    }
}

// ---------------- 2-pass (A hi/lo, B single): K projection ----------------
#define G2STAGE (3 * TILE80)
#define G2SMEM  (3 * G2STAGE)
template <int EPI>
__global__ __launch_bounds__(256) void gemm2p(
    const __half* __restrict__ Ah, const __half* __restrict__ Al,
    const __half* __restrict__ B, __half* __restrict__ Ch, __half* __restrict__ Cl,
    const float* __restrict__ cosb, const float* __restrict__ sinb, int N, int K)
{
    extern __shared__ char smraw[];
    const uint32_t sbase = s2u32(smraw);
    const int tid  = threadIdx.x;
    const int wid  = tid >> 5;
    const int lane = tid & 31;
    const int bm = blockIdx.y << 7, bn = blockIdx.x << 7;
    const int wm = (wid & 3) * 32;
    const int wn = (wid >> 2) * 64;
    const int NCH = K >> 5;

    float acc[2][8][4];
#pragma unroll
    for (int i = 0; i < 2; i++)
#pragma unroll
        for (int j = 0; j < 8; j++)
#pragma unroll
            for (int t = 0; t < 4; t++) acc[i][j][t] = 0.0f;

    const __half* tsrc[3] = {Ah, Al, B};

    auto load_stage = [&](int ch, int st) {
        const int k0 = ch << 5;
        const uint32_t stb = sbase + st * G2STAGE;
#pragma unroll
        for (int i = 0; i < 6; i++) {
            int f = i * 256 + tid;
            int tile = f >> 9;
            int c = f & 511;
            int row = c >> 2, c4 = c & 3;
            const __half* g = tsrc[tile];
            int rb = (tile < 2) ? bm : bn;
            cp16(stb + tile * TILE80 + row * 80 + c4 * 16,
                 g + (size_t)(rb + row) * K + k0 + c4 * 8);
        }
    };

    uint32_t offA[2], offB[4];
#pragma unroll
    for (int mt = 0; mt < 2; mt++)
        offA[mt] = (uint32_t)((wm + mt * 16 + (lane & 15)) * 80 + (lane >> 4) * 16);
#pragma unroll
    for (int nb = 0; nb < 4; nb++)
        offB[nb] = (uint32_t)((wn + nb * 16 + (lane & 15)) * 80 + (lane >> 4) * 16);

    load_stage(0, 0); cp_commit();
    load_stage(1, 1); cp_commit();

    for (int it = 0; it < NCH; ++it) {
        if (it + 1 < NCH) cp_wait<1>(); else cp_wait<0>();
        __syncthreads();
        if (it + 2 < NCH) { load_stage(it + 2, (it + 2) % 3); cp_commit(); }

        const uint32_t bAh = sbase + (it % 3) * G2STAGE;
        const uint32_t bAl = bAh + TILE80;
        const uint32_t bB  = bAh + 2 * TILE80;

#pragma unroll
        for (int kk = 0; kk < 2; kk++) {
            const uint32_t ks = kk * 32;
            uint32_t ah[2][4], al[2][4], bfr[4][4];
#pragma unroll
            for (int mt = 0; mt < 2; mt++) {
                ldsm4(ah[mt][0], ah[mt][1], ah[mt][2], ah[mt][3], bAh + offA[mt] + ks);
                ldsm4(al[mt][0], al[mt][1], al[mt][2], al[mt][3], bAl + offA[mt] + ks);
            }
#pragma unroll
            for (int nb = 0; nb < 4; nb++)
                ldsm4(bfr[nb][0], bfr[nb][1], bfr[nb][2], bfr[nb][3], bB + offB[nb] + ks);
#pragma unroll
            for (int mt = 0; mt < 2; mt++)
#pragma unroll
                for (int nb = 0; nb < 4; nb++)
#pragma unroll
                    for (int hf = 0; hf < 2; hf++) {
                        float* c = acc[mt][nb * 2 + hf];
                        mma16816f(c, ah[mt], bfr[nb][hf], bfr[nb][hf + 2]);
                        mma16816f(c, al[mt], bfr[nb][hf], bfr[nb][hf + 2]);
                    }
        }
    }

    epilogue16<EPI>(acc, Ch, Cl, cosb, sinb, bm, bn, wm, wn, lane, N);
}

// ---------------- 1-pass with fused epilogue: Q / V projections ----------------
#define G1STAGE (2 * TILE80)
#define G1SMEM  (3 * G1STAGE)
template <int EPI>
__global__ __launch_bounds__(256) void gemm1pe(
    const __half* __restrict__ A, const __half* __restrict__ B,
    __half* __restrict__ Ch, __half* __restrict__ Cl,
    const float* __restrict__ cosb, const float* __restrict__ sinb, int N, int K)
{
    extern __shared__ char smraw[];
    const uint32_t sbase = s2u32(smraw);
    const int tid  = threadIdx.x;
    const int wid  = tid >> 5;
    const int lane = tid & 31;
    const int bm = blockIdx.y << 7, bn = blockIdx.x << 7;
    const int wm = (wid & 3) * 32;
    const int wn = (wid >> 2) * 64;
    const int NCH = K >> 5;

    float acc[2][8][4];
#pragma unroll
    for (int i = 0; i < 2; i++)
#pragma unroll
        for (int j = 0; j < 8; j++)
#pragma unroll
            for (int t = 0; t < 4; t++) acc[i][j][t] = 0.0f;

    auto load_stage = [&](int ch, int st) {
        const int k0 = ch << 5;
        const uint32_t stb = sbase + st * G1STAGE;
#pragma unroll
        for (int i = 0; i < 4; i++) {
            int f = i * 256 + tid;
            int tile = f >> 9;
            int c = f & 511;
            int row = c >> 2, c4 = c & 3;
            const __half* g = tile ? B : A;
            int rb = tile ? bn : bm;
            cp16(stb + tile * TILE80 + row * 80 + c4 * 16,
                 g + (size_t)(rb + row) * K + k0 + c4 * 8);
        }
    };

    uint32_t offA[2], offB[4];
#pragma unroll
    for (int mt = 0; mt < 2; mt++)
        offA[mt] = (uint32_t)((wm + mt * 16 + (lane & 15)) * 80 + (lane >> 4) * 16);
#pragma unroll
    for (int nb = 0; nb < 4; nb++)
        offB[nb] = (uint32_t)((wn + nb * 16 + (lane & 15)) * 80 + (lane >> 4) * 16);

    load_stage(0, 0); cp_commit();
    load_stage(1, 1); cp_commit();

    for (int it = 0; it < NCH; ++it) {
        if (it + 1 < NCH) cp_wait<1>(); else cp_wait<0>();
        __syncthreads();
        if (it + 2 < NCH) { load_stage(it + 2, (it + 2) % 3); cp_commit(); }

        const uint32_t bA = sbase + (it % 3) * G1STAGE;
        const uint32_t bB = bA + TILE80;

#pragma unroll
        for (int kk = 0; kk < 2; kk++) {
            const uint32_t ks = kk * 32;
            uint32_t a[2][4], bfr[4][4];
#pragma unroll
            for (int mt = 0; mt < 2; mt++)
                ldsm4(a[mt][0], a[mt][1], a[mt][2], a[mt][3], bA + offA[mt] + ks);
#pragma unroll
            for (int nb = 0; nb < 4; nb++)
                ldsm4(bfr[nb][0], bfr[nb][1], bfr[nb][2], bfr[nb][3], bB + offB[nb] + ks);
#pragma unroll
            for (int mt = 0; mt < 2; mt++)
#pragma unroll
                for (int nb = 0; nb < 4; nb++)
#pragma unroll
                    for (int hf = 0; hf < 2; hf++)
                        mma16816f(acc[mt][nb * 2 + hf], a[mt],
                                  bfr[nb][hf], bfr[nb][hf + 2]);
        }
    }

    epilogue16<EPI>(acc, Ch, Cl, cosb, sinb, bm, bn, wm, wn, lane, N);
}

// ---------------- 1-pass fp16 -> fp32 out: O projection ----------------
__global__ __launch_bounds__(256) void gemm1p(
    const __half* __restrict__ A, const __half* __restrict__ B,
    float* __restrict__ C, int N, int K)
{
    extern __shared__ char smraw[];
    const uint32_t sbase = s2u32(smraw);
    const int tid  = threadIdx.x;
    const int wid  = tid >> 5;
    const int lane = tid & 31;
    const int bm = blockIdx.y << 7, bn = blockIdx.x << 7;
    const int wm = (wid & 3) * 32;
    const int wn = (wid >> 2) * 64;
    const int NCH = K >> 5;

    float acc[2][8][4];
#pragma unroll
    for (int i = 0; i < 2; i++)
#pragma unroll
        for (int j = 0; j < 8; j++)
#pragma unroll
            for (int t = 0; t < 4; t++) acc[i][j][t] = 0.0f;

    auto load_stage = [&](int ch, int st) {
        const int k0 = ch << 5;
        const uint32_t stb = sbase + st * G1STAGE;
#pragma unroll
        for (int i = 0; i < 4; i++) {
            int f = i * 256 + tid;
            int tile = f >> 9;
            int c = f & 511;
            int row = c >> 2, c4 = c & 3;
            const __half* g = tile ? B : A;
            int rb = tile ? bn : bm;
            cp16(stb + tile * TILE80 + row * 80 + c4 * 16,
                 g + (size_t)(rb + row) * K + k0 + c4 * 8);
        }
    };

    uint32_t offA[2], offB[4];
#pragma unroll
    for (int mt = 0; mt < 2; mt++)
        offA[mt] = (uint32_t)((wm + mt * 16 + (lane & 15)) * 80 + (lane >> 4) * 16);
#pragma unroll
    for (int nb = 0; nb < 4; nb++)
        offB[nb] = (uint32_t)((wn + nb * 16 + (lane & 15)) * 80 + (lane >> 4) * 16);

    load_stage(0, 0); cp_commit();
    load_stage(1, 1); cp_commit();

    for (int it = 0; it < NCH; ++it) {
        if (it + 1 < NCH) cp_wait<1>(); else cp_wait<0>();
        __syncthreads();
        if (it + 2 < NCH) { load_stage(it + 2, (it + 2) % 3); cp_commit(); }

        const uint32_t bA = sbase + (it % 3) * G1STAGE;
        const uint32_t bB = bA + TILE80;

#pragma unroll
        for (int kk = 0; kk < 2; kk++) {
            const uint32_t ks = kk * 32;
            uint32_t a[2][4], bfr[4][4];
#pragma unroll
            for (int mt = 0; mt < 2; mt++)
                ldsm4(a[mt][0], a[mt][1], a[mt][2], a[mt][3], bA + offA[mt] + ks);
#pragma unroll
            for (int nb = 0; nb < 4; nb++)
                ldsm4(bfr[nb][0], bfr[nb][1], bfr[nb][2], bfr[nb][3], bB + offB[nb] + ks);
#pragma unroll
            for (int mt = 0; mt < 2; mt++)
#pragma unroll
                for (int nb = 0; nb < 4; nb++)
#pragma unroll
                    for (int hf = 0; hf < 2; hf++)
                        mma16816f(acc[mt][nb * 2 + hf], a[mt],
                                  bfr[nb][hf], bfr[nb][hf + 2]);
        }
    }

#pragma unroll
    for (int mt = 0; mt < 2; mt++) {
        int r0 = bm + wm + mt * 16 + (lane >> 2);
#pragma unroll
        for (int nt = 0; nt < 8; nt++) {
            int c0 = bn + wn + nt * 8 + (lane & 3) * 2;
            float* p = acc[mt][nt];
            *(float2*)&C[(size_t)r0 * N + c0]       = make_float2(p[0], p[1]);
            *(float2*)&C[(size_t)(r0 + 8) * N + c0] = make_float2(p[2], p[3]);
        }
    }
}

// ---------------- flash attention via mma.sync ----------------
// 128 q-rows/CTA, 8 warps x 16 rows, 64-key tiles double buffered.
// S: Q hi/lo 2-pass vs K fp16; PV: fp16 single pass. fp32 softmax/accum.
#define APITCH  272
#define QS_BYTES (128 * APITCH)
#define KVTILE   (64 * APITCH)
#define STG      (2 * KVTILE)
#define ASMEM    (2 * QS_BYTES + 2 * STG)
__global__ __launch_bounds__(256) void attn_mma(
    const __half* __restrict__ Qh, const __half* __restrict__ Ql,
    const __half* __restrict__ Kk, const __half* __restrict__ V,
    __half* __restrict__ O16)
{
    extern __shared__ char smraw[];
    const uint32_t sb = s2u32(smraw);
    const uint32_t qh_s = sb;
    const uint32_t ql_s = sb + QS_BYTES;
    const uint32_t kvb  = sb + 2 * QS_BYTES;

    const int tid = threadIdx.x;
    const int wid = tid >> 5, lane = tid & 31;
    const int qt = blockIdx.x;
    const int bh = blockIdx.y;
    const int b = bh >> 5, h = bh & 31;
    const int kvh = h >> 2;

    {
        const size_t qrow0 = (size_t)(b * NSEQ + qt * 128) * DIMM + h * HDIM;
#pragma unroll
        for (int i = 0; i < 16; i++) {
            int f = i * 256 + tid;
            int tile = f >> 11;
            int c = f & 2047;
            int row = c >> 4, ch = c & 15;
            const __half* src = (tile ? Ql : Qh) + qrow0 + (size_t)row * DIMM + ch * 8;
            cp16((tile ? ql_s : qh_s) + row * APITCH + ch * 16, src);
        }
    }

    auto load_kv = [&](int kt, int st) {
        const uint32_t stb = kvb + st * STG;
        const size_t row0 = (size_t)(b * NSEQ + kt * 64) * KVDIM + kvh * HDIM;
#pragma unroll
        for (int i = 0; i < 8; i++) {
            int f = i * 256 + tid;
            int tile = f >> 10;
            int c = f & 1023;
            int row = c >> 4, ch = c & 15;
            const __half* src = (tile ? V : Kk) + row0 + (size_t)row * KVDIM + ch * 8;
            cp16(stb + tile * KVTILE + row * APITCH + ch * 16, src);
        }
    };

    float o[16][4];
#pragma unroll
    for (int t = 0; t < 16; t++)
#pragma unroll
        for (int r = 0; r < 4; r++) o[t][r] = 0.0f;
    float m0 = -1e30f, m1 = -1e30f, l0 = 0.0f, l1 = 0.0f;

    const int NIT = 2 * qt + 2;
    load_kv(0, 0); cp_commit();

    const int rowA = qt * 128 + wid * 16 + (lane >> 2);
    const uint32_t aoff = (uint32_t)((wid * 16 + (lane & 15)) * APITCH + (lane >> 4) * 16);

    for (int it = 0; it < NIT; it++) {
        const int st = it & 1;
        cp_wait<0>();
        __syncthreads();
        if (it + 1 < NIT) { load_kv(it + 1, st ^ 1); cp_commit(); }

        const uint32_t k_t = kvb + st * STG;
        const uint32_t v_t = k_t + KVTILE;

        float s[8][4];
#pragma unroll
        for (int t = 0; t < 8; t++)
#pragma unroll
            for (int r = 0; r < 4; r++) s[t][r] = 0.0f;

#pragma unroll
        for (int kki = 0; kki < 8; kki++) {
            uint32_t ah[4], al[4];
            ldsm4(ah[0], ah[1], ah[2], ah[3], qh_s + aoff + kki * 32);
            ldsm4(al[0], al[1], al[2], al[3], ql_s + aoff + kki * 32);
#pragma unroll
            for (int g = 0; g < 4; g++) {
                uint32_t boff = (uint32_t)((16 * g + (lane & 15)) * APITCH
                                           + (kki * 2 + (lane >> 4)) * 16);
                uint32_t b0, b1, b2, b3;
                ldsm4(b0, b1, b2, b3, k_t + boff);
                mma16816f(s[2 * g],     ah, b0, b2);
                mma16816f(s[2 * g],     al, b0, b2);
                mma16816f(s[2 * g + 1], ah, b1, b3);
                mma16816f(s[2 * g + 1], al, b1, b3);
            }
        }

        if (it >= 2 * qt) {
            const int kbase = it * 64 + (lane & 3) * 2;
#pragma unroll
            for (int t = 0; t < 8; t++) {
                int k0 = kbase + t * 8;
                if (k0     > rowA)     s[t][0] = -1e30f;
                if (k0 + 1 > rowA)     s[t][1] = -1e30f;
                if (k0     > rowA + 8) s[t][2] = -1e30f;
                if (k0 + 1 > rowA + 8) s[t][3] = -1e30f;
            }
        }

        float mxA = m0, mxB = m1;
#pragma unroll
        for (int t = 0; t < 8; t++) {
            mxA = fmaxf(mxA, fmaxf(s[t][0], s[t][1]));
            mxB = fmaxf(mxB, fmaxf(s[t][2], s[t][3]));
        }
        mxA = fmaxf(mxA, __shfl_xor_sync(0xFFFFFFFFu, mxA, 1));
        mxA = fmaxf(mxA, __shfl_xor_sync(0xFFFFFFFFu, mxA, 2));
        mxB = fmaxf(mxB, __shfl_xor_sync(0xFFFFFFFFu, mxB, 1));
        mxB = fmaxf(mxB, __shfl_xor_sync(0xFFFFFFFFu, mxB, 2));

        float aA = __expf(m0 - mxA), aB = __expf(m1 - mxB);
        float sA = 0.0f, sB = 0.0f;
#pragma unroll
        for (int t = 0; t < 8; t++) {
            s[t][0] = __expf(s[t][0] - mxA);
            s[t][1] = __expf(s[t][1] - mxA);
            s[t][2] = __expf(s[t][2] - mxB);
            s[t][3] = __expf(s[t][3] - mxB);
            sA += s[t][0] + s[t][1];
            sB += s[t][2] + s[t][3];
        }
        sA += __shfl_xor_sync(0xFFFFFFFFu, sA, 1);
        sA += __shfl_xor_sync(0xFFFFFFFFu, sA, 2);
        sB += __shfl_xor_sync(0xFFFFFFFFu, sB, 1);
        sB += __shfl_xor_sync(0xFFFFFFFFu, sB, 2);
        l0 = l0 * aA + sA;  l1 = l1 * aB + sB;
        m0 = mxA;           m1 = mxB;

#pragma unroll
        for (int t = 0; t < 16; t++) {
            o[t][0] *= aA; o[t][1] *= aA;
            o[t][2] *= aB; o[t][3] *= aB;
        }

        uint32_t ap[4][4];
#pragma unroll
        for (int kk = 0; kk < 4; kk++) {
            ap[kk][0] = packh2(s[2 * kk][0],     s[2 * kk][1]);
            ap[kk][1] = packh2(s[2 * kk][2],     s[2 * kk][3]);
            ap[kk][2] = packh2(s[2 * kk + 1][0], s[2 * kk + 1][1]);
            ap[kk][3] = packh2(s[2 * kk + 1][2], s[2 * kk + 1][3]);
        }
        const uint32_t vrow = (uint32_t)((((lane >> 3) & 1) * 8 + (lane & 7)) * APITCH
                                         + (lane >> 4) * 16);
#pragma unroll
        for (int kk = 0; kk < 4; kk++) {
#pragma unroll
            for (int g = 0; g < 8; g++) {
                uint32_t v0, v1, v2, v3;
                ldsm4t(v0, v1, v2, v3, v_t + vrow + (uint32_t)(16 * kk * APITCH + g * 32));
                mma16816f(o[2 * g],     ap[kk], v0, v1);
                mma16816f(o[2 * g + 1], ap[kk], v2, v3);
            }
        }
    }

    const float iA = 1.0f / l0, iB = 1.0f / l1;
    __half* obase = O16 + ((size_t)(b * NSEQ) * NHEAD + h) * HDIM;
#pragma unroll
    for (int t = 0; t < 16; t++) {
        int d = t * 8 + (lane & 3) * 2;
        *(__half2*)(obase + (size_t)rowA * (NHEAD * HDIM) + d) =
            __floats2half2_rn(o[t][0] * iA, o[t][1] * iA);
        *(__half2*)(obase + (size_t)(rowA + 8) * (NHEAD * HDIM) + d) =
            __floats2half2_rn(o[t][2] * iB, o[t][3] * iB);
    }
}

// ---------------- launch ----------------
extern "C" void kernel_launch(void* const* d_in, const int* in_sizes, int n_in,
                              void* d_out, int out_size)
{
    const float* x    = (const float*)d_in[0];
    const float* wq   = (const float*)d_in[1];
    const float* wk   = (const float*)d_in[2];
    const float* wv   = (const float*)d_in[3];
    const float* wo   = (const float*)d_in[4];
    const float* cosb = (const float*)d_in[5];
    const float* sinb = (const float*)d_in[6];
    float* out = (float*)d_out;

    __half *x16h, *x16l, *wq16, *wk16, *wv16, *wo16;
    cudaGetSymbolAddress((void**)&x16h, g_x16h);
    cudaGetSymbolAddress((void**)&x16l, g_x16l);
    cudaGetSymbolAddress((void**)&wq16, g_wq16);
    cudaGetSymbolAddress((void**)&wk16, g_wk16);
    cudaGetSymbolAddress((void**)&wv16, g_wv16);
    cudaGetSymbolAddress((void**)&wo16, g_wo16);
    __half *q16h, *q16l, *k16, *v16, *o16;
    cudaGetSymbolAddress((void**)&q16h, g_q16h);
    cudaGetSymbolAddress((void**)&q16l, g_q16l);
    cudaGetSymbolAddress((void**)&k16,  g_k16);
    cudaGetSymbolAddress((void**)&v16,  g_v16);
    cudaGetSymbolAddress((void**)&o16,  g_o16);

    cudaFuncSetAttribute(gemm2p<1>, cudaFuncAttributeMaxDynamicSharedMemorySize, G2SMEM);
    cudaFuncSetAttribute(gemm1pe<0>, cudaFuncAttributeMaxDynamicSharedMemorySize, G1SMEM);
    cudaFuncSetAttribute(gemm1pe<2>, cudaFuncAttributeMaxDynamicSharedMemorySize, G1SMEM);
    cudaFuncSetAttribute(gemm1p, cudaFuncAttributeMaxDynamicSharedMemorySize, G1SMEM);
    cudaFuncSetAttribute(attn_mma, cudaFuncAttributeMaxDynamicSharedMemorySize, ASMEM);

    dim3 blk(256);

    // input conversions (x split still feeds K 2-pass)
    splitf16_kernel<<<(MROWS * DIMM / 4 + 255) / 256, blk>>>(x, x16h, x16l, MROWS * DIMM / 4);
    cvt16_kernel<<<(DIMM * DIMM / 4 + 255) / 256, blk>>>(wq, wq16, DIMM * DIMM / 4);
    cvt16_kernel<<<(KVDIM * DIMM / 4 + 255) / 256, blk>>>(wk, wk16, KVDIM * DIMM / 4);
    cvt16_kernel<<<(KVDIM * DIMM / 4 + 255) / 256, blk>>>(wv, wv16, KVDIM * DIMM / 4);
    cvt16_kernel<<<(DIMM * DIMM / 4 + 255) / 256, blk>>>(wo, wo16, DIMM * DIMM / 4);

    // projections: Q 1-pass (rope+scale+hi/lo), K 2-pass (rope), V 1-pass
    gemm1pe<0><<<dim3(DIMM / 128, MROWS / 128), blk, G1SMEM>>>(
        x16h, wq16, q16h, q16l, cosb, sinb, DIMM, DIMM);
    gemm2p<1><<<dim3(KVDIM / 128, MROWS / 128), blk, G2SMEM>>>(
        x16h, x16l, wk16, k16, nullptr, cosb, sinb, KVDIM, DIMM);
    gemm1pe<2><<<dim3(KVDIM / 128, MROWS / 128), blk, G1SMEM>>>(
        x16h, wv16, v16, nullptr, cosb, sinb, KVDIM, DIMM);

    // attention (Q hi/lo, K/V fp16) -> fp16 o16
    attn_mma<<<dim3(NSEQ / 128, BATCH * NHEAD), blk, ASMEM>>>(q16h, q16l, k16, v16, o16);

    // output projection: single-pass fp16
    gemm1p<<<dim3(DIMM / 128, MROWS / 128), blk, G1SMEM>>>(o16, wo16, out, DIMM, DIMM);
}

// round 10
// speedup vs baseline: 11.8018x; 1.0838x over previous
#include <cuda_runtime.h>
#include <cuda_fp16.h>
#include <cstdint>

// ---------------- constants ----------------
#define BATCH   2
#define NSEQ    2048
#define DIMM    4096
#define NHEAD   32
#define NKV     8
#define HDIM    128
#define MROWS   (BATCH*NSEQ)            // 4096
#define KVDIM   (NKV*HDIM)              // 1024
#define ATT_SCALE 0.08838834764831845f  // 1/sqrt(128)

// ---------------- scratch (device globals; no allocations allowed) ----------------
__device__ __half g_x16h[MROWS * DIMM], g_x16l[MROWS * DIMM];
__device__ __half g_wq16[DIMM * DIMM];
__device__ __half g_wk16[KVDIM * DIMM];
__device__ __half g_wv16[KVDIM * DIMM];
__device__ __half g_wo16[DIMM * DIMM];

__device__ __half g_q16h[MROWS * DIMM], g_q16l[MROWS * DIMM];  // roped+scaled Q hi/lo
__device__ __half g_k16[MROWS * KVDIM];                        // roped K
__device__ __half g_v16[MROWS * KVDIM];
__device__ __half g_o16[MROWS * DIMM];

// ---------------- PTX helpers (plain sm_80+ PTX) ----------------
__device__ __forceinline__ uint32_t s2u32(const void* p) {
    uint32_t a;
    asm("{ .reg .u64 t; cvta.to.shared.u64 t, %1; cvt.u32.u64 %0, t; }" : "=r"(a) : "l"(p));
    return a;
}
__device__ __forceinline__ void cp16(uint32_t d, const void* s) {
    asm volatile("cp.async.cg.shared.global [%0], [%1], 16;" :: "r"(d), "l"(s));
}
__device__ __forceinline__ void cp_commit() {
    asm volatile("cp.async.commit_group;" ::: "memory");
}
template <int N>
__device__ __forceinline__ void cp_wait() {
    asm volatile("cp.async.wait_group %0;" :: "n"(N) : "memory");
}
__device__ __forceinline__ void ldsm4(uint32_t& r0, uint32_t& r1, uint32_t& r2,
                                      uint32_t& r3, uint32_t addr) {
    asm volatile("ldmatrix.sync.aligned.m8n8.x4.shared.b16 {%0,%1,%2,%3}, [%4];"
                 : "=r"(r0), "=r"(r1), "=r"(r2), "=r"(r3) : "r"(addr));
}
__device__ __forceinline__ void ldsm4t(uint32_t& r0, uint32_t& r1, uint32_t& r2,
                                       uint32_t& r3, uint32_t addr) {
    asm volatile("ldmatrix.sync.aligned.m8n8.x4.trans.shared.b16 {%0,%1,%2,%3}, [%4];"
                 : "=r"(r0), "=r"(r1), "=r"(r2), "=r"(r3) : "r"(addr));
}
__device__ __forceinline__ void mma16816f(float* c, const uint32_t* a, uint32_t b0, uint32_t b1) {
    asm volatile(
        "mma.sync.aligned.m16n8k16.row.col.f32.f16.f16.f32 "
        "{%0,%1,%2,%3}, {%4,%5,%6,%7}, {%8,%9}, {%0,%1,%2,%3};"
        : "+f"(c[0]), "+f"(c[1]), "+f"(c[2]), "+f"(c[3])
        : "r"(a[0]), "r"(a[1]), "r"(a[2]), "r"(a[3]), "r"(b0), "r"(b1));
}
__device__ __forceinline__ uint32_t packh2(float x, float y) {
    __half2 h = __floats2half2_rn(x, y);
    return *(uint32_t*)&h;
}

// ---------------- hi/lo split: fp32 -> fp16 pair ----------------
__global__ __launch_bounds__(256) void splitf16_kernel(
    const float* __restrict__ src, __half* __restrict__ hi,
    __half* __restrict__ lo, int n4)
{
    int i = blockIdx.x * blockDim.x + threadIdx.x;
    if (i >= n4) return;
    float4 v = ((const float4*)src)[i];
    __half h0 = __float2half_rn(v.x), h1 = __float2half_rn(v.y);
    __half h2 = __float2half_rn(v.z), h3 = __float2half_rn(v.w);
    __half l0 = __float2half_rn(v.x - __half2float(h0));
    __half l1 = __float2half_rn(v.y - __half2float(h1));
    __half l2 = __float2half_rn(v.z - __half2float(h2));
    __half l3 = __float2half_rn(v.w - __half2float(h3));
    ((__half2*)hi)[2 * i]     = __halves2half2(h0, h1);
    ((__half2*)hi)[2 * i + 1] = __halves2half2(h2, h3);
    ((__half2*)lo)[2 * i]     = __halves2half2(l0, l1);
    ((__half2*)lo)[2 * i + 1] = __halves2half2(l2, l3);
}

// ---------------- fp32 -> fp16 convert ----------------
__global__ __launch_bounds__(256) void cvt16_kernel(
    const float* __restrict__ src, __half* __restrict__ dst, int n4)
{
    int i = blockIdx.x * blockDim.x + threadIdx.x;
    if (i >= n4) return;
    float4 v = ((const float4*)src)[i];
    ((__half2*)dst)[2 * i]     = __floats2half2_rn(v.x, v.y);
    ((__half2*)dst)[2 * i + 1] = __floats2half2_rn(v.z, v.w);
}

// =====================================================================
// GEMM: C[M,N] = A[M,K] * B[N,K]^T, fp16 in, fp32 accum.
// CTA 128x128, BK=64, 256 thr (8 warps, warp tile 32x64), 3-stage cp.async,
// single __syncthreads per iteration.
// Tile pitch 144B (64 fp16 + 16B pad) -> conflict-free ldmatrix.
// =====================================================================
#define TILE144 (128 * 144)          // 18432 B: one 128x64-fp16 tile

// shared fused epilogue:
//  EPI 0: rope + ATT_SCALE + hi/lo fp16 split -> Ch, Cl   (Q)
//  EPI 1: rope + fp16 -> Ch                                (K)
//  EPI 2: fp16 -> Ch                                       (V)
template <int EPI>
__device__ __forceinline__ void epilogue16(
    float acc[2][8][4], __half* Ch, __half* Cl,
    const float* cosb, const float* sinb,
    int bm, int bn, int wm, int wn, int lane, int N)
{
#pragma unroll
    for (int mt = 0; mt < 2; mt++) {
        int r0 = bm + wm + mt * 16 + (lane >> 2);
        int n0 = r0 & (NSEQ - 1);
#pragma unroll
        for (int nt = 0; nt < 8; nt++) {
            int c0 = bn + wn + nt * 8 + (lane & 3) * 2;
            float* p = acc[mt][nt];
            float p0 = p[0], p1 = p[1], p2 = p[2], p3 = p[3];
            if (EPI <= 1) {
                int j = (c0 & (HDIM - 1)) >> 1;
                float ca = cosb[n0 * 64 + j],       sa = sinb[n0 * 64 + j];
                float cb = cosb[(n0 + 8) * 64 + j], sb = sinb[(n0 + 8) * 64 + j];
                float t0 = p0 * ca - p1 * sa, t1 = p0 * sa + p1 * ca;
                float t2 = p2 * cb - p3 * sb, t3 = p2 * sb + p3 * cb;
                p0 = t0; p1 = t1; p2 = t2; p3 = t3;
            }
            if (EPI == 0) {
                p0 *= ATT_SCALE; p1 *= ATT_SCALE; p2 *= ATT_SCALE; p3 *= ATT_SCALE;
                __half h0 = __float2half_rn(p0), h1 = __float2half_rn(p1);
                __half h2 = __float2half_rn(p2), h3 = __float2half_rn(p3);
                *(__half2*)&Ch[(size_t)r0 * N + c0]       = __halves2half2(h0, h1);
                *(__half2*)&Ch[(size_t)(r0 + 8) * N + c0] = __halves2half2(h2, h3);
                *(__half2*)&Cl[(size_t)r0 * N + c0] = __halves2half2(
                    __float2half_rn(p0 - __half2float(h0)),
                    __float2half_rn(p1 - __half2float(h1)));
                *(__half2*)&Cl[(size_t)(r0 + 8) * N + c0] = __halves2half2(
                    __float2half_rn(p2 - __half2float(h2)),
                    __float2half_rn(p3 - __half2float(h3)));
            } else {
                *(__half2*)&Ch[(size_t)r0 * N + c0]       = __floats2half2_rn(p0, p1);
                *(__half2*)&Ch[(size_t)(r0 + 8) * N + c0] = __floats2half2_rn(p2, p3);
            }
        }
    }
}

// ---------------- 2-pass (A hi/lo, B single): K projection ----------------
#define G2STAGE (3 * TILE144)        // 55296
#define G2SMEM  (3 * G2STAGE)        // 165888
template <int EPI>
__global__ __launch_bounds__(256) void gemm2p(
    const __half* __restrict__ Ah, const __half* __restrict__ Al,
    const __half* __restrict__ B, __half* __restrict__ Ch, __half* __restrict__ Cl,
    const float* __restrict__ cosb, const float* __restrict__ sinb, int N, int K)
{
    extern __shared__ char smraw[];
    const uint32_t sbase = s2u32(smraw);
    const int tid  = threadIdx.x;
    const int wid  = tid >> 5;
    const int lane = tid & 31;
    const int bm = blockIdx.y << 7, bn = blockIdx.x << 7;
    const int wm = (wid & 3) * 32;
    const int wn = (wid >> 2) * 64;
    const int NCH = K >> 6;

    float acc[2][8][4];
#pragma unroll
    for (int i = 0; i < 2; i++)
#pragma unroll
        for (int j = 0; j < 8; j++)
#pragma unroll
            for (int t = 0; t < 4; t++) acc[i][j][t] = 0.0f;

    const __half* tsrc[3] = {Ah, Al, B};

    auto load_stage = [&](int ch, int st) {
        const int k0 = ch << 6;
        const uint32_t stb = sbase + st * G2STAGE;
#pragma unroll
        for (int i = 0; i < 12; i++) {
            int f = i * 256 + tid;          // 0..3071 16B chunks (3 tiles x 1024)
            int tile = f >> 10;
            int c = f & 1023;
            int row = c >> 3, ch8 = c & 7;
            const __half* g = tsrc[tile];
            int rb = (tile < 2) ? bm : bn;
            cp16(stb + tile * TILE144 + row * 144 + ch8 * 16,
                 g + (size_t)(rb + row) * K + k0 + ch8 * 8);
        }
    };

    uint32_t offA[2], offB[4];
#pragma unroll
    for (int mt = 0; mt < 2; mt++)
        offA[mt] = (uint32_t)((wm + mt * 16 + (lane & 15)) * 144 + (lane >> 4) * 16);
#pragma unroll
    for (int nb = 0; nb < 4; nb++)
        offB[nb] = (uint32_t)((wn + nb * 16 + (lane & 15)) * 144 + (lane >> 4) * 16);

    load_stage(0, 0); cp_commit();
    load_stage(1, 1); cp_commit();

    for (int it = 0; it < NCH; ++it) {
        if (it + 1 < NCH) cp_wait<1>(); else cp_wait<0>();
        __syncthreads();
        if (it + 2 < NCH) { load_stage(it + 2, (it + 2) % 3); cp_commit(); }

        const uint32_t bAh = sbase + (it % 3) * G2STAGE;
        const uint32_t bAl = bAh + TILE144;
        const uint32_t bB  = bAh + 2 * TILE144;

#pragma unroll
        for (int kk = 0; kk < 4; kk++) {
            const uint32_t ks = kk * 32;
            uint32_t ah[2][4], al[2][4], bfr[4][4];
#pragma unroll
            for (int mt = 0; mt < 2; mt++) {
                ldsm4(ah[mt][0], ah[mt][1], ah[mt][2], ah[mt][3], bAh + offA[mt] + ks);
                ldsm4(al[mt][0], al[mt][1], al[mt][2], al[mt][3], bAl + offA[mt] + ks);
            }
#pragma unroll
            for (int nb = 0; nb < 4; nb++)
                ldsm4(bfr[nb][0], bfr[nb][1], bfr[nb][2], bfr[nb][3], bB + offB[nb] + ks);
#pragma unroll
            for (int mt = 0; mt < 2; mt++)
#pragma unroll
                for (int nb = 0; nb < 4; nb++)
#pragma unroll
                    for (int hf = 0; hf < 2; hf++) {
                        float* c = acc[mt][nb * 2 + hf];
                        mma16816f(c, ah[mt], bfr[nb][hf], bfr[nb][hf + 2]);
                        mma16816f(c, al[mt], bfr[nb][hf], bfr[nb][hf + 2]);
                    }
        }
    }

    epilogue16<EPI>(acc, Ch, Cl, cosb, sinb, bm, bn, wm, wn, lane, N);
}

// ---------------- 1-pass with fused epilogue: Q / V projections ----------------
#define G1STAGE (2 * TILE144)        // 36864
#define G1SMEM  (3 * G1STAGE)        // 110592
template <int EPI>
__global__ __launch_bounds__(256) void gemm1pe(
    const __half* __restrict__ A, const __half* __restrict__ B,
    __half* __restrict__ Ch, __half* __restrict__ Cl,
    const float* __restrict__ cosb, const float* __restrict__ sinb, int N, int K)
{
    extern __shared__ char smraw[];
    const uint32_t sbase = s2u32(smraw);
    const int tid  = threadIdx.x;
    const int wid  = tid >> 5;
    const int lane = tid & 31;
    const int bm = blockIdx.y << 7, bn = blockIdx.x << 7;
    const int wm = (wid & 3) * 32;
    const int wn = (wid >> 2) * 64;
    const int NCH = K >> 6;

    float acc[2][8][4];
#pragma unroll
    for (int i = 0; i < 2; i++)
#pragma unroll
        for (int j = 0; j < 8; j++)
#pragma unroll
            for (int t = 0; t < 4; t++) acc[i][j][t] = 0.0f;

    auto load_stage = [&](int ch, int st) {
        const int k0 = ch << 6;
        const uint32_t stb = sbase + st * G1STAGE;
#pragma unroll
        for (int i = 0; i < 8; i++) {
            int f = i * 256 + tid;          // 0..2047 (2 tiles x 1024)
            int tile = f >> 10;
            int c = f & 1023;
            int row = c >> 3, ch8 = c & 7;
            const __half* g = tile ? B : A;
            int rb = tile ? bn : bm;
            cp16(stb + tile * TILE144 + row * 144 + ch8 * 16,
                 g + (size_t)(rb + row) * K + k0 + ch8 * 8);
        }
    };

    uint32_t offA[2], offB[4];
#pragma unroll
    for (int mt = 0; mt < 2; mt++)
        offA[mt] = (uint32_t)((wm + mt * 16 + (lane & 15)) * 144 + (lane >> 4) * 16);
#pragma unroll
    for (int nb = 0; nb < 4; nb++)
        offB[nb] = (uint32_t)((wn + nb * 16 + (lane & 15)) * 144 + (lane >> 4) * 16);

    load_stage(0, 0); cp_commit();
    load_stage(1, 1); cp_commit();

    for (int it = 0; it < NCH; ++it) {
        if (it + 1 < NCH) cp_wait<1>(); else cp_wait<0>();
        __syncthreads();
        if (it + 2 < NCH) { load_stage(it + 2, (it + 2) % 3); cp_commit(); }

        const uint32_t bA = sbase + (it % 3) * G1STAGE;
        const uint32_t bB = bA + TILE144;

#pragma unroll
        for (int kk = 0; kk < 4; kk++) {
            const uint32_t ks = kk * 32;
            uint32_t a[2][4], bfr[4][4];
#pragma unroll
            for (int mt = 0; mt < 2; mt++)
                ldsm4(a[mt][0], a[mt][1], a[mt][2], a[mt][3], bA + offA[mt] + ks);
#pragma unroll
            for (int nb = 0; nb < 4; nb++)
                ldsm4(bfr[nb][0], bfr[nb][1], bfr[nb][2], bfr[nb][3], bB + offB[nb] + ks);
#pragma unroll
            for (int mt = 0; mt < 2; mt++)
#pragma unroll
                for (int nb = 0; nb < 4; nb++)
#pragma unroll
                    for (int hf = 0; hf < 2; hf++)
                        mma16816f(acc[mt][nb * 2 + hf], a[mt],
                                  bfr[nb][hf], bfr[nb][hf + 2]);
        }
    }

    epilogue16<EPI>(acc, Ch, Cl, cosb, sinb, bm, bn, wm, wn, lane, N);
}

// ---------------- 1-pass fp16 -> fp32 out: O projection ----------------
__global__ __launch_bounds__(256) void gemm1p(
    const __half* __restrict__ A, const __half* __restrict__ B,
    float* __restrict__ C, int N, int K)
{
    extern __shared__ char smraw[];
    const uint32_t sbase = s2u32(smraw);
    const int tid  = threadIdx.x;
    const int wid  = tid >> 5;
    const int lane = tid & 31;
    const int bm = blockIdx.y << 7, bn = blockIdx.x << 7;
    const int wm = (wid & 3) * 32;
    const int wn = (wid >> 2) * 64;
    const int NCH = K >> 6;

    float acc[2][8][4];
#pragma unroll
    for (int i = 0; i < 2; i++)
#pragma unroll
        for (int j = 0; j < 8; j++)
#pragma unroll
            for (int t = 0; t < 4; t++) acc[i][j][t] = 0.0f;

    auto load_stage = [&](int ch, int st) {
        const int k0 = ch << 6;
        const uint32_t stb = sbase + st * G1STAGE;
#pragma unroll
        for (int i = 0; i < 8; i++) {
            int f = i * 256 + tid;
            int tile = f >> 10;
            int c = f & 1023;
            int row = c >> 3, ch8 = c & 7;
            const __half* g = tile ? B : A;
            int rb = tile ? bn : bm;
            cp16(stb + tile * TILE144 + row * 144 + ch8 * 16,
                 g + (size_t)(rb + row) * K + k0 + ch8 * 8);
        }
    };

    uint32_t offA[2], offB[4];
#pragma unroll
    for (int mt = 0; mt < 2; mt++)
        offA[mt] = (uint32_t)((wm + mt * 16 + (lane & 15)) * 144 + (lane >> 4) * 16);
#pragma unroll
    for (int nb = 0; nb < 4; nb++)
        offB[nb] = (uint32_t)((wn + nb * 16 + (lane & 15)) * 144 + (lane >> 4) * 16);

    load_stage(0, 0); cp_commit();
    load_stage(1, 1); cp_commit();

    for (int it = 0; it < NCH; ++it) {
        if (it + 1 < NCH) cp_wait<1>(); else cp_wait<0>();
        __syncthreads();
        if (it + 2 < NCH) { load_stage(it + 2, (it + 2) % 3); cp_commit(); }

        const uint32_t bA = sbase + (it % 3) * G1STAGE;
        const uint32_t bB = bA + TILE144;

#pragma unroll
        for (int kk = 0; kk < 4; kk++) {
            const uint32_t ks = kk * 32;
            uint32_t a[2][4], bfr[4][4];
#pragma unroll
            for (int mt = 0; mt < 2; mt++)
                ldsm4(a[mt][0], a[mt][1], a[mt][2], a[mt][3], bA + offA[mt] + ks);
#pragma unroll
            for (int nb = 0; nb < 4; nb++)
                ldsm4(bfr[nb][0], bfr[nb][1], bfr[nb][2], bfr[nb][3], bB + offB[nb] + ks);
#pragma unroll
            for (int mt = 0; mt < 2; mt++)
#pragma unroll
                for (int nb = 0; nb < 4; nb++)
#pragma unroll
                    for (int hf = 0; hf < 2; hf++)
                        mma16816f(acc[mt][nb * 2 + hf], a[mt],
                                  bfr[nb][hf], bfr[nb][hf + 2]);
        }
    }

#pragma unroll
    for (int mt = 0; mt < 2; mt++) {
        int r0 = bm + wm + mt * 16 + (lane >> 2);
#pragma unroll
        for (int nt = 0; nt < 8; nt++) {
            int c0 = bn + wn + nt * 8 + (lane & 3) * 2;
            float* p = acc[mt][nt];
            *(float2*)&C[(size_t)r0 * N + c0]       = make_float2(p[0], p[1]);
            *(float2*)&C[(size_t)(r0 + 8) * N + c0] = make_float2(p[2], p[3]);
        }
    }
}

// ---------------- flash attention via mma.sync ----------------
// 128 q-rows/CTA, 8 warps x 16 rows, 64-key tiles double buffered.
// S: Q hi/lo 2-pass vs K fp16; PV: fp16 single pass. fp32 softmax/accum.
// Grid reversed so longest (most-keys) tiles launch first.
#define APITCH  272
#define QS_BYTES (128 * APITCH)
#define KVTILE   (64 * APITCH)
#define STG      (2 * KVTILE)
#define ASMEM    (2 * QS_BYTES + 2 * STG)
__global__ __launch_bounds__(256) void attn_mma(
    const __half* __restrict__ Qh, const __half* __restrict__ Ql,
    const __half* __restrict__ Kk, const __half* __restrict__ V,
    __half* __restrict__ O16)
{
    extern __shared__ char smraw[];
    const uint32_t sb = s2u32(smraw);
    const uint32_t qh_s = sb;
    const uint32_t ql_s = sb + QS_BYTES;
    const uint32_t kvb  = sb + 2 * QS_BYTES;

    const int tid = threadIdx.x;
    const int wid = tid >> 5, lane = tid & 31;
    const int qt = gridDim.x - 1 - blockIdx.x;   // big tiles first
    const int bh = blockIdx.y;
    const int b = bh >> 5, h = bh & 31;
    const int kvh = h >> 2;

    {
        const size_t qrow0 = (size_t)(b * NSEQ + qt * 128) * DIMM + h * HDIM;
#pragma unroll
        for (int i = 0; i < 16; i++) {
            int f = i * 256 + tid;
            int tile = f >> 11;
            int c = f & 2047;
            int row = c >> 4, ch = c & 15;
            const __half* src = (tile ? Ql : Qh) + qrow0 + (size_t)row * DIMM + ch * 8;
            cp16((tile ? ql_s : qh_s) + row * APITCH + ch * 16, src);
        }
    }

    auto load_kv = [&](int kt, int st) {
        const uint32_t stb = kvb + st * STG;
        const size_t row0 = (size_t)(b * NSEQ + kt * 64) * KVDIM + kvh * HDIM;
#pragma unroll
        for (int i = 0; i < 8; i++) {
            int f = i * 256 + tid;
            int tile = f >> 10;
            int c = f & 1023;
            int row = c >> 4, ch = c & 15;
            const __half* src = (tile ? V : Kk) + row0 + (size_t)row * KVDIM + ch * 8;
            cp16(stb + tile * KVTILE + row * APITCH + ch * 16, src);
        }
    };

    float o[16][4];
#pragma unroll
    for (int t = 0; t < 16; t++)
#pragma unroll
        for (int r = 0; r < 4; r++) o[t][r] = 0.0f;
    float m0 = -1e30f, m1 = -1e30f, l0 = 0.0f, l1 = 0.0f;

    const int NIT = 2 * qt + 2;
    load_kv(0, 0); cp_commit();

    const int rowA = qt * 128 + wid * 16 + (lane >> 2);
    const uint32_t aoff = (uint32_t)((wid * 16 + (lane & 15)) * APITCH + (lane >> 4) * 16);

    for (int it = 0; it < NIT; it++) {
        const int st = it & 1;
        cp_wait<0>();
        __syncthreads();
        if (it + 1 < NIT) { load_kv(it + 1, st ^ 1); cp_commit(); }

        const uint32_t k_t = kvb + st * STG;
        const uint32_t v_t = k_t + KVTILE;

        float s[8][4];
#pragma unroll
        for (int t = 0; t < 8; t++)
#pragma unroll
            for (int r = 0; r < 4; r++) s[t][r] = 0.0f;

#pragma unroll
        for (int kki = 0; kki < 8; kki++) {
            uint32_t ah[4], al[4];
            ldsm4(ah[0], ah[1], ah[2], ah[3], qh_s + aoff + kki * 32);
            ldsm4(al[0], al[1], al[2], al[3], ql_s + aoff + kki * 32);
#pragma unroll
            for (int g = 0; g < 4; g++) {
                uint32_t boff = (uint32_t)((16 * g + (lane & 15)) * APITCH
                                           + (kki * 2 + (lane >> 4)) * 16);
                uint32_t b0, b1, b2, b3;
                ldsm4(b0, b1, b2, b3, k_t + boff);
                mma16816f(s[2 * g],     ah, b0, b2);
                mma16816f(s[2 * g],     al, b0, b2);
                mma16816f(s[2 * g + 1], ah, b1, b3);
                mma16816f(s[2 * g + 1], al, b1, b3);
            }
        }

        if (it >= 2 * qt) {
            const int kbase = it * 64 + (lane & 3) * 2;
#pragma unroll
            for (int t = 0; t < 8; t++) {
                int k0 = kbase + t * 8;
                if (k0     > rowA)     s[t][0] = -1e30f;
                if (k0 + 1 > rowA)     s[t][1] = -1e30f;
                if (k0     > rowA + 8) s[t][2] = -1e30f;
                if (k0 + 1 > rowA + 8) s[t][3] = -1e30f;
            }
        }

        float mxA = m0, mxB = m1;
#pragma unroll
        for (int t = 0; t < 8; t++) {
            mxA = fmaxf(mxA, fmaxf(s[t][0], s[t][1]));
            mxB = fmaxf(mxB, fmaxf(s[t][2], s[t][3]));
        }
        mxA = fmaxf(mxA, __shfl_xor_sync(0xFFFFFFFFu, mxA, 1));
        mxA = fmaxf(mxA, __shfl_xor_sync(0xFFFFFFFFu, mxA, 2));
        mxB = fmaxf(mxB, __shfl_xor_sync(0xFFFFFFFFu, mxB, 1));
        mxB = fmaxf(mxB, __shfl_xor_sync(0xFFFFFFFFu, mxB, 2));

        float aA = __expf(m0 - mxA), aB = __expf(m1 - mxB);
        float sA = 0.0f, sB = 0.0f;
#pragma unroll
        for (int t = 0; t < 8; t++) {
            s[t][0] = __expf(s[t][0] - mxA);
            s[t][1] = __expf(s[t][1] - mxA);
            s[t][2] = __expf(s[t][2] - mxB);
            s[t][3] = __expf(s[t][3] - mxB);
            sA += s[t][0] + s[t][1];
            sB += s[t][2] + s[t][3];
        }
        sA += __shfl_xor_sync(0xFFFFFFFFu, sA, 1);
        sA += __shfl_xor_sync(0xFFFFFFFFu, sA, 2);
        sB += __shfl_xor_sync(0xFFFFFFFFu, sB, 1);
        sB += __shfl_xor_sync(0xFFFFFFFFu, sB, 2);
        l0 = l0 * aA + sA;  l1 = l1 * aB + sB;
        m0 = mxA;           m1 = mxB;

#pragma unroll
        for (int t = 0; t < 16; t++) {
            o[t][0] *= aA; o[t][1] *= aA;
            o[t][2] *= aB; o[t][3] *= aB;
        }

        uint32_t ap[4][4];
#pragma unroll
        for (int kk = 0; kk < 4; kk++) {
            ap[kk][0] = packh2(s[2 * kk][0],     s[2 * kk][1]);
            ap[kk][1] = packh2(s[2 * kk][2],     s[2 * kk][3]);
            ap[kk][2] = packh2(s[2 * kk + 1][0], s[2 * kk + 1][1]);
            ap[kk][3] = packh2(s[2 * kk + 1][2], s[2 * kk + 1][3]);
        }
        const uint32_t vrow = (uint32_t)((((lane >> 3) & 1) * 8 + (lane & 7)) * APITCH
                                         + (lane >> 4) * 16);
#pragma unroll
        for (int kk = 0; kk < 4; kk++) {
#pragma unroll
            for (int g = 0; g < 8; g++) {
                uint32_t v0, v1, v2, v3;
                ldsm4t(v0, v1, v2, v3, v_t + vrow + (uint32_t)(16 * kk * APITCH + g * 32));
                mma16816f(o[2 * g],     ap[kk], v0, v1);
                mma16816f(o[2 * g + 1], ap[kk], v2, v3);
            }
        }
    }

    const float iA = 1.0f / l0, iB = 1.0f / l1;
    __half* obase = O16 + ((size_t)(b * NSEQ) * NHEAD + h) * HDIM;
#pragma unroll
    for (int t = 0; t < 16; t++) {
        int d = t * 8 + (lane & 3) * 2;
        *(__half2*)(obase + (size_t)rowA * (NHEAD * HDIM) + d) =
            __floats2half2_rn(o[t][0] * iA, o[t][1] * iA);
        *(__half2*)(obase + (size_t)(rowA + 8) * (NHEAD * HDIM) + d) =
            __floats2half2_rn(o[t][2] * iB, o[t][3] * iB);
    }
}

// ---------------- launch ----------------
extern "C" void kernel_launch(void* const* d_in, const int* in_sizes, int n_in,
                              void* d_out, int out_size)
{
    const float* x    = (const float*)d_in[0];
    const float* wq   = (const float*)d_in[1];
    const float* wk   = (const float*)d_in[2];
    const float* wv   = (const float*)d_in[3];
    const float* wo   = (const float*)d_in[4];
    const float* cosb = (const float*)d_in[5];
    const float* sinb = (const float*)d_in[6];
    float* out = (float*)d_out;

    __half *x16h, *x16l, *wq16, *wk16, *wv16, *wo16;
    cudaGetSymbolAddress((void**)&x16h, g_x16h);
    cudaGetSymbolAddress((void**)&x16l, g_x16l);
    cudaGetSymbolAddress((void**)&wq16, g_wq16);
    cudaGetSymbolAddress((void**)&wk16, g_wk16);
    cudaGetSymbolAddress((void**)&wv16, g_wv16);
    cudaGetSymbolAddress((void**)&wo16, g_wo16);
    __half *q16h, *q16l, *k16, *v16, *o16;
    cudaGetSymbolAddress((void**)&q16h, g_q16h);
    cudaGetSymbolAddress((void**)&q16l, g_q16l);
    cudaGetSymbolAddress((void**)&k16,  g_k16);
    cudaGetSymbolAddress((void**)&v16,  g_v16);
    cudaGetSymbolAddress((void**)&o16,  g_o16);

    cudaFuncSetAttribute(gemm2p<1>, cudaFuncAttributeMaxDynamicSharedMemorySize, G2SMEM);
    cudaFuncSetAttribute(gemm1pe<0>, cudaFuncAttributeMaxDynamicSharedMemorySize, G1SMEM);
    cudaFuncSetAttribute(gemm1pe<2>, cudaFuncAttributeMaxDynamicSharedMemorySize, G1SMEM);
    cudaFuncSetAttribute(gemm1p, cudaFuncAttributeMaxDynamicSharedMemorySize, G1SMEM);
    cudaFuncSetAttribute(attn_mma, cudaFuncAttributeMaxDynamicSharedMemorySize, ASMEM);

    dim3 blk(256);

    // input conversions (x split still feeds K 2-pass)
    splitf16_kernel<<<(MROWS * DIMM / 4 + 255) / 256, blk>>>(x, x16h, x16l, MROWS * DIMM / 4);
    cvt16_kernel<<<(DIMM * DIMM / 4 + 255) / 256, blk>>>(wq, wq16, DIMM * DIMM / 4);
    cvt16_kernel<<<(KVDIM * DIMM / 4 + 255) / 256, blk>>>(wk, wk16, KVDIM * DIMM / 4);
    cvt16_kernel<<<(KVDIM * DIMM / 4 + 255) / 256, blk>>>(wv, wv16, KVDIM * DIMM / 4);
    cvt16_kernel<<<(DIMM * DIMM / 4 + 255) / 256, blk>>>(wo, wo16, DIMM * DIMM / 4);

    // projections: Q 1-pass (rope+scale+hi/lo), K 2-pass (rope), V 1-pass
    gemm1pe<0><<<dim3(DIMM / 128, MROWS / 128), blk, G1SMEM>>>(
        x16h, wq16, q16h, q16l, cosb, sinb, DIMM, DIMM);
    gemm2p<1><<<dim3(KVDIM / 128, MROWS / 128), blk, G2SMEM>>>(
        x16h, x16l, wk16, k16, nullptr, cosb, sinb, KVDIM, DIMM);
    gemm1pe<2><<<dim3(KVDIM / 128, MROWS / 128), blk, G1SMEM>>>(
        x16h, wv16, v16, nullptr, cosb, sinb, KVDIM, DIMM);

    // attention (Q hi/lo, K/V fp16) -> fp16 o16
    attn_mma<<<dim3(NSEQ / 128, BATCH * NHEAD), blk, ASMEM>>>(q16h, q16l, k16, v16, o16);

    // output projection: single-pass fp16
    gemm1p<<<dim3(DIMM / 128, MROWS / 128), blk, G1SMEM>>>(o16, wo16, out, DIMM, DIMM);
}